// round 3
// baseline (speedup 1.0000x reference)
#include <cuda_runtime.h>
#include <cuda_bf16.h>
#include <cstdint>

// ============================================================================
// CellLSTM on GB300 (sm_103a)
//   z = [x|h] @ [Wi|Wf|Wg|Wo] + b ; gates; c' = f*c + i*g ; h' = o*tanh(c')
//   GEMM M=8192, K=2048, N=4096 via tcgen05 bf16x3 split (fp32-accurate),
//   now as 2-CTA clusters (cta_group::2, M=256 x N=256 tiles) to halve LTS
//   traffic, plus a coalesced SMEM-staged epilogue (R2 epilogue scattered
//   4B stores at 4KB lane stride -> 8x sector amplification).
//   tcgen05 is arch-specific: only compiled when the "a" feature macros are
//   defined; plain compute_103 passes get a SIMT fallback (never executed).
// ============================================================================

#if defined(__CUDA_ARCH_FEAT_SM103_ALL) || defined(__CUDA_ARCH_FEAT_SM100_ALL)
#define USE_TCGEN05 1
#else
#define USE_TCGEN05 0
#endif

#define B_DIM 8192
#define T_DIM 1024
#define U_DIM 1024
#define K_DIM 2048
#define N_DIM 4096

#define BM 256              // per cluster (128 per CTA)
#define BN 256              // per cluster (B split: 128 rows per CTA)
#define BK 64
#define KTILES (K_DIM / BK)   // 32
#define GEMM_THREADS 256

// ---------------- scratch (device globals: allocation-rule-safe) -----------
__device__ __align__(16) __nv_bfloat16 g_A_hi[(size_t)B_DIM * K_DIM];
__device__ __align__(16) __nv_bfloat16 g_A_lo[(size_t)B_DIM * K_DIM];
// W transposed & gate-interleaved: row n = u*4 + gate, K-major
__device__ __align__(16) __nv_bfloat16 g_W_hi[(size_t)N_DIM * K_DIM];
__device__ __align__(16) __nv_bfloat16 g_W_lo[(size_t)N_DIM * K_DIM];

// ---------------- arch-neutral helpers -------------------------------------
__device__ __forceinline__ uint32_t smem_u32(const void* p) {
    uint32_t a;
    asm("{ .reg .u64 t; cvta.to.shared.u64 t, %1; cvt.u32.u64 %0, t; }"
        : "=r"(a) : "l"(p));
    return a;
}

#define SWZ128(off) ((off) ^ (((off) >> 3) & 0x70))

__device__ __forceinline__ float fast_sigmoid(float z) {
    return 1.0f / (1.0f + __expf(-z));
}

#if USE_TCGEN05
// ---------------- tcgen05 / mbarrier / cp.async helpers --------------------
__device__ __forceinline__ uint32_t elect_one() {
    uint32_t pred;
    asm volatile(
        "{\n\t.reg .pred p;\n\telect.sync _|p, 0xFFFFFFFF;\n\t"
        "selp.b32 %0, 1, 0, p;\n\t}" : "=r"(pred));
    return pred;
}

#define MBARRIER_INIT(addr, cnt) \
    asm volatile("mbarrier.init.shared.b64 [%0], %1;" \
                 :: "r"((uint32_t)(addr)), "r"((uint32_t)(cnt)) : "memory")

#define MBARRIER_INVAL(addr) \
    asm volatile("mbarrier.inval.shared.b64 [%0];" \
                 :: "r"((uint32_t)(addr)) : "memory")

#define MBARRIER_WAIT_PARITY(mbar_smem_addr, phase_parity) do { \
    uint32_t _mbar = (uint32_t)(mbar_smem_addr); \
    uint32_t _parity = (uint32_t)(phase_parity); \
    uint32_t _done; \
    asm volatile( \
        "{\n\t.reg .pred p;\n\t" \
        "mbarrier.try_wait.parity.acquire.cta.shared::cta.b64 p, [%1], %2;\n\t" \
        "selp.b32 %0, 1, 0, p;\n\t}" \
        : "=r"(_done) : "r"(_mbar), "r"(_parity) : "memory"); \
    if (!_done) { \
        asm volatile( \
            "{\n\t.reg .pred P1;\n\t" \
            "WAIT_LOOP_%=:\n\t" \
            "mbarrier.try_wait.parity.acquire.cta.shared::cta.b64 P1, [%0], %1, 0x989680;\n\t" \
            "@P1 bra.uni WAIT_DONE_%=;\n\t" \
            "bra.uni WAIT_LOOP_%=;\n\t" \
            "WAIT_DONE_%=:\n\t}" \
            :: "r"(_mbar), "r"(_parity) : "memory"); \
    } \
} while (0)

#define TCGEN05_ALLOC_CG2(smem_result_addr, nCols) \
    asm volatile("tcgen05.alloc.cta_group::2.sync.aligned.shared::cta.b32 [%0], %1;" \
                 :: "r"((uint32_t)(smem_result_addr)), "r"((uint32_t)(nCols)) : "memory")

#define TCGEN05_DEALLOC_CG2(tmem_addr, nCols) \
    asm volatile("tcgen05.dealloc.cta_group::2.sync.aligned.b32 %0, %1;" \
                 :: "r"(tmem_addr), "r"((uint32_t)(nCols)))

#define TCGEN05_RELINQUISH_CG2() \
    asm volatile("tcgen05.relinquish_alloc_permit.cta_group::2.sync.aligned;")

#define TCGEN05_COMMIT_MULTICAST_CG2(mbar_smem_addr, cta_mask) \
    asm volatile( \
        "tcgen05.commit.cta_group::2.mbarrier::arrive::one.shared::cluster.multicast::cluster.b64 [%0], %1;" \
        :: "r"((uint32_t)(mbar_smem_addr)), "h"((uint16_t)(cta_mask)) : "memory")

#define TCGEN05_FENCE_AFTER() \
    asm volatile("tcgen05.fence::after_thread_sync;" ::: "memory")
#define TCGEN05_FENCE_BEFORE() \
    asm volatile("tcgen05.fence::before_thread_sync;" ::: "memory")
#define TCGEN05_WAIT_LD() \
    asm volatile("tcgen05.wait::ld.sync.aligned;" ::: "memory")

#define FENCE_PROXY_ASYNC() \
    asm volatile("fence.proxy.async.shared::cta;" ::: "memory")

#define CLUSTER_SYNC() do { \
    asm volatile("barrier.cluster.arrive.aligned;" ::: "memory"); \
    asm volatile("barrier.cluster.wait.aligned;" ::: "memory"); \
} while (0)

#define CP_ASYNC_COMMIT() asm volatile("cp.async.commit_group;" ::: "memory")
#define CP_ASYNC_WAIT(n)  asm volatile("cp.async.wait_group %0;" :: "n"(n) : "memory")

__device__ __forceinline__ void cp16(uint32_t dst, const void* src) {
    asm volatile("cp.async.cg.shared.global [%0], [%1], 16;"
                 :: "r"(dst), "l"(src) : "memory");
}

#define TCGEN05_LD_32X32B_X32(r, tmem_addr) \
    asm volatile( \
        "tcgen05.ld.sync.aligned.32x32b.x32.b32 " \
        "{%0, %1, %2, %3, %4, %5, %6, %7, " \
        " %8, %9, %10, %11, %12, %13, %14, %15, " \
        " %16, %17, %18, %19, %20, %21, %22, %23, " \
        " %24, %25, %26, %27, %28, %29, %30, %31}, [%32];" \
        : "=r"((r)[0]),  "=r"((r)[1]),  "=r"((r)[2]),  "=r"((r)[3]), \
          "=r"((r)[4]),  "=r"((r)[5]),  "=r"((r)[6]),  "=r"((r)[7]), \
          "=r"((r)[8]),  "=r"((r)[9]),  "=r"((r)[10]), "=r"((r)[11]), \
          "=r"((r)[12]), "=r"((r)[13]), "=r"((r)[14]), "=r"((r)[15]), \
          "=r"((r)[16]), "=r"((r)[17]), "=r"((r)[18]), "=r"((r)[19]), \
          "=r"((r)[20]), "=r"((r)[21]), "=r"((r)[22]), "=r"((r)[23]), \
          "=r"((r)[24]), "=r"((r)[25]), "=r"((r)[26]), "=r"((r)[27]), \
          "=r"((r)[28]), "=r"((r)[29]), "=r"((r)[30]), "=r"((r)[31]) \
        : "r"(tmem_addr))

// K-major SW128 smem descriptor (verified: test_mma_iter / test_2cta_mma_bf16)
static constexpr uint64_t SMEM_DESC_BASE_SW128 =
    (uint64_t(2)  << 61) | (uint64_t(1) << 46) |
    (uint64_t(64) << 32) | (uint64_t(1) << 16);

__device__ __forceinline__ uint64_t make_desc(uint32_t addr) {
    return SMEM_DESC_BASE_SW128 | ((uint64_t)(addr >> 4) & 0x3FFF);
}

// idesc kind::f16 bf16->f32, M_TOTAL=256 (cg2), N=256
static constexpr uint32_t MMA_IDESC =
    (1u << 4) | (1u << 7) | (1u << 10) | ((BN / 8) << 17) | ((BM / 16) << 24);

__device__ __forceinline__ void mma_f16_ss_cg2(uint32_t d, uint64_t ad, uint64_t bd,
                                               uint32_t idesc, uint32_t acc) {
    asm volatile(
        "{\n\t.reg .pred p;\n\t"
        "setp.ne.u32 p, %6, 0;\n\t"
        "tcgen05.mma.cta_group::2.kind::f16 [%0], %1, %2, %3, "
        "{%4, %4, %4, %4, %4, %4, %4, %4}, p;\n\t"
        "}"
        :: "r"(d), "l"(ad), "l"(bd), "r"(idesc),
           "r"(0u), "r"(0u), "r"(acc)
        : "memory");
}
#endif // USE_TCGEN05

// ---------------- prep kernel A: concat(x,h) -> bf16 hi/lo -----------------
__global__ void prep_a_kernel(const float* __restrict__ x, const float* __restrict__ h) {
    size_t idx4 = ((size_t)blockIdx.x * blockDim.x + threadIdx.x) * 4;
    int m = (int)(idx4 / K_DIM);
    int k = (int)(idx4 % K_DIM);
    const float* src = (k < T_DIM) ? (x + (size_t)m * T_DIM + k)
                                   : (h + (size_t)m * U_DIM + (k - T_DIM));
    float4 v = *reinterpret_cast<const float4*>(src);

    __nv_bfloat16 h0 = __float2bfloat16(v.x);
    __nv_bfloat16 h1 = __float2bfloat16(v.y);
    __nv_bfloat16 h2 = __float2bfloat16(v.z);
    __nv_bfloat16 h3 = __float2bfloat16(v.w);
    __nv_bfloat16 l0 = __float2bfloat16(v.x - __bfloat162float(h0));
    __nv_bfloat16 l1 = __float2bfloat16(v.y - __bfloat162float(h1));
    __nv_bfloat16 l2 = __float2bfloat16(v.z - __bfloat162float(h2));
    __nv_bfloat16 l3 = __float2bfloat16(v.w - __bfloat162float(h3));

    union Pack { __nv_bfloat16 b[4]; uint2 u; } ph, pl;
    ph.b[0] = h0; ph.b[1] = h1; ph.b[2] = h2; ph.b[3] = h3;
    pl.b[0] = l0; pl.b[1] = l1; pl.b[2] = l2; pl.b[3] = l3;
    *reinterpret_cast<uint2*>(g_A_hi + idx4) = ph.u;
    *reinterpret_cast<uint2*>(g_A_lo + idx4) = pl.u;
}

// ---------------- prep kernel B: W transpose+convert, gate-interleaved -----
__global__ void prep_w_kernel(const float* __restrict__ Wi, const float* __restrict__ Wf,
                              const float* __restrict__ Wg, const float* __restrict__ Wo) {
    __shared__ float tile[32][33];
    int gate = blockIdx.z;
    const float* W = (gate == 0) ? Wi : (gate == 1) ? Wf : (gate == 2) ? Wg : Wo;
    int k0 = blockIdx.x * 32;
    int u0 = blockIdx.y * 32;
    int tx = threadIdx.x, ty = threadIdx.y;

#pragma unroll
    for (int i = 0; i < 4; i++) {
        int k = k0 + ty + i * 8;
        tile[ty + i * 8][tx] = W[(size_t)k * U_DIM + u0 + tx];  // coalesced over u
    }
    __syncthreads();
#pragma unroll
    for (int i = 0; i < 4; i++) {
        int u = u0 + ty + i * 8;
        float v = tile[tx][ty + i * 8];          // = W[k0+tx, u]
        __nv_bfloat16 hi = __float2bfloat16(v);
        __nv_bfloat16 lo = __float2bfloat16(v - __bfloat162float(hi));
        size_t off = (size_t)(u * 4 + gate) * K_DIM + k0 + tx;  // coalesced over k
        g_W_hi[off] = hi;
        g_W_lo[off] = lo;
    }
}

// ---------------- GEMM + LSTM epilogue -------------------------------------
// SMEM map (tcgen05 path):
//   [0]      tmem ptr
//   [8]      commit mbar
//   [1024]   stage0: Ah(16K) Al(16K) Bh(16K) Bl(16K)  = 64KB
//   [66560]  stage1: same                              = 64KB
// epilogue (after final MMA wait, stages dead):
//   [1024]   h_stage  128 x 65 fp32 (33280B)
//   [34304]  c_stage  128 x 65 fp32 (33280B)
//   [67584]  cin_stage 128 x 65 fp32 (33280B)
#define SM_TMEM 0
#define SM_MBAR 8
#define SM_STAGE 1024
#define TILE_BYTES 16384                   // 128 rows x 128B
#define STAGE_BYTES (4 * TILE_BYTES)       // 65536
#define GEMM_SMEM (SM_STAGE + 2 * STAGE_BYTES)   // 132096
#define EP_PAD 65

#if USE_TCGEN05
__device__ __forceinline__ void load_stage(uint32_t sbase, int kt,
                                           int m0c, int n0c, int tid) {
    int koff = kt * BK;
#pragma unroll
    for (int j = 0; j < 4; j++) {
        int chunk = tid + j * GEMM_THREADS;   // 0..1023
        int r = chunk >> 3;                   // row 0..127
        int c = chunk & 7;                    // 16B chunk in 128B row
        uint32_t soff = SWZ128((uint32_t)(r * 128 + c * 16));
        size_t ga = (size_t)(m0c + r) * K_DIM + koff + c * 8;
        size_t gb = (size_t)(n0c + r) * K_DIM + koff + c * 8;
        cp16(sbase + 0 * TILE_BYTES + soff, g_A_hi + ga);
        cp16(sbase + 1 * TILE_BYTES + soff, g_A_lo + ga);
        cp16(sbase + 2 * TILE_BYTES + soff, g_W_hi + gb);
        cp16(sbase + 3 * TILE_BYTES + soff, g_W_lo + gb);
    }
}
#endif

__global__ void __launch_bounds__(GEMM_THREADS, 1) __cluster_dims__(2, 1, 1)
lstm_gemm_kernel(const float* __restrict__ c_in,
                 const float* __restrict__ bi, const float* __restrict__ bf_,
                 const float* __restrict__ bg, const float* __restrict__ bo,
                 float* __restrict__ out) {
    extern __shared__ char smem[];
    int tid = threadIdx.x;
    const size_t c_off = (size_t)B_DIM * U_DIM;

    int rank = blockIdx.x & 1;                    // cluster_ctarank for (2,1,1)
    int m0_cta = (blockIdx.x >> 1) * BM + rank * 128;  // this CTA's 128 M-rows
    int n0_base = blockIdx.y * BN;                // cluster's 256 n columns
    int n0_cta = n0_base + rank * 128;            // this CTA's 128 B rows
    int u_base = n0_base >> 2;                    // 64 u's per cluster tile

#if USE_TCGEN05
    // ======================= tcgen05 cg2 path ===============================
    uint32_t sb = smem_u32(smem);
    int wid = tid >> 5;
    int lid = tid & 31;

    if (wid == 0) TCGEN05_ALLOC_CG2(sb + SM_TMEM, 256);
    if (tid == 0) MBARRIER_INIT(sb + SM_MBAR, 1);
    __syncthreads();
    uint32_t tmem;
    asm volatile("ld.shared.b32 %0, [%1];" : "=r"(tmem) : "r"(sb + SM_TMEM));

    load_stage(sb + SM_STAGE, 0, m0_cta, n0_cta, tid);
    CP_ASYNC_COMMIT();

    int phase = 0;
#pragma unroll 1
    for (int kt = 0; kt < KTILES; kt++) {
        // MMA(kt-1) done before load(kt+1) overwrites its stage (multicast
        // commit arrives on BOTH CTAs' mbars)
        if (kt > 0) { MBARRIER_WAIT_PARITY(sb + SM_MBAR, phase); phase ^= 1; }

        if (kt + 1 < KTILES) {
            load_stage(sb + SM_STAGE + ((kt + 1) & 1) * STAGE_BYTES,
                       kt + 1, m0_cta, n0_cta, tid);
            CP_ASYNC_COMMIT();
            CP_ASYNC_WAIT(1);   // stage kt landed locally
        } else {
            CP_ASYNC_WAIT(0);
        }
        __syncthreads();
        // cross-CTA: peer stage kt visible before MMA reads peer SMEM
        CLUSTER_SYNC();

        if (rank == 0 && wid == 0) {
            FENCE_PROXY_ASYNC();
            uint32_t st = sb + SM_STAGE + (kt & 1) * STAGE_BYTES;
            uint64_t dAh = make_desc(st);
            uint64_t dAl = make_desc(st + 1 * TILE_BYTES);
            uint64_t dBh = make_desc(st + 2 * TILE_BYTES);
            uint64_t dBl = make_desc(st + 3 * TILE_BYTES);
            if (elect_one()) {
#pragma unroll
                for (int s = 0; s < 4; s++) {   // 4 x K=16 steps per 64-K tile
                    uint32_t off = s * 2;       // 32B = 2 x 16B units
                    mma_f16_ss_cg2(tmem, dAh + off, dBh + off, MMA_IDESC, (kt | s) != 0);
                    mma_f16_ss_cg2(tmem, dAh + off, dBl + off, MMA_IDESC, 1u);
                    mma_f16_ss_cg2(tmem, dAl + off, dBh + off, MMA_IDESC, 1u);
                }
                TCGEN05_COMMIT_MULTICAST_CG2(sb + SM_MBAR, 0x3);
            }
        }
    }

    MBARRIER_WAIT_PARITY(sb + SM_MBAR, phase);
    TCGEN05_FENCE_AFTER();

    // ---------------- epilogue (coalesced via SMEM staging) ----------------
    float* h_sm = reinterpret_cast<float*>(smem + SM_STAGE);
    float* c_sm = h_sm + 128 * EP_PAD;            // c_new staging
    float* ci_sm = c_sm + 128 * EP_PAD;           // c_in staging

    // stage c_in tile coalesced: 128 rows x 64 u (float4 LDG, scalar STS)
#pragma unroll
    for (int i = tid; i < 128 * 16; i += GEMM_THREADS) {
        int row = i >> 4;
        int q = i & 15;
        float4 v = *reinterpret_cast<const float4*>(
            c_in + (size_t)(m0_cta + row) * U_DIM + u_base + q * 4);
        int base = row * EP_PAD + q * 4;
        ci_sm[base + 0] = v.x; ci_sm[base + 1] = v.y;
        ci_sm[base + 2] = v.z; ci_sm[base + 3] = v.w;
    }
    __syncthreads();

    // D[128 rows, 256 cols] fp32 in this CTA's TMEM.
    // warp w: rows (w&3)*32 + lid ; col half (w>>2)*128, in 4 chunks of 32.
    int sub = wid & 3;
    int half = wid >> 2;
    int row = sub * 32 + lid;

#pragma unroll
    for (int ch = 0; ch < 4; ch++) {
        uint32_t col = (uint32_t)(half * 128 + ch * 32);
        uint32_t d[32];
        TCGEN05_LD_32X32B_X32(d, tmem + col);
        TCGEN05_WAIT_LD();
#pragma unroll
        for (int j = 0; j < 8; j++) {
            int ul = half * 32 + ch * 8 + j;     // u within the 64-u tile
            int u = u_base + ul;
            float zi = __uint_as_float(d[4 * j + 0]) + bi[u];
            float zf = __uint_as_float(d[4 * j + 1]) + bf_[u];
            float zg = __uint_as_float(d[4 * j + 2]) + bg[u];
            float zo = __uint_as_float(d[4 * j + 3]) + bo[u];
            float ig = fast_sigmoid(zi);
            float fg = fast_sigmoid(zf);
            float gg = tanhf(zg);
            float og = fast_sigmoid(zo);
            float cv = ci_sm[row * EP_PAD + ul];
            float cn = fg * cv + ig * gg;
            float hn = og * tanhf(cn);
            h_sm[row * EP_PAD + ul] = hn;
            c_sm[row * EP_PAD + ul] = cn;
        }
    }
    TCGEN05_FENCE_BEFORE();
    __syncthreads();

    // cooperative coalesced store: consecutive tids -> consecutive u
#pragma unroll
    for (int i = tid; i < 128 * 64; i += GEMM_THREADS) {
        int r = i >> 6;
        int u = i & 63;
        size_t g = (size_t)(m0_cta + r) * U_DIM + u_base + u;
        out[g] = h_sm[r * EP_PAD + u];
        out[c_off + g] = c_sm[r * EP_PAD + u];
    }

    __syncthreads();
    if (tid == 0) MBARRIER_INVAL(sb + SM_MBAR);
    __syncthreads();
    if (wid == 0) {
        TCGEN05_RELINQUISH_CG2();
        TCGEN05_DEALLOC_CG2(tmem, 256);
    }
    CLUSTER_SYNC();

#else
    // ======================= SIMT fallback (plain sm_103 target) ===========
    // Never executed when the sm_103a pass exists; kept correct + compilable.
    const int PAD = 132;
    float* As = reinterpret_cast<float*>(smem);          // [32][PAD]
    float* Bs = As + 32 * PAD;                           // [32][PAD]

    int tx = tid & 15;
    int ty = tid >> 4;

#pragma unroll 1
    for (int ns = 0; ns < 2; ns++) {                     // two 128-wide n halves
        int n0h = n0_base + ns * 128;
        int u0 = n0h >> 2;
        float acc[8][8];
#pragma unroll
        for (int i = 0; i < 8; i++)
#pragma unroll
            for (int j = 0; j < 8; j++) acc[i][j] = 0.0f;

#pragma unroll 1
        for (int kt = 0; kt < K_DIM / 32; kt++) {
            int koff = kt * 32;
#pragma unroll
            for (int i = 0; i < 16; i++) {
                int idx = tid + i * 256;
                int kk = idx & 31;
                int r = idx >> 5;
                size_t ga = (size_t)(m0_cta + r) * K_DIM + koff + kk;
                size_t gb = (size_t)(n0h + r) * K_DIM + koff + kk;
                As[kk * PAD + r] = __bfloat162float(g_A_hi[ga]) + __bfloat162float(g_A_lo[ga]);
                Bs[kk * PAD + r] = __bfloat162float(g_W_hi[gb]) + __bfloat162float(g_W_lo[gb]);
            }
            __syncthreads();
#pragma unroll 1
            for (int kk = 0; kk < 32; kk++) {
                float a[8], b[8];
#pragma unroll
                for (int i = 0; i < 8; i++) a[i] = As[kk * PAD + ty * 8 + i];
#pragma unroll
                for (int j = 0; j < 8; j++) b[j] = Bs[kk * PAD + tx * 8 + j];
#pragma unroll
                for (int i = 0; i < 8; i++)
#pragma unroll
                    for (int j = 0; j < 8; j++) acc[i][j] += a[i] * b[j];
            }
            __syncthreads();
        }

#pragma unroll
        for (int i = 0; i < 8; i++) {
            int m = m0_cta + ty * 8 + i;
#pragma unroll
            for (int jj = 0; jj < 2; jj++) {
                int u = u0 + tx * 2 + jj;
                float zi = acc[i][jj * 4 + 0] + bi[u];
                float zf = acc[i][jj * 4 + 1] + bf_[u];
                float zg = acc[i][jj * 4 + 2] + bg[u];
                float zo = acc[i][jj * 4 + 3] + bo[u];
                float ig = fast_sigmoid(zi);
                float fg = fast_sigmoid(zf);
                float gg = tanhf(zg);
                float og = fast_sigmoid(zo);
                float cv = c_in[(size_t)m * U_DIM + u];
                float cn = fg * cv + ig * gg;
                float hn = og * tanhf(cn);
                out[(size_t)m * U_DIM + u] = hn;
                out[c_off + (size_t)m * U_DIM + u] = cn;
            }
        }
        __syncthreads();
    }
#endif
}

// ---------------- launch ----------------------------------------------------
extern "C" void kernel_launch(void* const* d_in, const int* in_sizes, int n_in,
                              void* d_out, int out_size) {
    const float* x  = (const float*)d_in[0];
    const float* h  = (const float*)d_in[1];
    const float* c  = (const float*)d_in[2];
    const float* Wi = (const float*)d_in[3];
    const float* Wf = (const float*)d_in[4];
    const float* Wg = (const float*)d_in[5];
    const float* Wo = (const float*)d_in[6];
    const float* bi = (const float*)d_in[7];
    const float* bf = (const float*)d_in[8];
    const float* bg = (const float*)d_in[9];
    const float* bo = (const float*)d_in[10];
    float* out = (float*)d_out;

    // 1) concat+split A
    prep_a_kernel<<<(int)(((size_t)B_DIM * K_DIM / 4) / 256), 256>>>(x, h);
    // 2) transpose+split W (gate-interleaved columns)
    prep_w_kernel<<<dim3(K_DIM / 32, U_DIM / 32, 4), dim3(32, 8)>>>(Wi, Wf, Wg, Wo);
    // 3) GEMM + LSTM epilogue: cg2 clusters, 256x256 tiles
    cudaFuncSetAttribute(lstm_gemm_kernel,
                         cudaFuncAttributeMaxDynamicSharedMemorySize, GEMM_SMEM);
    lstm_gemm_kernel<<<dim3((B_DIM / BM) * 2, N_DIM / BN), GEMM_THREADS, GEMM_SMEM>>>(
        c, bi, bf, bg, bo, out);
}

// round 4
// speedup vs baseline: 1.4985x; 1.4985x over previous
#include <cuda_runtime.h>
#include <cuda_bf16.h>
#include <cstdint>

// ============================================================================
// CellLSTM on GB300 (sm_103a)
//   z = [x|h] @ [Wi|Wf|Wg|Wo] + b ; gates; c' = f*c + i*g ; h' = o*tanh(c')
//   GEMM M=8192, K=2048, N=4096 via tcgen05 bf16x3 split (fp32-accurate).
//   R4: cg1 (R3's cg2 + per-iter cluster.sync regressed: L1-flush + lockstep),
//   128x256 tiles (-25% LTS traffic vs 128x128), coalesced SMEM epilogue.
// ============================================================================

#if defined(__CUDA_ARCH_FEAT_SM103_ALL) || defined(__CUDA_ARCH_FEAT_SM100_ALL)
#define USE_TCGEN05 1
#else
#define USE_TCGEN05 0
#endif

#define B_DIM 8192
#define T_DIM 1024
#define U_DIM 1024
#define K_DIM 2048
#define N_DIM 4096

#define BM 128
#define BN 256
#define BK 64
#define KTILES (K_DIM / BK)   // 32
#define GEMM_THREADS 256

// ---------------- scratch (device globals: allocation-rule-safe) -----------
__device__ __align__(16) __nv_bfloat16 g_A_hi[(size_t)B_DIM * K_DIM];
__device__ __align__(16) __nv_bfloat16 g_A_lo[(size_t)B_DIM * K_DIM];
// W transposed & gate-interleaved: row n = u*4 + gate, K-major
__device__ __align__(16) __nv_bfloat16 g_W_hi[(size_t)N_DIM * K_DIM];
__device__ __align__(16) __nv_bfloat16 g_W_lo[(size_t)N_DIM * K_DIM];

// ---------------- arch-neutral helpers -------------------------------------
__device__ __forceinline__ uint32_t smem_u32(const void* p) {
    uint32_t a;
    asm("{ .reg .u64 t; cvta.to.shared.u64 t, %1; cvt.u32.u64 %0, t; }"
        : "=r"(a) : "l"(p));
    return a;
}

#define SWZ128(off) ((off) ^ (((off) >> 3) & 0x70))

__device__ __forceinline__ float fast_sigmoid(float z) {
    return 1.0f / (1.0f + __expf(-z));
}

#if USE_TCGEN05
// ---------------- tcgen05 / mbarrier / cp.async helpers --------------------
__device__ __forceinline__ uint32_t elect_one() {
    uint32_t pred;
    asm volatile(
        "{\n\t.reg .pred p;\n\telect.sync _|p, 0xFFFFFFFF;\n\t"
        "selp.b32 %0, 1, 0, p;\n\t}" : "=r"(pred));
    return pred;
}

#define MBARRIER_INIT(addr, cnt) \
    asm volatile("mbarrier.init.shared.b64 [%0], %1;" \
                 :: "r"((uint32_t)(addr)), "r"((uint32_t)(cnt)) : "memory")

#define MBARRIER_INVAL(addr) \
    asm volatile("mbarrier.inval.shared.b64 [%0];" \
                 :: "r"((uint32_t)(addr)) : "memory")

#define MBARRIER_WAIT_PARITY(mbar_smem_addr, phase_parity) do { \
    uint32_t _mbar = (uint32_t)(mbar_smem_addr); \
    uint32_t _parity = (uint32_t)(phase_parity); \
    uint32_t _done; \
    asm volatile( \
        "{\n\t.reg .pred p;\n\t" \
        "mbarrier.try_wait.parity.acquire.cta.shared::cta.b64 p, [%1], %2;\n\t" \
        "selp.b32 %0, 1, 0, p;\n\t}" \
        : "=r"(_done) : "r"(_mbar), "r"(_parity) : "memory"); \
    if (!_done) { \
        asm volatile( \
            "{\n\t.reg .pred P1;\n\t" \
            "WAIT_LOOP_%=:\n\t" \
            "mbarrier.try_wait.parity.acquire.cta.shared::cta.b64 P1, [%0], %1, 0x989680;\n\t" \
            "@P1 bra.uni WAIT_DONE_%=;\n\t" \
            "bra.uni WAIT_LOOP_%=;\n\t" \
            "WAIT_DONE_%=:\n\t}" \
            :: "r"(_mbar), "r"(_parity) : "memory"); \
    } \
} while (0)

#define TCGEN05_ALLOC(smem_result_addr, nCols) \
    asm volatile("tcgen05.alloc.cta_group::1.sync.aligned.shared::cta.b32 [%0], %1;" \
                 :: "r"((uint32_t)(smem_result_addr)), "r"((uint32_t)(nCols)) : "memory")

#define TCGEN05_DEALLOC(tmem_addr, nCols) \
    asm volatile("tcgen05.dealloc.cta_group::1.sync.aligned.b32 %0, %1;" \
                 :: "r"(tmem_addr), "r"((uint32_t)(nCols)))

#define TCGEN05_COMMIT(mbar_smem_addr) \
    asm volatile("tcgen05.commit.cta_group::1.mbarrier::arrive::one.shared::cluster.b64 [%0];" \
                 :: "r"((uint32_t)(mbar_smem_addr)) : "memory")

#define TCGEN05_FENCE_AFTER() \
    asm volatile("tcgen05.fence::after_thread_sync;" ::: "memory")
#define TCGEN05_FENCE_BEFORE() \
    asm volatile("tcgen05.fence::before_thread_sync;" ::: "memory")
#define TCGEN05_WAIT_LD() \
    asm volatile("tcgen05.wait::ld.sync.aligned;" ::: "memory")

#define FENCE_PROXY_ASYNC() \
    asm volatile("fence.proxy.async.shared::cta;" ::: "memory")

#define CP_ASYNC_COMMIT() asm volatile("cp.async.commit_group;" ::: "memory")
#define CP_ASYNC_WAIT(n)  asm volatile("cp.async.wait_group %0;" :: "n"(n) : "memory")

__device__ __forceinline__ void cp16(uint32_t dst, const void* src) {
    asm volatile("cp.async.cg.shared.global [%0], [%1], 16;"
                 :: "r"(dst), "l"(src) : "memory");
}

#define TCGEN05_LD_32X32B_X32(r, tmem_addr) \
    asm volatile( \
        "tcgen05.ld.sync.aligned.32x32b.x32.b32 " \
        "{%0, %1, %2, %3, %4, %5, %6, %7, " \
        " %8, %9, %10, %11, %12, %13, %14, %15, " \
        " %16, %17, %18, %19, %20, %21, %22, %23, " \
        " %24, %25, %26, %27, %28, %29, %30, %31}, [%32];" \
        : "=r"((r)[0]),  "=r"((r)[1]),  "=r"((r)[2]),  "=r"((r)[3]), \
          "=r"((r)[4]),  "=r"((r)[5]),  "=r"((r)[6]),  "=r"((r)[7]), \
          "=r"((r)[8]),  "=r"((r)[9]),  "=r"((r)[10]), "=r"((r)[11]), \
          "=r"((r)[12]), "=r"((r)[13]), "=r"((r)[14]), "=r"((r)[15]), \
          "=r"((r)[16]), "=r"((r)[17]), "=r"((r)[18]), "=r"((r)[19]), \
          "=r"((r)[20]), "=r"((r)[21]), "=r"((r)[22]), "=r"((r)[23]), \
          "=r"((r)[24]), "=r"((r)[25]), "=r"((r)[26]), "=r"((r)[27]), \
          "=r"((r)[28]), "=r"((r)[29]), "=r"((r)[30]), "=r"((r)[31]) \
        : "r"(tmem_addr))

// K-major SW128 smem descriptor (verified: test_mma_iter)
static constexpr uint64_t SMEM_DESC_BASE_SW128 =
    (uint64_t(2)  << 61) | (uint64_t(1) << 46) |
    (uint64_t(64) << 32) | (uint64_t(1) << 16);

__device__ __forceinline__ uint64_t make_desc(uint32_t addr) {
    return SMEM_DESC_BASE_SW128 | ((uint64_t)(addr >> 4) & 0x3FFF);
}

// idesc kind::f16 bf16->f32, M=128, N=256 (cg1)
static constexpr uint32_t MMA_IDESC =
    (1u << 4) | (1u << 7) | (1u << 10) | ((BN / 8) << 17) | ((BM / 16) << 24);

__device__ __forceinline__ void mma_f16_ss(uint32_t d, uint64_t ad, uint64_t bd,
                                           uint32_t idesc, uint32_t acc) {
    asm volatile(
        "{\n\t.reg .pred p;\n\t"
        "setp.ne.u32 p, %4, 0;\n\t"
        "tcgen05.mma.cta_group::1.kind::f16 [%0], %1, %2, %3, {%5, %5, %5, %5}, p;\n\t"
        "}"
        :: "r"(d), "l"(ad), "l"(bd), "r"(idesc), "r"(acc), "r"(0u)
        : "memory");
}
#endif // USE_TCGEN05

// ---------------- prep kernel A: concat(x,h) -> bf16 hi/lo -----------------
__global__ void prep_a_kernel(const float* __restrict__ x, const float* __restrict__ h) {
    size_t idx4 = ((size_t)blockIdx.x * blockDim.x + threadIdx.x) * 4;
    int m = (int)(idx4 / K_DIM);
    int k = (int)(idx4 % K_DIM);
    const float* src = (k < T_DIM) ? (x + (size_t)m * T_DIM + k)
                                   : (h + (size_t)m * U_DIM + (k - T_DIM));
    float4 v = *reinterpret_cast<const float4*>(src);

    __nv_bfloat16 h0 = __float2bfloat16(v.x);
    __nv_bfloat16 h1 = __float2bfloat16(v.y);
    __nv_bfloat16 h2 = __float2bfloat16(v.z);
    __nv_bfloat16 h3 = __float2bfloat16(v.w);
    __nv_bfloat16 l0 = __float2bfloat16(v.x - __bfloat162float(h0));
    __nv_bfloat16 l1 = __float2bfloat16(v.y - __bfloat162float(h1));
    __nv_bfloat16 l2 = __float2bfloat16(v.z - __bfloat162float(h2));
    __nv_bfloat16 l3 = __float2bfloat16(v.w - __bfloat162float(h3));

    union Pack { __nv_bfloat16 b[4]; uint2 u; } ph, pl;
    ph.b[0] = h0; ph.b[1] = h1; ph.b[2] = h2; ph.b[3] = h3;
    pl.b[0] = l0; pl.b[1] = l1; pl.b[2] = l2; pl.b[3] = l3;
    *reinterpret_cast<uint2*>(g_A_hi + idx4) = ph.u;
    *reinterpret_cast<uint2*>(g_A_lo + idx4) = pl.u;
}

// ---------------- prep kernel B: W transpose+convert, gate-interleaved -----
__global__ void prep_w_kernel(const float* __restrict__ Wi, const float* __restrict__ Wf,
                              const float* __restrict__ Wg, const float* __restrict__ Wo) {
    __shared__ float tile[32][33];
    int gate = blockIdx.z;
    const float* W = (gate == 0) ? Wi : (gate == 1) ? Wf : (gate == 2) ? Wg : Wo;
    int k0 = blockIdx.x * 32;
    int u0 = blockIdx.y * 32;
    int tx = threadIdx.x, ty = threadIdx.y;

#pragma unroll
    for (int i = 0; i < 4; i++) {
        int k = k0 + ty + i * 8;
        tile[ty + i * 8][tx] = W[(size_t)k * U_DIM + u0 + tx];  // coalesced over u
    }
    __syncthreads();
#pragma unroll
    for (int i = 0; i < 4; i++) {
        int u = u0 + ty + i * 8;
        float v = tile[tx][ty + i * 8];          // = W[k0+tx, u]
        __nv_bfloat16 hi = __float2bfloat16(v);
        __nv_bfloat16 lo = __float2bfloat16(v - __bfloat162float(hi));
        size_t off = (size_t)(u * 4 + gate) * K_DIM + k0 + tx;  // coalesced over k
        g_W_hi[off] = hi;
        g_W_lo[off] = lo;
    }
}

// ---------------- GEMM + LSTM epilogue -------------------------------------
// SMEM map:
//   [0]      tmem ptr
//   [8]      commit mbar
//   [1024]   stage0: Ah(16K) Al(16K) Bh(32K) Bl(32K) = 96KB
//   [99328]  stage1: same                            = 96KB
// epilogue reuses the (dead) stage region:
//   h_sm / c_sm / ci_sm, each 128 x 65 fp32
#define SM_TMEM 0
#define SM_MBAR 8
#define SM_STAGE 1024
#define A_TILE_BYTES 16384                  // 128 rows x 128B
#define B_TILE_BYTES 32768                  // 256 rows x 128B
#define STAGE_BYTES (2 * A_TILE_BYTES + 2 * B_TILE_BYTES)   // 98304
#define GEMM_SMEM (SM_STAGE + 2 * STAGE_BYTES)              // 197632
#define EP_PAD 65

#if USE_TCGEN05
__device__ __forceinline__ void load_stage(uint32_t sbase, int kt,
                                           int m0, int n0, int tid) {
    int koff = kt * BK;
    // A: 128 rows x 8 chunks of 16B  (hi + lo)
#pragma unroll
    for (int j = 0; j < 4; j++) {
        int i = tid + j * GEMM_THREADS;       // 0..1023
        int r = i >> 3;
        int c = i & 7;
        uint32_t soff = SWZ128((uint32_t)(r * 128 + c * 16));
        size_t ga = (size_t)(m0 + r) * K_DIM + koff + c * 8;
        cp16(sbase + soff, g_A_hi + ga);
        cp16(sbase + A_TILE_BYTES + soff, g_A_lo + ga);
    }
    // B: 256 rows x 8 chunks of 16B  (hi + lo)
    uint32_t bbase = sbase + 2 * A_TILE_BYTES;
#pragma unroll
    for (int j = 0; j < 8; j++) {
        int i = tid + j * GEMM_THREADS;       // 0..2047
        int r = i >> 3;
        int c = i & 7;
        uint32_t soff = SWZ128((uint32_t)(r * 128 + c * 16));
        size_t gb = (size_t)(n0 + r) * K_DIM + koff + c * 8;
        cp16(bbase + soff, g_W_hi + gb);
        cp16(bbase + B_TILE_BYTES + soff, g_W_lo + gb);
    }
}
#endif

__global__ void __launch_bounds__(GEMM_THREADS, 1)
lstm_gemm_kernel(const float* __restrict__ c_in,
                 const float* __restrict__ bi, const float* __restrict__ bf_,
                 const float* __restrict__ bg, const float* __restrict__ bo,
                 float* __restrict__ out) {
    extern __shared__ char smem[];
    int tid = threadIdx.x;
    const size_t c_off = (size_t)B_DIM * U_DIM;

    int n0 = blockIdx.x * BN;          // 16 tiles
    int m0 = blockIdx.y * BM;          // 64 tiles
    int u_base = n0 >> 2;              // 64 u's per tile (4 gates interleaved)

#if USE_TCGEN05
    // ======================= tcgen05 cg1 path ===============================
    uint32_t sb = smem_u32(smem);
    int wid = tid >> 5;
    int lid = tid & 31;

    if (wid == 0) TCGEN05_ALLOC(sb + SM_TMEM, 256);
    if (tid == 0) MBARRIER_INIT(sb + SM_MBAR, 1);
    __syncthreads();
    uint32_t tmem;
    asm volatile("ld.shared.b32 %0, [%1];" : "=r"(tmem) : "r"(sb + SM_TMEM));

    load_stage(sb + SM_STAGE, 0, m0, n0, tid);
    CP_ASYNC_COMMIT();

    int phase = 0;
#pragma unroll 1
    for (int kt = 0; kt < KTILES; kt++) {
        // MMA(kt-1) must finish before load(kt+1) overwrites its stage
        if (kt > 0) { MBARRIER_WAIT_PARITY(sb + SM_MBAR, phase); phase ^= 1; }

        if (kt + 1 < KTILES) {
            load_stage(sb + SM_STAGE + ((kt + 1) & 1) * STAGE_BYTES, kt + 1, m0, n0, tid);
            CP_ASYNC_COMMIT();
            CP_ASYNC_WAIT(1);   // stage kt landed
        } else {
            CP_ASYNC_WAIT(0);
        }
        __syncthreads();

        if (wid == 0) {
            FENCE_PROXY_ASYNC();
            uint32_t st = sb + SM_STAGE + (kt & 1) * STAGE_BYTES;
            uint64_t dAh = make_desc(st);
            uint64_t dAl = make_desc(st + A_TILE_BYTES);
            uint64_t dBh = make_desc(st + 2 * A_TILE_BYTES);
            uint64_t dBl = make_desc(st + 2 * A_TILE_BYTES + B_TILE_BYTES);
            if (elect_one()) {
#pragma unroll
                for (int s = 0; s < 4; s++) {   // 4 x K=16 steps per 64-K tile
                    uint32_t off = s * 2;       // 32B = 2 x 16B units
                    mma_f16_ss(tmem, dAh + off, dBh + off, MMA_IDESC, (kt | s) != 0);
                    mma_f16_ss(tmem, dAh + off, dBl + off, MMA_IDESC, 1u);
                    mma_f16_ss(tmem, dAl + off, dBh + off, MMA_IDESC, 1u);
                }
                TCGEN05_COMMIT(sb + SM_MBAR);
            }
        }
    }

    MBARRIER_WAIT_PARITY(sb + SM_MBAR, phase);
    TCGEN05_FENCE_AFTER();

    // ---------------- epilogue (coalesced via SMEM staging) ----------------
    float* h_sm = reinterpret_cast<float*>(smem + SM_STAGE);
    float* c_sm = h_sm + 128 * EP_PAD;
    float* ci_sm = c_sm + 128 * EP_PAD;

    // stage c_in tile coalesced: 128 rows x 64 u (float4 LDG)
#pragma unroll
    for (int i = tid; i < 128 * 16; i += GEMM_THREADS) {
        int row = i >> 4;
        int q = i & 15;
        float4 v = *reinterpret_cast<const float4*>(
            c_in + (size_t)(m0 + row) * U_DIM + u_base + q * 4);
        int base = row * EP_PAD + q * 4;
        ci_sm[base + 0] = v.x; ci_sm[base + 1] = v.y;
        ci_sm[base + 2] = v.z; ci_sm[base + 3] = v.w;
    }
    __syncthreads();

    // D[128 rows, 256 cols] fp32 in TMEM.
    // warp w: rows (w&3)*32 + lid ; col half (w>>2)*128, 4 chunks of 32 cols.
    int sub = wid & 3;
    int half = wid >> 2;
    int row = sub * 32 + lid;

#pragma unroll
    for (int ch = 0; ch < 4; ch++) {
        uint32_t col = (uint32_t)(half * 128 + ch * 32);
        uint32_t d[32];
        TCGEN05_LD_32X32B_X32(d, tmem + col);
        TCGEN05_WAIT_LD();
#pragma unroll
        for (int j = 0; j < 8; j++) {
            int ul = half * 32 + ch * 8 + j;     // u within the 64-u tile
            int u = u_base + ul;
            float zi = __uint_as_float(d[4 * j + 0]) + bi[u];
            float zf = __uint_as_float(d[4 * j + 1]) + bf_[u];
            float zg = __uint_as_float(d[4 * j + 2]) + bg[u];
            float zo = __uint_as_float(d[4 * j + 3]) + bo[u];
            float ig = fast_sigmoid(zi);
            float fg = fast_sigmoid(zf);
            float gg = tanhf(zg);
            float og = fast_sigmoid(zo);
            float cv = ci_sm[row * EP_PAD + ul];
            float cn = fg * cv + ig * gg;
            float hn = og * tanhf(cn);
            h_sm[row * EP_PAD + ul] = hn;
            c_sm[row * EP_PAD + ul] = cn;
        }
    }
    TCGEN05_FENCE_BEFORE();
    __syncthreads();

    // cooperative coalesced store: consecutive tids -> consecutive u
#pragma unroll
    for (int i = tid; i < 128 * 64; i += GEMM_THREADS) {
        int r = i >> 6;
        int u = i & 63;
        size_t g = (size_t)(m0 + r) * U_DIM + u_base + u;
        out[g] = h_sm[r * EP_PAD + u];
        out[c_off + g] = c_sm[r * EP_PAD + u];
    }

    __syncthreads();
    if (tid == 0) MBARRIER_INVAL(sb + SM_MBAR);
    __syncthreads();
    if (wid == 0) TCGEN05_DEALLOC(tmem, 256);

#else
    // ======================= SIMT fallback (plain sm_103 target) ===========
    const int PAD = 132;
    float* As = reinterpret_cast<float*>(smem);          // [32][PAD]
    float* Bs = As + 32 * PAD;                           // [32][PAD]

    int tx = tid & 15;
    int ty = tid >> 4;

#pragma unroll 1
    for (int ns = 0; ns < 2; ns++) {                     // two 128-wide n halves
        int n0h = n0 + ns * 128;
        int u0 = n0h >> 2;
        float acc[8][8];
#pragma unroll
        for (int i = 0; i < 8; i++)
#pragma unroll
            for (int j = 0; j < 8; j++) acc[i][j] = 0.0f;

#pragma unroll 1
        for (int kt = 0; kt < K_DIM / 32; kt++) {
            int koff = kt * 32;
#pragma unroll
            for (int i = 0; i < 16; i++) {
                int idx = tid + i * 256;
                int kk = idx & 31;
                int r = idx >> 5;
                size_t ga = (size_t)(m0 + r) * K_DIM + koff + kk;
                size_t gb = (size_t)(n0h + r) * K_DIM + koff + kk;
                As[kk * PAD + r] = __bfloat162float(g_A_hi[ga]) + __bfloat162float(g_A_lo[ga]);
                Bs[kk * PAD + r] = __bfloat162float(g_W_hi[gb]) + __bfloat162float(g_W_lo[gb]);
            }
            __syncthreads();
#pragma unroll 1
            for (int kk = 0; kk < 32; kk++) {
                float a[8], b[8];
#pragma unroll
                for (int i = 0; i < 8; i++) a[i] = As[kk * PAD + ty * 8 + i];
#pragma unroll
                for (int j = 0; j < 8; j++) b[j] = Bs[kk * PAD + tx * 8 + j];
#pragma unroll
                for (int i = 0; i < 8; i++)
#pragma unroll
                    for (int j = 0; j < 8; j++) acc[i][j] += a[i] * b[j];
            }
            __syncthreads();
        }

#pragma unroll
        for (int i = 0; i < 8; i++) {
            int m = m0 + ty * 8 + i;
#pragma unroll
            for (int jj = 0; jj < 2; jj++) {
                int u = u0 + tx * 2 + jj;
                float zi = acc[i][jj * 4 + 0] + bi[u];
                float zf = acc[i][jj * 4 + 1] + bf_[u];
                float zg = acc[i][jj * 4 + 2] + bg[u];
                float zo = acc[i][jj * 4 + 3] + bo[u];
                float ig = fast_sigmoid(zi);
                float fg = fast_sigmoid(zf);
                float gg = tanhf(zg);
                float og = fast_sigmoid(zo);
                float cv = c_in[(size_t)m * U_DIM + u];
                float cn = fg * cv + ig * gg;
                float hn = og * tanhf(cn);
                out[(size_t)m * U_DIM + u] = hn;
                out[c_off + (size_t)m * U_DIM + u] = cn;
            }
        }
        __syncthreads();
    }
#endif
}

// ---------------- launch ----------------------------------------------------
extern "C" void kernel_launch(void* const* d_in, const int* in_sizes, int n_in,
                              void* d_out, int out_size) {
    const float* x  = (const float*)d_in[0];
    const float* h  = (const float*)d_in[1];
    const float* c  = (const float*)d_in[2];
    const float* Wi = (const float*)d_in[3];
    const float* Wf = (const float*)d_in[4];
    const float* Wg = (const float*)d_in[5];
    const float* Wo = (const float*)d_in[6];
    const float* bi = (const float*)d_in[7];
    const float* bf = (const float*)d_in[8];
    const float* bg = (const float*)d_in[9];
    const float* bo = (const float*)d_in[10];
    float* out = (float*)d_out;

    // 1) concat+split A
    prep_a_kernel<<<(int)(((size_t)B_DIM * K_DIM / 4) / 256), 256>>>(x, h);
    // 2) transpose+split W (gate-interleaved columns)
    prep_w_kernel<<<dim3(K_DIM / 32, U_DIM / 32, 4), dim3(32, 8)>>>(Wi, Wf, Wg, Wo);
    // 3) GEMM + LSTM epilogue: cg1, 128x256 tiles
    cudaFuncSetAttribute(lstm_gemm_kernel,
                         cudaFuncAttributeMaxDynamicSharedMemorySize, GEMM_SMEM);
    lstm_gemm_kernel<<<dim3(N_DIM / BN, B_DIM / BM), GEMM_THREADS, GEMM_SMEM>>>(
        c, bi, bf, bg, bo, out);
}

// round 5
// speedup vs baseline: 2.4507x; 1.6354x over previous
#include <cuda_runtime.h>
#include <cuda_fp16.h>
#include <cstdint>

// ============================================================================
// CellLSTM on GB300 (sm_103a)
//   z = [x|h] @ [Wi|Wf|Wg|Wo] + b ; gates; c' = f*c + i*g ; h' = o*tanh(c')
//   R5: single-pass fp16 tcgen05 GEMM (fp32 TMEM accum). fp16's 11 mantissa
//   bits give z rel-rms ~4e-4 < 1e-3 gate, at HALF the operand traffic and
//   1/3 the MMA dispatches of the R2-R4 bf16x3 split. 48KB stages -> 2 CTAs
//   per SM for natural load/MMA overlap. Loop structure identical to R4.
// ============================================================================

#if defined(__CUDA_ARCH_FEAT_SM103_ALL) || defined(__CUDA_ARCH_FEAT_SM100_ALL)
#define USE_TCGEN05 1
#else
#define USE_TCGEN05 0
#endif

#define B_DIM 8192
#define T_DIM 1024
#define U_DIM 1024
#define K_DIM 2048
#define N_DIM 4096

#define BM 128
#define BN 256
#define BK 64
#define KTILES (K_DIM / BK)   // 32
#define GEMM_THREADS 256

// ---------------- scratch (device globals: allocation-rule-safe) -----------
__device__ __align__(16) __half g_A_h[(size_t)B_DIM * K_DIM];
// W transposed & gate-interleaved: row n = u*4 + gate, K-major
__device__ __align__(16) __half g_W_h[(size_t)N_DIM * K_DIM];

// ---------------- arch-neutral helpers -------------------------------------
__device__ __forceinline__ uint32_t smem_u32(const void* p) {
    uint32_t a;
    asm("{ .reg .u64 t; cvta.to.shared.u64 t, %1; cvt.u32.u64 %0, t; }"
        : "=r"(a) : "l"(p));
    return a;
}

#define SWZ128(off) ((off) ^ (((off) >> 3) & 0x70))

__device__ __forceinline__ float fast_sigmoid(float z) {
    return 1.0f / (1.0f + __expf(-z));
}

#if USE_TCGEN05
// ---------------- tcgen05 / mbarrier / cp.async helpers --------------------
__device__ __forceinline__ uint32_t elect_one() {
    uint32_t pred;
    asm volatile(
        "{\n\t.reg .pred p;\n\telect.sync _|p, 0xFFFFFFFF;\n\t"
        "selp.b32 %0, 1, 0, p;\n\t}" : "=r"(pred));
    return pred;
}

#define MBARRIER_INIT(addr, cnt) \
    asm volatile("mbarrier.init.shared.b64 [%0], %1;" \
                 :: "r"((uint32_t)(addr)), "r"((uint32_t)(cnt)) : "memory")

#define MBARRIER_INVAL(addr) \
    asm volatile("mbarrier.inval.shared.b64 [%0];" \
                 :: "r"((uint32_t)(addr)) : "memory")

#define MBARRIER_WAIT_PARITY(mbar_smem_addr, phase_parity) do { \
    uint32_t _mbar = (uint32_t)(mbar_smem_addr); \
    uint32_t _parity = (uint32_t)(phase_parity); \
    uint32_t _done; \
    asm volatile( \
        "{\n\t.reg .pred p;\n\t" \
        "mbarrier.try_wait.parity.acquire.cta.shared::cta.b64 p, [%1], %2;\n\t" \
        "selp.b32 %0, 1, 0, p;\n\t}" \
        : "=r"(_done) : "r"(_mbar), "r"(_parity) : "memory"); \
    if (!_done) { \
        asm volatile( \
            "{\n\t.reg .pred P1;\n\t" \
            "WAIT_LOOP_%=:\n\t" \
            "mbarrier.try_wait.parity.acquire.cta.shared::cta.b64 P1, [%0], %1, 0x989680;\n\t" \
            "@P1 bra.uni WAIT_DONE_%=;\n\t" \
            "bra.uni WAIT_LOOP_%=;\n\t" \
            "WAIT_DONE_%=:\n\t}" \
            :: "r"(_mbar), "r"(_parity) : "memory"); \
    } \
} while (0)

#define TCGEN05_ALLOC(smem_result_addr, nCols) \
    asm volatile("tcgen05.alloc.cta_group::1.sync.aligned.shared::cta.b32 [%0], %1;" \
                 :: "r"((uint32_t)(smem_result_addr)), "r"((uint32_t)(nCols)) : "memory")

#define TCGEN05_DEALLOC(tmem_addr, nCols) \
    asm volatile("tcgen05.dealloc.cta_group::1.sync.aligned.b32 %0, %1;" \
                 :: "r"(tmem_addr), "r"((uint32_t)(nCols)))

#define TCGEN05_COMMIT(mbar_smem_addr) \
    asm volatile("tcgen05.commit.cta_group::1.mbarrier::arrive::one.shared::cluster.b64 [%0];" \
                 :: "r"((uint32_t)(mbar_smem_addr)) : "memory")

#define TCGEN05_FENCE_AFTER() \
    asm volatile("tcgen05.fence::after_thread_sync;" ::: "memory")
#define TCGEN05_FENCE_BEFORE() \
    asm volatile("tcgen05.fence::before_thread_sync;" ::: "memory")
#define TCGEN05_WAIT_LD() \
    asm volatile("tcgen05.wait::ld.sync.aligned;" ::: "memory")

#define FENCE_PROXY_ASYNC() \
    asm volatile("fence.proxy.async.shared::cta;" ::: "memory")

#define CP_ASYNC_COMMIT() asm volatile("cp.async.commit_group;" ::: "memory")
#define CP_ASYNC_WAIT(n)  asm volatile("cp.async.wait_group %0;" :: "n"(n) : "memory")

__device__ __forceinline__ void cp16(uint32_t dst, const void* src) {
    asm volatile("cp.async.cg.shared.global [%0], [%1], 16;"
                 :: "r"(dst), "l"(src) : "memory");
}

#define TCGEN05_LD_32X32B_X32(r, tmem_addr) \
    asm volatile( \
        "tcgen05.ld.sync.aligned.32x32b.x32.b32 " \
        "{%0, %1, %2, %3, %4, %5, %6, %7, " \
        " %8, %9, %10, %11, %12, %13, %14, %15, " \
        " %16, %17, %18, %19, %20, %21, %22, %23, " \
        " %24, %25, %26, %27, %28, %29, %30, %31}, [%32];" \
        : "=r"((r)[0]),  "=r"((r)[1]),  "=r"((r)[2]),  "=r"((r)[3]), \
          "=r"((r)[4]),  "=r"((r)[5]),  "=r"((r)[6]),  "=r"((r)[7]), \
          "=r"((r)[8]),  "=r"((r)[9]),  "=r"((r)[10]), "=r"((r)[11]), \
          "=r"((r)[12]), "=r"((r)[13]), "=r"((r)[14]), "=r"((r)[15]), \
          "=r"((r)[16]), "=r"((r)[17]), "=r"((r)[18]), "=r"((r)[19]), \
          "=r"((r)[20]), "=r"((r)[21]), "=r"((r)[22]), "=r"((r)[23]), \
          "=r"((r)[24]), "=r"((r)[25]), "=r"((r)[26]), "=r"((r)[27]), \
          "=r"((r)[28]), "=r"((r)[29]), "=r"((r)[30]), "=r"((r)[31]) \
        : "r"(tmem_addr))

// K-major SW128 smem descriptor (verified: test_mma_iter)
static constexpr uint64_t SMEM_DESC_BASE_SW128 =
    (uint64_t(2)  << 61) | (uint64_t(1) << 46) |
    (uint64_t(64) << 32) | (uint64_t(1) << 16);

__device__ __forceinline__ uint64_t make_desc(uint32_t addr) {
    return SMEM_DESC_BASE_SW128 | ((uint64_t)(addr >> 4) & 0x3FFF);
}

// idesc kind::f16, FP16 inputs (atype=btype=0), f32 accum, M=128, N=256
static constexpr uint32_t MMA_IDESC =
    (1u << 4) | (0u << 7) | (0u << 10) | ((BN / 8) << 17) | ((BM / 16) << 24);

__device__ __forceinline__ void mma_f16_ss(uint32_t d, uint64_t ad, uint64_t bd,
                                           uint32_t idesc, uint32_t acc) {
    asm volatile(
        "{\n\t.reg .pred p;\n\t"
        "setp.ne.u32 p, %4, 0;\n\t"
        "tcgen05.mma.cta_group::1.kind::f16 [%0], %1, %2, %3, {%5, %5, %5, %5}, p;\n\t"
        "}"
        :: "r"(d), "l"(ad), "l"(bd), "r"(idesc), "r"(acc), "r"(0u)
        : "memory");
}
#endif // USE_TCGEN05

// ---------------- prep kernel A: concat(x,h) -> fp16 -----------------------
__global__ void prep_a_kernel(const float* __restrict__ x, const float* __restrict__ h) {
    size_t idx8 = ((size_t)blockIdx.x * blockDim.x + threadIdx.x) * 8;
    int m = (int)(idx8 / K_DIM);
    int k = (int)(idx8 % K_DIM);
    const float* src = (k < T_DIM) ? (x + (size_t)m * T_DIM + k)
                                   : (h + (size_t)m * U_DIM + (k - T_DIM));
    float4 v0 = *reinterpret_cast<const float4*>(src);
    float4 v1 = *reinterpret_cast<const float4*>(src + 4);

    union Pack { __half b[8]; uint4 u; } p;
    p.b[0] = __float2half_rn(v0.x); p.b[1] = __float2half_rn(v0.y);
    p.b[2] = __float2half_rn(v0.z); p.b[3] = __float2half_rn(v0.w);
    p.b[4] = __float2half_rn(v1.x); p.b[5] = __float2half_rn(v1.y);
    p.b[6] = __float2half_rn(v1.z); p.b[7] = __float2half_rn(v1.w);
    *reinterpret_cast<uint4*>(g_A_h + idx8) = p.u;
}

// ---------------- prep kernel B: W transpose+convert, gate-interleaved -----
__global__ void prep_w_kernel(const float* __restrict__ Wi, const float* __restrict__ Wf,
                              const float* __restrict__ Wg, const float* __restrict__ Wo) {
    __shared__ float tile[32][33];
    int gate = blockIdx.z;
    const float* W = (gate == 0) ? Wi : (gate == 1) ? Wf : (gate == 2) ? Wg : Wo;
    int k0 = blockIdx.x * 32;
    int u0 = blockIdx.y * 32;
    int tx = threadIdx.x, ty = threadIdx.y;

#pragma unroll
    for (int i = 0; i < 4; i++) {
        int k = k0 + ty + i * 8;
        tile[ty + i * 8][tx] = W[(size_t)k * U_DIM + u0 + tx];  // coalesced over u
    }
    __syncthreads();
#pragma unroll
    for (int i = 0; i < 4; i++) {
        int u = u0 + ty + i * 8;
        float v = tile[tx][ty + i * 8];          // = W[k0+tx, u]
        size_t off = (size_t)(u * 4 + gate) * K_DIM + k0 + tx;  // coalesced over k
        g_W_h[off] = __float2half_rn(v);
    }
}

// ---------------- GEMM + LSTM epilogue -------------------------------------
// SMEM map:
//   [0]      tmem ptr
//   [8]      commit mbar
//   [1024]   stage0: Ah(16K) Bh(32K) = 48KB
//   [50176]  stage1: same            = 48KB
// epilogue reuses the (dead) stage region: h_sm / c_sm / ci_sm, 128 x 65 fp32
#define SM_TMEM 0
#define SM_MBAR 8
#define SM_STAGE 1024
#define A_TILE_BYTES 16384                  // 128 rows x 128B
#define B_TILE_BYTES 32768                  // 256 rows x 128B
#define STAGE_BYTES (A_TILE_BYTES + B_TILE_BYTES)           // 49152
#define EP_PAD 65
#define EP_BYTES (3 * 128 * EP_PAD * 4)                     // 99840
#define GEMM_SMEM (SM_STAGE + EP_BYTES)                     // 100864 (> 2 stages)

#if USE_TCGEN05
__device__ __forceinline__ void load_stage(uint32_t sbase, int kt,
                                           int m0, int n0, int tid) {
    int koff = kt * BK;
    // A: 128 rows x 8 chunks of 16B
#pragma unroll
    for (int j = 0; j < 4; j++) {
        int i = tid + j * GEMM_THREADS;       // 0..1023
        int r = i >> 3;
        int c = i & 7;
        uint32_t soff = SWZ128((uint32_t)(r * 128 + c * 16));
        size_t ga = (size_t)(m0 + r) * K_DIM + koff + c * 8;
        cp16(sbase + soff, g_A_h + ga);
    }
    // B: 256 rows x 8 chunks of 16B
    uint32_t bbase = sbase + A_TILE_BYTES;
#pragma unroll
    for (int j = 0; j < 8; j++) {
        int i = tid + j * GEMM_THREADS;       // 0..2047
        int r = i >> 3;
        int c = i & 7;
        uint32_t soff = SWZ128((uint32_t)(r * 128 + c * 16));
        size_t gb = (size_t)(n0 + r) * K_DIM + koff + c * 8;
        cp16(bbase + soff, g_W_h + gb);
    }
}
#endif

__global__ void __launch_bounds__(GEMM_THREADS)
lstm_gemm_kernel(const float* __restrict__ c_in,
                 const float* __restrict__ bi, const float* __restrict__ bf_,
                 const float* __restrict__ bg, const float* __restrict__ bo,
                 float* __restrict__ out) {
    extern __shared__ char smem[];
    int tid = threadIdx.x;
    const size_t c_off = (size_t)B_DIM * U_DIM;

    int n0 = blockIdx.x * BN;          // 16 tiles
    int m0 = blockIdx.y * BM;          // 64 tiles
    int u_base = n0 >> 2;              // 64 u's per tile (4 gates interleaved)

#if USE_TCGEN05
    // ======================= tcgen05 cg1 path ===============================
    uint32_t sb = smem_u32(smem);
    int wid = tid >> 5;
    int lid = tid & 31;

    if (wid == 0) TCGEN05_ALLOC(sb + SM_TMEM, 256);
    if (tid == 0) MBARRIER_INIT(sb + SM_MBAR, 1);
    __syncthreads();
    uint32_t tmem;
    asm volatile("ld.shared.b32 %0, [%1];" : "=r"(tmem) : "r"(sb + SM_TMEM));

    load_stage(sb + SM_STAGE, 0, m0, n0, tid);
    CP_ASYNC_COMMIT();

    int phase = 0;
#pragma unroll 1
    for (int kt = 0; kt < KTILES; kt++) {
        // MMA(kt-1) must finish before load(kt+1) overwrites its stage
        if (kt > 0) { MBARRIER_WAIT_PARITY(sb + SM_MBAR, phase); phase ^= 1; }

        if (kt + 1 < KTILES) {
            load_stage(sb + SM_STAGE + ((kt + 1) & 1) * STAGE_BYTES, kt + 1, m0, n0, tid);
            CP_ASYNC_COMMIT();
            CP_ASYNC_WAIT(1);   // stage kt landed
        } else {
            CP_ASYNC_WAIT(0);
        }
        __syncthreads();

        if (wid == 0) {
            FENCE_PROXY_ASYNC();
            uint32_t st = sb + SM_STAGE + (kt & 1) * STAGE_BYTES;
            uint64_t dA = make_desc(st);
            uint64_t dB = make_desc(st + A_TILE_BYTES);
            if (elect_one()) {
#pragma unroll
                for (int s = 0; s < 4; s++) {   // 4 x K=16 steps per 64-K tile
                    uint32_t off = s * 2;       // 32B = 2 x 16B units
                    mma_f16_ss(tmem, dA + off, dB + off, MMA_IDESC, (kt | s) != 0);
                }
                TCGEN05_COMMIT(sb + SM_MBAR);
            }
        }
    }

    MBARRIER_WAIT_PARITY(sb + SM_MBAR, phase);
    TCGEN05_FENCE_AFTER();

    // ---------------- epilogue (coalesced via SMEM staging) ----------------
    float* h_sm = reinterpret_cast<float*>(smem + SM_STAGE);
    float* c_sm = h_sm + 128 * EP_PAD;
    float* ci_sm = c_sm + 128 * EP_PAD;

    // stage c_in tile coalesced: 128 rows x 64 u (float4 LDG)
#pragma unroll
    for (int i = tid; i < 128 * 16; i += GEMM_THREADS) {
        int row = i >> 4;
        int q = i & 15;
        float4 v = *reinterpret_cast<const float4*>(
            c_in + (size_t)(m0 + row) * U_DIM + u_base + q * 4);
        int base = row * EP_PAD + q * 4;
        ci_sm[base + 0] = v.x; ci_sm[base + 1] = v.y;
        ci_sm[base + 2] = v.z; ci_sm[base + 3] = v.w;
    }
    __syncthreads();

    // D[128 rows, 256 cols] fp32 in TMEM.
    // warp w: rows (w&3)*32 + lid ; col half (w>>2)*128, 4 chunks of 32 cols.
    int sub = wid & 3;
    int half = wid >> 2;
    int row = sub * 32 + lid;

#pragma unroll
    for (int ch = 0; ch < 4; ch++) {
        uint32_t col = (uint32_t)(half * 128 + ch * 32);
        uint32_t d[32];
        TCGEN05_LD_32X32B_X32(d, tmem + col);
        TCGEN05_WAIT_LD();
#pragma unroll
        for (int j = 0; j < 8; j++) {
            int ul = half * 32 + ch * 8 + j;     // u within the 64-u tile
            int u = u_base + ul;
            float zi = __uint_as_float(d[4 * j + 0]) + bi[u];
            float zf = __uint_as_float(d[4 * j + 1]) + bf_[u];
            float zg = __uint_as_float(d[4 * j + 2]) + bg[u];
            float zo = __uint_as_float(d[4 * j + 3]) + bo[u];
            float ig = fast_sigmoid(zi);
            float fg = fast_sigmoid(zf);
            float gg = tanhf(zg);
            float og = fast_sigmoid(zo);
            float cv = ci_sm[row * EP_PAD + ul];
            float cn = fg * cv + ig * gg;
            float hn = og * tanhf(cn);
            h_sm[row * EP_PAD + ul] = hn;
            c_sm[row * EP_PAD + ul] = cn;
        }
    }
    TCGEN05_FENCE_BEFORE();
    __syncthreads();

    // cooperative coalesced store: consecutive tids -> consecutive u
#pragma unroll
    for (int i = tid; i < 128 * 64; i += GEMM_THREADS) {
        int r = i >> 6;
        int u = i & 63;
        size_t g = (size_t)(m0 + r) * U_DIM + u_base + u;
        out[g] = h_sm[r * EP_PAD + u];
        out[c_off + g] = c_sm[r * EP_PAD + u];
    }

    __syncthreads();
    if (tid == 0) MBARRIER_INVAL(sb + SM_MBAR);
    __syncthreads();
    if (wid == 0) TCGEN05_DEALLOC(tmem, 256);

#else
    // ======================= SIMT fallback (plain sm_103 target) ===========
    const int PAD = 132;
    float* As = reinterpret_cast<float*>(smem);          // [32][PAD]
    float* Bs = As + 32 * PAD;                           // [32][PAD]

    int tx = tid & 15;
    int ty = tid >> 4;

#pragma unroll 1
    for (int ns = 0; ns < 2; ns++) {                     // two 128-wide n halves
        int n0h = n0 + ns * 128;
        int u0 = n0h >> 2;
        float acc[8][8];
#pragma unroll
        for (int i = 0; i < 8; i++)
#pragma unroll
            for (int j = 0; j < 8; j++) acc[i][j] = 0.0f;

#pragma unroll 1
        for (int kt = 0; kt < K_DIM / 32; kt++) {
            int koff = kt * 32;
#pragma unroll
            for (int i = 0; i < 16; i++) {
                int idx = tid + i * 256;
                int kk = idx & 31;
                int r = idx >> 5;
                size_t ga = (size_t)(m0 + r) * K_DIM + koff + kk;
                size_t gb = (size_t)(n0h + r) * K_DIM + koff + kk;
                As[kk * PAD + r] = __half2float(g_A_h[ga]);
                Bs[kk * PAD + r] = __half2float(g_W_h[gb]);
            }
            __syncthreads();
#pragma unroll 1
            for (int kk = 0; kk < 32; kk++) {
                float a[8], b[8];
#pragma unroll
                for (int i = 0; i < 8; i++) a[i] = As[kk * PAD + ty * 8 + i];
#pragma unroll
                for (int j = 0; j < 8; j++) b[j] = Bs[kk * PAD + tx * 8 + j];
#pragma unroll
                for (int i = 0; i < 8; i++)
#pragma unroll
                    for (int j = 0; j < 8; j++) acc[i][j] += a[i] * b[j];
            }
            __syncthreads();
        }

#pragma unroll
        for (int i = 0; i < 8; i++) {
            int m = m0 + ty * 8 + i;
#pragma unroll
            for (int jj = 0; jj < 2; jj++) {
                int u = u0 + tx * 2 + jj;
                float zi = acc[i][jj * 4 + 0] + bi[u];
                float zf = acc[i][jj * 4 + 1] + bf_[u];
                float zg = acc[i][jj * 4 + 2] + bg[u];
                float zo = acc[i][jj * 4 + 3] + bo[u];
                float ig = fast_sigmoid(zi);
                float fg = fast_sigmoid(zf);
                float gg = tanhf(zg);
                float og = fast_sigmoid(zo);
                float cv = c_in[(size_t)m * U_DIM + u];
                float cn = fg * cv + ig * gg;
                float hn = og * tanhf(cn);
                out[(size_t)m * U_DIM + u] = hn;
                out[c_off + (size_t)m * U_DIM + u] = cn;
            }
        }
        __syncthreads();
    }
#endif
}

// ---------------- launch ----------------------------------------------------
extern "C" void kernel_launch(void* const* d_in, const int* in_sizes, int n_in,
                              void* d_out, int out_size) {
    const float* x  = (const float*)d_in[0];
    const float* h  = (const float*)d_in[1];
    const float* c  = (const float*)d_in[2];
    const float* Wi = (const float*)d_in[3];
    const float* Wf = (const float*)d_in[4];
    const float* Wg = (const float*)d_in[5];
    const float* Wo = (const float*)d_in[6];
    const float* bi = (const float*)d_in[7];
    const float* bf = (const float*)d_in[8];
    const float* bg = (const float*)d_in[9];
    const float* bo = (const float*)d_in[10];
    float* out = (float*)d_out;

    // 1) concat -> fp16 A
    prep_a_kernel<<<(int)(((size_t)B_DIM * K_DIM / 8) / 256), 256>>>(x, h);
    // 2) transpose -> fp16 W (gate-interleaved columns)
    prep_w_kernel<<<dim3(K_DIM / 32, U_DIM / 32, 4), dim3(32, 8)>>>(Wi, Wf, Wg, Wo);
    // 3) GEMM + LSTM epilogue: cg1, 128x256 tiles, fp16 single-pass
    cudaFuncSetAttribute(lstm_gemm_kernel,
                         cudaFuncAttributeMaxDynamicSharedMemorySize, GEMM_SMEM);
    lstm_gemm_kernel<<<dim3(N_DIM / BN, B_DIM / BM), GEMM_THREADS, GEMM_SMEM>>>(
        c, bi, bf, bg, bo, out);
}

// round 6
// speedup vs baseline: 2.5944x; 1.0586x over previous
#include <cuda_runtime.h>
#include <cuda_fp16.h>
#include <cstdint>

// ============================================================================
// CellLSTM on GB300 (sm_103a)
//   z = [x|h] @ [Wi|Wf|Wg|Wo] + b ; gates; c' = f*c + i*g ; h' = o*tanh(c')
//   R6: fp16 tcgen05, 256x256 tiles via TWO M=128 MMA streams sharing one B
//   SMEM tile (2 x 256 TMEM cols). Halves W-side LTS traffic vs R5
//   (1.61GB -> 1.03GB) with zero cluster synchronization.
// ============================================================================

#if defined(__CUDA_ARCH_FEAT_SM103_ALL) || defined(__CUDA_ARCH_FEAT_SM100_ALL)
#define USE_TCGEN05 1
#else
#define USE_TCGEN05 0
#endif

#define B_DIM 8192
#define T_DIM 1024
#define U_DIM 1024
#define K_DIM 2048
#define N_DIM 4096

#define BM 256              // two M=128 MMA halves
#define BN 256
#define BK 64
#define KTILES (K_DIM / BK)   // 32
#define GEMM_THREADS 256

// ---------------- scratch (device globals: allocation-rule-safe) -----------
__device__ __align__(16) __half g_A_h[(size_t)B_DIM * K_DIM];
// W transposed & gate-interleaved: row n = u*4 + gate, K-major
__device__ __align__(16) __half g_W_h[(size_t)N_DIM * K_DIM];

// ---------------- arch-neutral helpers -------------------------------------
__device__ __forceinline__ uint32_t smem_u32(const void* p) {
    uint32_t a;
    asm("{ .reg .u64 t; cvta.to.shared.u64 t, %1; cvt.u32.u64 %0, t; }"
        : "=r"(a) : "l"(p));
    return a;
}

#define SWZ128(off) ((off) ^ (((off) >> 3) & 0x70))

__device__ __forceinline__ float fast_sigmoid(float z) {
    return 1.0f / (1.0f + __expf(-z));
}

#if USE_TCGEN05
// ---------------- tcgen05 / mbarrier / cp.async helpers --------------------
__device__ __forceinline__ uint32_t elect_one() {
    uint32_t pred;
    asm volatile(
        "{\n\t.reg .pred p;\n\telect.sync _|p, 0xFFFFFFFF;\n\t"
        "selp.b32 %0, 1, 0, p;\n\t}" : "=r"(pred));
    return pred;
}

#define MBARRIER_INIT(addr, cnt) \
    asm volatile("mbarrier.init.shared.b64 [%0], %1;" \
                 :: "r"((uint32_t)(addr)), "r"((uint32_t)(cnt)) : "memory")

#define MBARRIER_INVAL(addr) \
    asm volatile("mbarrier.inval.shared.b64 [%0];" \
                 :: "r"((uint32_t)(addr)) : "memory")

#define MBARRIER_WAIT_PARITY(mbar_smem_addr, phase_parity) do { \
    uint32_t _mbar = (uint32_t)(mbar_smem_addr); \
    uint32_t _parity = (uint32_t)(phase_parity); \
    uint32_t _done; \
    asm volatile( \
        "{\n\t.reg .pred p;\n\t" \
        "mbarrier.try_wait.parity.acquire.cta.shared::cta.b64 p, [%1], %2;\n\t" \
        "selp.b32 %0, 1, 0, p;\n\t}" \
        : "=r"(_done) : "r"(_mbar), "r"(_parity) : "memory"); \
    if (!_done) { \
        asm volatile( \
            "{\n\t.reg .pred P1;\n\t" \
            "WAIT_LOOP_%=:\n\t" \
            "mbarrier.try_wait.parity.acquire.cta.shared::cta.b64 P1, [%0], %1, 0x989680;\n\t" \
            "@P1 bra.uni WAIT_DONE_%=;\n\t" \
            "bra.uni WAIT_LOOP_%=;\n\t" \
            "WAIT_DONE_%=:\n\t}" \
            :: "r"(_mbar), "r"(_parity) : "memory"); \
    } \
} while (0)

#define TCGEN05_ALLOC(smem_result_addr, nCols) \
    asm volatile("tcgen05.alloc.cta_group::1.sync.aligned.shared::cta.b32 [%0], %1;" \
                 :: "r"((uint32_t)(smem_result_addr)), "r"((uint32_t)(nCols)) : "memory")

#define TCGEN05_DEALLOC(tmem_addr, nCols) \
    asm volatile("tcgen05.dealloc.cta_group::1.sync.aligned.b32 %0, %1;" \
                 :: "r"(tmem_addr), "r"((uint32_t)(nCols)))

#define TCGEN05_COMMIT(mbar_smem_addr) \
    asm volatile("tcgen05.commit.cta_group::1.mbarrier::arrive::one.shared::cluster.b64 [%0];" \
                 :: "r"((uint32_t)(mbar_smem_addr)) : "memory")

#define TCGEN05_FENCE_AFTER() \
    asm volatile("tcgen05.fence::after_thread_sync;" ::: "memory")
#define TCGEN05_FENCE_BEFORE() \
    asm volatile("tcgen05.fence::before_thread_sync;" ::: "memory")
#define TCGEN05_WAIT_LD() \
    asm volatile("tcgen05.wait::ld.sync.aligned;" ::: "memory")

#define FENCE_PROXY_ASYNC() \
    asm volatile("fence.proxy.async.shared::cta;" ::: "memory")

#define CP_ASYNC_COMMIT() asm volatile("cp.async.commit_group;" ::: "memory")
#define CP_ASYNC_WAIT(n)  asm volatile("cp.async.wait_group %0;" :: "n"(n) : "memory")

__device__ __forceinline__ void cp16(uint32_t dst, const void* src) {
    asm volatile("cp.async.cg.shared.global [%0], [%1], 16;"
                 :: "r"(dst), "l"(src) : "memory");
}

#define TCGEN05_LD_32X32B_X32(r, tmem_addr) \
    asm volatile( \
        "tcgen05.ld.sync.aligned.32x32b.x32.b32 " \
        "{%0, %1, %2, %3, %4, %5, %6, %7, " \
        " %8, %9, %10, %11, %12, %13, %14, %15, " \
        " %16, %17, %18, %19, %20, %21, %22, %23, " \
        " %24, %25, %26, %27, %28, %29, %30, %31}, [%32];" \
        : "=r"((r)[0]),  "=r"((r)[1]),  "=r"((r)[2]),  "=r"((r)[3]), \
          "=r"((r)[4]),  "=r"((r)[5]),  "=r"((r)[6]),  "=r"((r)[7]), \
          "=r"((r)[8]),  "=r"((r)[9]),  "=r"((r)[10]), "=r"((r)[11]), \
          "=r"((r)[12]), "=r"((r)[13]), "=r"((r)[14]), "=r"((r)[15]), \
          "=r"((r)[16]), "=r"((r)[17]), "=r"((r)[18]), "=r"((r)[19]), \
          "=r"((r)[20]), "=r"((r)[21]), "=r"((r)[22]), "=r"((r)[23]), \
          "=r"((r)[24]), "=r"((r)[25]), "=r"((r)[26]), "=r"((r)[27]), \
          "=r"((r)[28]), "=r"((r)[29]), "=r"((r)[30]), "=r"((r)[31]) \
        : "r"(tmem_addr))

// K-major SW128 smem descriptor (verified: test_mma_iter)
static constexpr uint64_t SMEM_DESC_BASE_SW128 =
    (uint64_t(2)  << 61) | (uint64_t(1) << 46) |
    (uint64_t(64) << 32) | (uint64_t(1) << 16);

__device__ __forceinline__ uint64_t make_desc(uint32_t addr) {
    return SMEM_DESC_BASE_SW128 | ((uint64_t)(addr >> 4) & 0x3FFF);
}

// idesc kind::f16, FP16 inputs, f32 accum, M=128 (per MMA stream), N=256
static constexpr uint32_t MMA_IDESC =
    (1u << 4) | (0u << 7) | (0u << 10) | ((BN / 8) << 17) | ((128 / 16) << 24);

__device__ __forceinline__ void mma_f16_ss(uint32_t d, uint64_t ad, uint64_t bd,
                                           uint32_t idesc, uint32_t acc) {
    asm volatile(
        "{\n\t.reg .pred p;\n\t"
        "setp.ne.u32 p, %4, 0;\n\t"
        "tcgen05.mma.cta_group::1.kind::f16 [%0], %1, %2, %3, {%5, %5, %5, %5}, p;\n\t"
        "}"
        :: "r"(d), "l"(ad), "l"(bd), "r"(idesc), "r"(acc), "r"(0u)
        : "memory");
}
#endif // USE_TCGEN05

// ---------------- prep kernel A: concat(x,h) -> fp16 -----------------------
__global__ void prep_a_kernel(const float* __restrict__ x, const float* __restrict__ h) {
    size_t idx8 = ((size_t)blockIdx.x * blockDim.x + threadIdx.x) * 8;
    int m = (int)(idx8 / K_DIM);
    int k = (int)(idx8 % K_DIM);
    const float* src = (k < T_DIM) ? (x + (size_t)m * T_DIM + k)
                                   : (h + (size_t)m * U_DIM + (k - T_DIM));
    float4 v0 = *reinterpret_cast<const float4*>(src);
    float4 v1 = *reinterpret_cast<const float4*>(src + 4);

    union Pack { __half b[8]; uint4 u; } p;
    p.b[0] = __float2half_rn(v0.x); p.b[1] = __float2half_rn(v0.y);
    p.b[2] = __float2half_rn(v0.z); p.b[3] = __float2half_rn(v0.w);
    p.b[4] = __float2half_rn(v1.x); p.b[5] = __float2half_rn(v1.y);
    p.b[6] = __float2half_rn(v1.z); p.b[7] = __float2half_rn(v1.w);
    *reinterpret_cast<uint4*>(g_A_h + idx8) = p.u;
}

// ---------------- prep kernel B: W transpose+convert, gate-interleaved -----
__global__ void prep_w_kernel(const float* __restrict__ Wi, const float* __restrict__ Wf,
                              const float* __restrict__ Wg, const float* __restrict__ Wo) {
    __shared__ float tile[32][33];
    int gate = blockIdx.z;
    const float* W = (gate == 0) ? Wi : (gate == 1) ? Wf : (gate == 2) ? Wg : Wo;
    int k0 = blockIdx.x * 32;
    int u0 = blockIdx.y * 32;
    int tx = threadIdx.x, ty = threadIdx.y;

#pragma unroll
    for (int i = 0; i < 4; i++) {
        int k = k0 + ty + i * 8;
        tile[ty + i * 8][tx] = W[(size_t)k * U_DIM + u0 + tx];  // coalesced over u
    }
    __syncthreads();
#pragma unroll
    for (int i = 0; i < 4; i++) {
        int u = u0 + ty + i * 8;
        float v = tile[tx][ty + i * 8];          // = W[k0+tx, u]
        size_t off = (size_t)(u * 4 + gate) * K_DIM + k0 + tx;  // coalesced over k
        g_W_h[off] = __float2half_rn(v);
    }
}

// ---------------- GEMM + LSTM epilogue -------------------------------------
// SMEM map:
//   [0]      tmem ptr
//   [8]      commit mbar
//   [1024]   stage0: A(32K: 256 rows) B(32K: 256 rows) = 64KB
//   [66560]  stage1: same                              = 64KB
// epilogue reuses the (dead) stage region per 128-row half:
//   h_sm / c_sm / ci_sm, each 128 x 65 fp32
#define SM_TMEM 0
#define SM_MBAR 8
#define SM_STAGE 1024
#define A_TILE_BYTES 32768                  // 256 rows x 128B
#define B_TILE_BYTES 32768                  // 256 rows x 128B
#define STAGE_BYTES (A_TILE_BYTES + B_TILE_BYTES)           // 65536
#define GEMM_SMEM (SM_STAGE + 2 * STAGE_BYTES)              // 132096
#define EP_PAD 65

#if USE_TCGEN05
__device__ __forceinline__ void load_stage(uint32_t sbase, int kt,
                                           int m0, int n0, int tid) {
    int koff = kt * BK;
    // A: 256 rows x 8 chunks of 16B
#pragma unroll
    for (int j = 0; j < 8; j++) {
        int i = tid + j * GEMM_THREADS;       // 0..2047
        int r = i >> 3;
        int c = i & 7;
        uint32_t soff = SWZ128((uint32_t)(r * 128 + c * 16));
        size_t ga = (size_t)(m0 + r) * K_DIM + koff + c * 8;
        cp16(sbase + soff, g_A_h + ga);
    }
    // B: 256 rows x 8 chunks of 16B
    uint32_t bbase = sbase + A_TILE_BYTES;
#pragma unroll
    for (int j = 0; j < 8; j++) {
        int i = tid + j * GEMM_THREADS;       // 0..2047
        int r = i >> 3;
        int c = i & 7;
        uint32_t soff = SWZ128((uint32_t)(r * 128 + c * 16));
        size_t gb = (size_t)(n0 + r) * K_DIM + koff + c * 8;
        cp16(bbase + soff, g_W_h + gb);
    }
}
#endif

__global__ void __launch_bounds__(GEMM_THREADS)
lstm_gemm_kernel(const float* __restrict__ c_in,
                 const float* __restrict__ bi, const float* __restrict__ bf_,
                 const float* __restrict__ bg, const float* __restrict__ bo,
                 float* __restrict__ out) {
    extern __shared__ char smem[];
    int tid = threadIdx.x;
    const size_t c_off = (size_t)B_DIM * U_DIM;

    int n0 = blockIdx.x * BN;          // 16 tiles
    int m0 = blockIdx.y * BM;          // 32 tiles
    int u_base = n0 >> 2;              // 64 u's per tile (4 gates interleaved)

#if USE_TCGEN05
    // ======================= tcgen05 cg1 path ===============================
    uint32_t sb = smem_u32(smem);
    int wid = tid >> 5;
    int lid = tid & 31;

    if (wid == 0) TCGEN05_ALLOC(sb + SM_TMEM, 512);
    if (tid == 0) MBARRIER_INIT(sb + SM_MBAR, 1);
    __syncthreads();
    uint32_t tmem;
    asm volatile("ld.shared.b32 %0, [%1];" : "=r"(tmem) : "r"(sb + SM_TMEM));

    load_stage(sb + SM_STAGE, 0, m0, n0, tid);
    CP_ASYNC_COMMIT();

    int phase = 0;
#pragma unroll 1
    for (int kt = 0; kt < KTILES; kt++) {
        // MMA(kt-1) must finish before load(kt+1) overwrites its stage
        if (kt > 0) { MBARRIER_WAIT_PARITY(sb + SM_MBAR, phase); phase ^= 1; }

        if (kt + 1 < KTILES) {
            load_stage(sb + SM_STAGE + ((kt + 1) & 1) * STAGE_BYTES, kt + 1, m0, n0, tid);
            CP_ASYNC_COMMIT();
            CP_ASYNC_WAIT(1);   // stage kt landed
        } else {
            CP_ASYNC_WAIT(0);
        }
        __syncthreads();

        if (wid == 0) {
            FENCE_PROXY_ASYNC();
            uint32_t st = sb + SM_STAGE + (kt & 1) * STAGE_BYTES;
            uint64_t dA0 = make_desc(st);                    // rows 0..127
            uint64_t dA1 = make_desc(st + 16384);            // rows 128..255
            uint64_t dB  = make_desc(st + A_TILE_BYTES);
            if (elect_one()) {
#pragma unroll
                for (int s = 0; s < 4; s++) {   // 4 x K=16 steps per 64-K tile
                    uint32_t off = s * 2;       // 32B = 2 x 16B units
                    uint32_t acc = (kt | s) != 0;
                    mma_f16_ss(tmem,       dA0 + off, dB + off, MMA_IDESC, acc);
                    mma_f16_ss(tmem + 256, dA1 + off, dB + off, MMA_IDESC, acc);
                }
                TCGEN05_COMMIT(sb + SM_MBAR);
            }
        }
    }

    MBARRIER_WAIT_PARITY(sb + SM_MBAR, phase);
    TCGEN05_FENCE_AFTER();

    // ---------------- epilogue (coalesced, two 128-row passes) -------------
    float* h_sm = reinterpret_cast<float*>(smem + SM_STAGE);
    float* c_sm = h_sm + 128 * EP_PAD;
    float* ci_sm = c_sm + 128 * EP_PAD;

    int sub = wid & 3;
    int half = wid >> 2;
    int row = sub * 32 + lid;

#pragma unroll 1
    for (int mh = 0; mh < 2; mh++) {
        int m0h = m0 + mh * 128;
        uint32_t dtile = tmem + mh * 256;

        // stage c_in: 128 rows x 64 u, coalesced float4
#pragma unroll
        for (int i = tid; i < 128 * 16; i += GEMM_THREADS) {
            int r = i >> 4;
            int q = i & 15;
            float4 v = *reinterpret_cast<const float4*>(
                c_in + (size_t)(m0h + r) * U_DIM + u_base + q * 4);
            int base = r * EP_PAD + q * 4;
            ci_sm[base + 0] = v.x; ci_sm[base + 1] = v.y;
            ci_sm[base + 2] = v.z; ci_sm[base + 3] = v.w;
        }
        __syncthreads();

#pragma unroll
        for (int ch = 0; ch < 4; ch++) {
            uint32_t col = (uint32_t)(half * 128 + ch * 32);
            uint32_t d[32];
            TCGEN05_LD_32X32B_X32(d, dtile + col);
            TCGEN05_WAIT_LD();
#pragma unroll
            for (int j = 0; j < 8; j++) {
                int ul = half * 32 + ch * 8 + j;     // u within the 64-u tile
                int u = u_base + ul;
                float zi = __uint_as_float(d[4 * j + 0]) + bi[u];
                float zf = __uint_as_float(d[4 * j + 1]) + bf_[u];
                float zg = __uint_as_float(d[4 * j + 2]) + bg[u];
                float zo = __uint_as_float(d[4 * j + 3]) + bo[u];
                float ig = fast_sigmoid(zi);
                float fg = fast_sigmoid(zf);
                float gg = tanhf(zg);
                float og = fast_sigmoid(zo);
                float cv = ci_sm[row * EP_PAD + ul];
                float cn = fg * cv + ig * gg;
                float hn = og * tanhf(cn);
                h_sm[row * EP_PAD + ul] = hn;
                c_sm[row * EP_PAD + ul] = cn;
            }
        }
        __syncthreads();

        // coalesced store sweep
#pragma unroll
        for (int i = tid; i < 128 * 64; i += GEMM_THREADS) {
            int r = i >> 6;
            int u = i & 63;
            size_t g = (size_t)(m0h + r) * U_DIM + u_base + u;
            out[g] = h_sm[r * EP_PAD + u];
            out[c_off + g] = c_sm[r * EP_PAD + u];
        }
        __syncthreads();
    }

    TCGEN05_FENCE_BEFORE();
    if (tid == 0) MBARRIER_INVAL(sb + SM_MBAR);
    __syncthreads();
    if (wid == 0) TCGEN05_DEALLOC(tmem, 512);

#else
    // ======================= SIMT fallback (plain sm_103 target) ===========
    const int PAD = 132;
    float* As = reinterpret_cast<float*>(smem);          // [32][PAD]
    float* Bs = As + 32 * PAD;                           // [32][PAD]

    int tx = tid & 15;
    int ty = tid >> 4;

#pragma unroll 1
    for (int mh = 0; mh < 2; mh++) {
        int m0h = m0 + mh * 128;
#pragma unroll 1
        for (int ns = 0; ns < 2; ns++) {                 // two 128-wide n halves
            int n0h = n0 + ns * 128;
            int u0 = n0h >> 2;
            float acc[8][8];
#pragma unroll
            for (int i = 0; i < 8; i++)
#pragma unroll
                for (int j = 0; j < 8; j++) acc[i][j] = 0.0f;

#pragma unroll 1
            for (int kt = 0; kt < K_DIM / 32; kt++) {
                int koff = kt * 32;
#pragma unroll
                for (int i = 0; i < 16; i++) {
                    int idx = tid + i * 256;
                    int kk = idx & 31;
                    int r = idx >> 5;
                    size_t ga = (size_t)(m0h + r) * K_DIM + koff + kk;
                    size_t gb = (size_t)(n0h + r) * K_DIM + koff + kk;
                    As[kk * PAD + r] = __half2float(g_A_h[ga]);
                    Bs[kk * PAD + r] = __half2float(g_W_h[gb]);
                }
                __syncthreads();
#pragma unroll 1
                for (int kk = 0; kk < 32; kk++) {
                    float a[8], b[8];
#pragma unroll
                    for (int i = 0; i < 8; i++) a[i] = As[kk * PAD + ty * 8 + i];
#pragma unroll
                    for (int j = 0; j < 8; j++) b[j] = Bs[kk * PAD + tx * 8 + j];
#pragma unroll
                    for (int i = 0; i < 8; i++)
#pragma unroll
                        for (int j = 0; j < 8; j++) acc[i][j] += a[i] * b[j];
                }
                __syncthreads();
            }

#pragma unroll
            for (int i = 0; i < 8; i++) {
                int m = m0h + ty * 8 + i;
#pragma unroll
                for (int jj = 0; jj < 2; jj++) {
                    int u = u0 + tx * 2 + jj;
                    float zi = acc[i][jj * 4 + 0] + bi[u];
                    float zf = acc[i][jj * 4 + 1] + bf_[u];
                    float zg = acc[i][jj * 4 + 2] + bg[u];
                    float zo = acc[i][jj * 4 + 3] + bo[u];
                    float ig = fast_sigmoid(zi);
                    float fg = fast_sigmoid(zf);
                    float gg = tanhf(zg);
                    float og = fast_sigmoid(zo);
                    float cv = c_in[(size_t)m * U_DIM + u];
                    float cn = fg * cv + ig * gg;
                    float hn = og * tanhf(cn);
                    out[(size_t)m * U_DIM + u] = hn;
                    out[c_off + (size_t)m * U_DIM + u] = cn;
                }
            }
            __syncthreads();
        }
    }
#endif
}

// ---------------- launch ----------------------------------------------------
extern "C" void kernel_launch(void* const* d_in, const int* in_sizes, int n_in,
                              void* d_out, int out_size) {
    const float* x  = (const float*)d_in[0];
    const float* h  = (const float*)d_in[1];
    const float* c  = (const float*)d_in[2];
    const float* Wi = (const float*)d_in[3];
    const float* Wf = (const float*)d_in[4];
    const float* Wg = (const float*)d_in[5];
    const float* Wo = (const float*)d_in[6];
    const float* bi = (const float*)d_in[7];
    const float* bf = (const float*)d_in[8];
    const float* bg = (const float*)d_in[9];
    const float* bo = (const float*)d_in[10];
    float* out = (float*)d_out;

    // 1) concat -> fp16 A
    prep_a_kernel<<<(int)(((size_t)B_DIM * K_DIM / 8) / 256), 256>>>(x, h);
    // 2) transpose -> fp16 W (gate-interleaved columns)
    prep_w_kernel<<<dim3(K_DIM / 32, U_DIM / 32, 4), dim3(32, 8)>>>(Wi, Wf, Wg, Wo);
    // 3) GEMM + LSTM epilogue: cg1, 256x256 tiles (two M=128 MMA streams)
    cudaFuncSetAttribute(lstm_gemm_kernel,
                         cudaFuncAttributeMaxDynamicSharedMemorySize, GEMM_SMEM);
    lstm_gemm_kernel<<<dim3(N_DIM / BN, B_DIM / BM), GEMM_THREADS, GEMM_SMEM>>>(
        c, bi, bf, bg, bo, out);
}

// round 8
// speedup vs baseline: 2.9780x; 1.1478x over previous
#include <cuda_runtime.h>
#include <cuda_fp16.h>
#include <cstdint>

// ============================================================================
// CellLSTM on GB300 (sm_103a)
//   z = [x|h] @ [Wi|Wf|Wg|Wo] + b ; gates; c' = f*c + i*g ; h' = o*tanh(c')
//   R8: fp16 tcgen05, 256x256 tiles (two M=128 MMA streams, shared B tile),
//   3-stage cp.async ring with PER-STAGE mbarriers. R7's single-mbarrier
//   parity wait aliased (commit #kt completing before the wait for #(kt-1)
//   flips parity back -> permanent block). One mbar per stage means a slot
//   is revisited only every 3 iterations -> no aliasing.
// ============================================================================

#if defined(__CUDA_ARCH_FEAT_SM103_ALL) || defined(__CUDA_ARCH_FEAT_SM100_ALL)
#define USE_TCGEN05 1
#else
#define USE_TCGEN05 0
#endif

#define B_DIM 8192
#define T_DIM 1024
#define U_DIM 1024
#define K_DIM 2048
#define N_DIM 4096

#define BM 256              // two M=128 MMA halves
#define BN 256
#define BK 64
#define KTILES (K_DIM / BK)   // 32
#define GEMM_THREADS 256

// ---------------- scratch (device globals: allocation-rule-safe) -----------
__device__ __align__(16) __half g_A_h[(size_t)B_DIM * K_DIM];
// W transposed & gate-interleaved: row n = u*4 + gate, K-major
__device__ __align__(16) __half g_W_h[(size_t)N_DIM * K_DIM];

// ---------------- arch-neutral helpers -------------------------------------
__device__ __forceinline__ uint32_t smem_u32(const void* p) {
    uint32_t a;
    asm("{ .reg .u64 t; cvta.to.shared.u64 t, %1; cvt.u32.u64 %0, t; }"
        : "=r"(a) : "l"(p));
    return a;
}

#define SWZ128(off) ((off) ^ (((off) >> 3) & 0x70))

__device__ __forceinline__ float fast_sigmoid(float z) {
    return 1.0f / (1.0f + __expf(-z));
}

#if USE_TCGEN05
// ---------------- tcgen05 / mbarrier / cp.async helpers --------------------
__device__ __forceinline__ uint32_t elect_one() {
    uint32_t pred;
    asm volatile(
        "{\n\t.reg .pred p;\n\telect.sync _|p, 0xFFFFFFFF;\n\t"
        "selp.b32 %0, 1, 0, p;\n\t}" : "=r"(pred));
    return pred;
}

#define MBARRIER_INIT(addr, cnt) \
    asm volatile("mbarrier.init.shared.b64 [%0], %1;" \
                 :: "r"((uint32_t)(addr)), "r"((uint32_t)(cnt)) : "memory")

#define MBARRIER_INVAL(addr) \
    asm volatile("mbarrier.inval.shared.b64 [%0];" \
                 :: "r"((uint32_t)(addr)) : "memory")

#define MBARRIER_WAIT_PARITY(mbar_smem_addr, phase_parity) do { \
    uint32_t _mbar = (uint32_t)(mbar_smem_addr); \
    uint32_t _parity = (uint32_t)(phase_parity); \
    uint32_t _done; \
    asm volatile( \
        "{\n\t.reg .pred p;\n\t" \
        "mbarrier.try_wait.parity.acquire.cta.shared::cta.b64 p, [%1], %2;\n\t" \
        "selp.b32 %0, 1, 0, p;\n\t}" \
        : "=r"(_done) : "r"(_mbar), "r"(_parity) : "memory"); \
    if (!_done) { \
        asm volatile( \
            "{\n\t.reg .pred P1;\n\t" \
            "WAIT_LOOP_%=:\n\t" \
            "mbarrier.try_wait.parity.acquire.cta.shared::cta.b64 P1, [%0], %1, 0x989680;\n\t" \
            "@P1 bra.uni WAIT_DONE_%=;\n\t" \
            "bra.uni WAIT_LOOP_%=;\n\t" \
            "WAIT_DONE_%=:\n\t}" \
            :: "r"(_mbar), "r"(_parity) : "memory"); \
    } \
} while (0)

#define TCGEN05_ALLOC(smem_result_addr, nCols) \
    asm volatile("tcgen05.alloc.cta_group::1.sync.aligned.shared::cta.b32 [%0], %1;" \
                 :: "r"((uint32_t)(smem_result_addr)), "r"((uint32_t)(nCols)) : "memory")

#define TCGEN05_DEALLOC(tmem_addr, nCols) \
    asm volatile("tcgen05.dealloc.cta_group::1.sync.aligned.b32 %0, %1;" \
                 :: "r"(tmem_addr), "r"((uint32_t)(nCols)))

#define TCGEN05_COMMIT(mbar_smem_addr) \
    asm volatile("tcgen05.commit.cta_group::1.mbarrier::arrive::one.shared::cluster.b64 [%0];" \
                 :: "r"((uint32_t)(mbar_smem_addr)) : "memory")

#define TCGEN05_FENCE_AFTER() \
    asm volatile("tcgen05.fence::after_thread_sync;" ::: "memory")
#define TCGEN05_FENCE_BEFORE() \
    asm volatile("tcgen05.fence::before_thread_sync;" ::: "memory")
#define TCGEN05_WAIT_LD() \
    asm volatile("tcgen05.wait::ld.sync.aligned;" ::: "memory")

#define FENCE_PROXY_ASYNC() \
    asm volatile("fence.proxy.async.shared::cta;" ::: "memory")

#define CP_ASYNC_COMMIT() asm volatile("cp.async.commit_group;" ::: "memory")
#define CP_ASYNC_WAIT(n)  asm volatile("cp.async.wait_group %0;" :: "n"(n) : "memory")

__device__ __forceinline__ void cp16(uint32_t dst, const void* src) {
    asm volatile("cp.async.cg.shared.global [%0], [%1], 16;"
                 :: "r"(dst), "l"(src) : "memory");
}

#define TCGEN05_LD_32X32B_X32(r, tmem_addr) \
    asm volatile( \
        "tcgen05.ld.sync.aligned.32x32b.x32.b32 " \
        "{%0, %1, %2, %3, %4, %5, %6, %7, " \
        " %8, %9, %10, %11, %12, %13, %14, %15, " \
        " %16, %17, %18, %19, %20, %21, %22, %23, " \
        " %24, %25, %26, %27, %28, %29, %30, %31}, [%32];" \
        : "=r"((r)[0]),  "=r"((r)[1]),  "=r"((r)[2]),  "=r"((r)[3]), \
          "=r"((r)[4]),  "=r"((r)[5]),  "=r"((r)[6]),  "=r"((r)[7]), \
          "=r"((r)[8]),  "=r"((r)[9]),  "=r"((r)[10]), "=r"((r)[11]), \
          "=r"((r)[12]), "=r"((r)[13]), "=r"((r)[14]), "=r"((r)[15]), \
          "=r"((r)[16]), "=r"((r)[17]), "=r"((r)[18]), "=r"((r)[19]), \
          "=r"((r)[20]), "=r"((r)[21]), "=r"((r)[22]), "=r"((r)[23]), \
          "=r"((r)[24]), "=r"((r)[25]), "=r"((r)[26]), "=r"((r)[27]), \
          "=r"((r)[28]), "=r"((r)[29]), "=r"((r)[30]), "=r"((r)[31]) \
        : "r"(tmem_addr))

// K-major SW128 smem descriptor (verified: test_mma_iter)
static constexpr uint64_t SMEM_DESC_BASE_SW128 =
    (uint64_t(2)  << 61) | (uint64_t(1) << 46) |
    (uint64_t(64) << 32) | (uint64_t(1) << 16);

__device__ __forceinline__ uint64_t make_desc(uint32_t addr) {
    return SMEM_DESC_BASE_SW128 | ((uint64_t)(addr >> 4) & 0x3FFF);
}

// idesc kind::f16, FP16 inputs, f32 accum, M=128 (per MMA stream), N=256
static constexpr uint32_t MMA_IDESC =
    (1u << 4) | (0u << 7) | (0u << 10) | ((BN / 8) << 17) | ((128 / 16) << 24);

__device__ __forceinline__ void mma_f16_ss(uint32_t d, uint64_t ad, uint64_t bd,
                                           uint32_t idesc, uint32_t acc) {
    asm volatile(
        "{\n\t.reg .pred p;\n\t"
        "setp.ne.u32 p, %4, 0;\n\t"
        "tcgen05.mma.cta_group::1.kind::f16 [%0], %1, %2, %3, {%5, %5, %5, %5}, p;\n\t"
        "}"
        :: "r"(d), "l"(ad), "l"(bd), "r"(idesc), "r"(acc), "r"(0u)
        : "memory");
}
#endif // USE_TCGEN05

// ---------------- prep kernel A: concat(x,h) -> fp16 -----------------------
__global__ void prep_a_kernel(const float* __restrict__ x, const float* __restrict__ h) {
    size_t idx8 = ((size_t)blockIdx.x * blockDim.x + threadIdx.x) * 8;
    int m = (int)(idx8 / K_DIM);
    int k = (int)(idx8 % K_DIM);
    const float* src = (k < T_DIM) ? (x + (size_t)m * T_DIM + k)
                                   : (h + (size_t)m * U_DIM + (k - T_DIM));
    float4 v0 = *reinterpret_cast<const float4*>(src);
    float4 v1 = *reinterpret_cast<const float4*>(src + 4);

    union Pack { __half b[8]; uint4 u; } p;
    p.b[0] = __float2half_rn(v0.x); p.b[1] = __float2half_rn(v0.y);
    p.b[2] = __float2half_rn(v0.z); p.b[3] = __float2half_rn(v0.w);
    p.b[4] = __float2half_rn(v1.x); p.b[5] = __float2half_rn(v1.y);
    p.b[6] = __float2half_rn(v1.z); p.b[7] = __float2half_rn(v1.w);
    *reinterpret_cast<uint4*>(g_A_h + idx8) = p.u;
}

// ---------------- prep kernel B: W transpose+convert, gate-interleaved -----
__global__ void prep_w_kernel(const float* __restrict__ Wi, const float* __restrict__ Wf,
                              const float* __restrict__ Wg, const float* __restrict__ Wo) {
    __shared__ float tile[32][33];
    int gate = blockIdx.z;
    const float* W = (gate == 0) ? Wi : (gate == 1) ? Wf : (gate == 2) ? Wg : Wo;
    int k0 = blockIdx.x * 32;
    int u0 = blockIdx.y * 32;
    int tx = threadIdx.x, ty = threadIdx.y;

#pragma unroll
    for (int i = 0; i < 4; i++) {
        int k = k0 + ty + i * 8;
        tile[ty + i * 8][tx] = W[(size_t)k * U_DIM + u0 + tx];  // coalesced over u
    }
    __syncthreads();
#pragma unroll
    for (int i = 0; i < 4; i++) {
        int u = u0 + ty + i * 8;
        float v = tile[tx][ty + i * 8];          // = W[k0+tx, u]
        size_t off = (size_t)(u * 4 + gate) * K_DIM + k0 + tx;  // coalesced over k
        g_W_h[off] = __float2half_rn(v);
    }
}

// ---------------- GEMM + LSTM epilogue -------------------------------------
// SMEM map:
//   [0]      tmem ptr
//   [8]      mbar[3] (one per stage, 8B each)
//   [1024]   3 stages x (A 32K + B 32K) = 192KB ring
// epilogue reuses the (dead) stage region per 128-row half:
//   h_sm / c_sm / ci_sm, each 128 x 65 fp32
#define SM_TMEM 0
#define SM_MBAR 8
#define SM_STAGE 1024
#define A_TILE_BYTES 32768                  // 256 rows x 128B
#define B_TILE_BYTES 32768                  // 256 rows x 128B
#define STAGE_BYTES (A_TILE_BYTES + B_TILE_BYTES)           // 65536
#define NSTAGES 3
#define GEMM_SMEM (SM_STAGE + NSTAGES * STAGE_BYTES)        // 197632
#define EP_PAD 65

#if USE_TCGEN05
__device__ __forceinline__ void load_stage(uint32_t sbase, int kt,
                                           int m0, int n0, int tid) {
    int koff = kt * BK;
    // A: 256 rows x 8 chunks of 16B
#pragma unroll
    for (int j = 0; j < 8; j++) {
        int i = tid + j * GEMM_THREADS;       // 0..2047
        int r = i >> 3;
        int c = i & 7;
        uint32_t soff = SWZ128((uint32_t)(r * 128 + c * 16));
        size_t ga = (size_t)(m0 + r) * K_DIM + koff + c * 8;
        cp16(sbase + soff, g_A_h + ga);
    }
    // B: 256 rows x 8 chunks of 16B
    uint32_t bbase = sbase + A_TILE_BYTES;
#pragma unroll
    for (int j = 0; j < 8; j++) {
        int i = tid + j * GEMM_THREADS;       // 0..2047
        int r = i >> 3;
        int c = i & 7;
        uint32_t soff = SWZ128((uint32_t)(r * 128 + c * 16));
        size_t gb = (size_t)(n0 + r) * K_DIM + koff + c * 8;
        cp16(bbase + soff, g_W_h + gb);
    }
}
#endif

__global__ void __launch_bounds__(GEMM_THREADS)
lstm_gemm_kernel(const float* __restrict__ c_in,
                 const float* __restrict__ bi, const float* __restrict__ bf_,
                 const float* __restrict__ bg, const float* __restrict__ bo,
                 float* __restrict__ out) {
    extern __shared__ char smem[];
    int tid = threadIdx.x;
    const size_t c_off = (size_t)B_DIM * U_DIM;

    int n0 = blockIdx.x * BN;          // 16 tiles
    int m0 = blockIdx.y * BM;          // 32 tiles
    int u_base = n0 >> 2;              // 64 u's per tile (4 gates interleaved)

#if USE_TCGEN05
    // ======================= tcgen05 cg1 path ===============================
    uint32_t sb = smem_u32(smem);
    int wid = tid >> 5;
    int lid = tid & 31;

    if (wid == 0) TCGEN05_ALLOC(sb + SM_TMEM, 512);
    if (tid == 0) {
#pragma unroll
        for (int s = 0; s < NSTAGES; s++) MBARRIER_INIT(sb + SM_MBAR + 8 * s, 1);
    }
    __syncthreads();
    uint32_t tmem;
    asm volatile("ld.shared.b32 %0, [%1];" : "=r"(tmem) : "r"(sb + SM_TMEM));

    // prologue: fill 2 of 3 stages
    load_stage(sb + SM_STAGE + 0 * STAGE_BYTES, 0, m0, n0, tid);
    CP_ASYNC_COMMIT();
    load_stage(sb + SM_STAGE + 1 * STAGE_BYTES, 1, m0, n0, tid);
    CP_ASYNC_COMMIT();

#pragma unroll 1
    for (int kt = 0; kt < KTILES; kt++) {
        // stage kt landed (keep the most recent load group in flight)
        if (kt < KTILES - 1) { CP_ASYNC_WAIT(1); } else { CP_ASYNC_WAIT(0); }
        __syncthreads();

        // issue MMA(kt) on stage kt%3; commit to that stage's mbar
        if (wid == 0) {
            FENCE_PROXY_ASYNC();
            uint32_t st = sb + SM_STAGE + (kt % NSTAGES) * STAGE_BYTES;
            uint64_t dA0 = make_desc(st);                    // rows 0..127
            uint64_t dA1 = make_desc(st + 16384);            // rows 128..255
            uint64_t dB  = make_desc(st + A_TILE_BYTES);
            if (elect_one()) {
#pragma unroll
                for (int s = 0; s < 4; s++) {   // 4 x K=16 steps per 64-K tile
                    uint32_t off = s * 2;       // 32B = 2 x 16B units
                    uint32_t acc = (kt | s) != 0;
                    mma_f16_ss(tmem,       dA0 + off, dB + off, MMA_IDESC, acc);
                    mma_f16_ss(tmem + 256, dA1 + off, dB + off, MMA_IDESC, acc);
                }
                TCGEN05_COMMIT(sb + SM_MBAR + 8 * (kt % NSTAGES));
            }
        }

        // refill stage (kt+2)%3 == (kt-1)%3: wait commit #(kt-1) on ITS mbar.
        // Per-stage mbar: slot revisited every 3 iters -> parity (j/3)&1,
        // aliasing impossible at <6 iterations of skew.
        if (kt + 2 < KTILES) {
            if (kt > 0) {
                int j = kt - 1;
                MBARRIER_WAIT_PARITY(sb + SM_MBAR + 8 * (j % NSTAGES), (j / NSTAGES) & 1);
            }
            load_stage(sb + SM_STAGE + ((kt + 2) % NSTAGES) * STAGE_BYTES,
                       kt + 2, m0, n0, tid);
            CP_ASYNC_COMMIT();
        }
    }

    // tail: commits complete in issue order, so waiting the LAST commit
    // (#KTILES-1) on its own mbar covers all prior MMAs.
    {
        int j = KTILES - 1;
        MBARRIER_WAIT_PARITY(sb + SM_MBAR + 8 * (j % NSTAGES), (j / NSTAGES) & 1);
    }
    TCGEN05_FENCE_AFTER();

    // ---------------- epilogue (coalesced, two 128-row passes) -------------
    float* h_sm = reinterpret_cast<float*>(smem + SM_STAGE);
    float* c_sm = h_sm + 128 * EP_PAD;
    float* ci_sm = c_sm + 128 * EP_PAD;

    int sub = wid & 3;
    int half = wid >> 2;
    int row = sub * 32 + lid;

#pragma unroll 1
    for (int mh = 0; mh < 2; mh++) {
        int m0h = m0 + mh * 128;
        uint32_t dtile = tmem + mh * 256;

        // stage c_in: 128 rows x 64 u, coalesced float4
#pragma unroll
        for (int i = tid; i < 128 * 16; i += GEMM_THREADS) {
            int r = i >> 4;
            int q = i & 15;
            float4 v = *reinterpret_cast<const float4*>(
                c_in + (size_t)(m0h + r) * U_DIM + u_base + q * 4);
            int base = r * EP_PAD + q * 4;
            ci_sm[base + 0] = v.x; ci_sm[base + 1] = v.y;
            ci_sm[base + 2] = v.z; ci_sm[base + 3] = v.w;
        }
        __syncthreads();

#pragma unroll
        for (int ch = 0; ch < 4; ch++) {
            uint32_t col = (uint32_t)(half * 128 + ch * 32);
            uint32_t d[32];
            TCGEN05_LD_32X32B_X32(d, dtile + col);
            TCGEN05_WAIT_LD();
#pragma unroll
            for (int j = 0; j < 8; j++) {
                int ul = half * 32 + ch * 8 + j;     // u within the 64-u tile
                int u = u_base + ul;
                float zi = __uint_as_float(d[4 * j + 0]) + bi[u];
                float zf = __uint_as_float(d[4 * j + 1]) + bf_[u];
                float zg = __uint_as_float(d[4 * j + 2]) + bg[u];
                float zo = __uint_as_float(d[4 * j + 3]) + bo[u];
                float ig = fast_sigmoid(zi);
                float fg = fast_sigmoid(zf);
                float gg = tanhf(zg);
                float og = fast_sigmoid(zo);
                float cv = ci_sm[row * EP_PAD + ul];
                float cn = fg * cv + ig * gg;
                float hn = og * tanhf(cn);
                h_sm[row * EP_PAD + ul] = hn;
                c_sm[row * EP_PAD + ul] = cn;
            }
        }
        __syncthreads();

        // coalesced store sweep
#pragma unroll
        for (int i = tid; i < 128 * 64; i += GEMM_THREADS) {
            int r = i >> 6;
            int u = i & 63;
            size_t g = (size_t)(m0h + r) * U_DIM + u_base + u;
            out[g] = h_sm[r * EP_PAD + u];
            out[c_off + g] = c_sm[r * EP_PAD + u];
        }
        __syncthreads();
    }

    TCGEN05_FENCE_BEFORE();
    if (tid == 0) {
#pragma unroll
        for (int s = 0; s < NSTAGES; s++) MBARRIER_INVAL(sb + SM_MBAR + 8 * s);
    }
    __syncthreads();
    if (wid == 0) TCGEN05_DEALLOC(tmem, 512);

#else
    // ======================= SIMT fallback (plain sm_103 target) ===========
    const int PAD = 132;
    float* As = reinterpret_cast<float*>(smem);          // [32][PAD]
    float* Bs = As + 32 * PAD;                           // [32][PAD]

    int tx = tid & 15;
    int ty = tid >> 4;

#pragma unroll 1
    for (int mh = 0; mh < 2; mh++) {
        int m0h = m0 + mh * 128;
#pragma unroll 1
        for (int ns = 0; ns < 2; ns++) {                 // two 128-wide n halves
            int n0h = n0 + ns * 128;
            int u0 = n0h >> 2;
            float acc[8][8];
#pragma unroll
            for (int i = 0; i < 8; i++)
#pragma unroll
                for (int j = 0; j < 8; j++) acc[i][j] = 0.0f;

#pragma unroll 1
            for (int kt = 0; kt < K_DIM / 32; kt++) {
                int koff = kt * 32;
#pragma unroll
                for (int i = 0; i < 16; i++) {
                    int idx = tid + i * 256;
                    int kk = idx & 31;
                    int r = idx >> 5;
                    size_t ga = (size_t)(m0h + r) * K_DIM + koff + kk;
                    size_t gb = (size_t)(n0h + r) * K_DIM + koff + kk;
                    As[kk * PAD + r] = __half2float(g_A_h[ga]);
                    Bs[kk * PAD + r] = __half2float(g_W_h[gb]);
                }
                __syncthreads();
#pragma unroll 1
                for (int kk = 0; kk < 32; kk++) {
                    float a[8], b[8];
#pragma unroll
                    for (int i = 0; i < 8; i++) a[i] = As[kk * PAD + ty * 8 + i];
#pragma unroll
                    for (int j = 0; j < 8; j++) b[j] = Bs[kk * PAD + tx * 8 + j];
#pragma unroll
                    for (int i = 0; i < 8; i++)
#pragma unroll
                        for (int j = 0; j < 8; j++) acc[i][j] += a[i] * b[j];
                }
                __syncthreads();
            }

#pragma unroll
            for (int i = 0; i < 8; i++) {
                int m = m0h + ty * 8 + i;
#pragma unroll
                for (int jj = 0; jj < 2; jj++) {
                    int u = u0 + tx * 2 + jj;
                    float zi = acc[i][jj * 4 + 0] + bi[u];
                    float zf = acc[i][jj * 4 + 1] + bf_[u];
                    float zg = acc[i][jj * 4 + 2] + bg[u];
                    float zo = acc[i][jj * 4 + 3] + bo[u];
                    float ig = fast_sigmoid(zi);
                    float fg = fast_sigmoid(zf);
                    float gg = tanhf(zg);
                    float og = fast_sigmoid(zo);
                    float cv = c_in[(size_t)m * U_DIM + u];
                    float cn = fg * cv + ig * gg;
                    float hn = og * tanhf(cn);
                    out[(size_t)m * U_DIM + u] = hn;
                    out[c_off + (size_t)m * U_DIM + u] = cn;
                }
            }
            __syncthreads();
        }
    }
#endif
}

// ---------------- launch ----------------------------------------------------
extern "C" void kernel_launch(void* const* d_in, const int* in_sizes, int n_in,
                              void* d_out, int out_size) {
    const float* x  = (const float*)d_in[0];
    const float* h  = (const float*)d_in[1];
    const float* c  = (const float*)d_in[2];
    const float* Wi = (const float*)d_in[3];
    const float* Wf = (const float*)d_in[4];
    const float* Wg = (const float*)d_in[5];
    const float* Wo = (const float*)d_in[6];
    const float* bi = (const float*)d_in[7];
    const float* bf = (const float*)d_in[8];
    const float* bg = (const float*)d_in[9];
    const float* bo = (const float*)d_in[10];
    float* out = (float*)d_out;

    // 1) concat -> fp16 A
    prep_a_kernel<<<(int)(((size_t)B_DIM * K_DIM / 8) / 256), 256>>>(x, h);
    // 2) transpose -> fp16 W (gate-interleaved columns)
    prep_w_kernel<<<dim3(K_DIM / 32, U_DIM / 32, 4), dim3(32, 8)>>>(Wi, Wf, Wg, Wo);
    // 3) GEMM + LSTM epilogue: cg1, 256x256 tiles, 3-stage ring, per-stage mbar
    cudaFuncSetAttribute(lstm_gemm_kernel,
                         cudaFuncAttributeMaxDynamicSharedMemorySize, GEMM_SMEM);
    lstm_gemm_kernel<<<dim3(N_DIM / BN, B_DIM / BM), GEMM_THREADS, GEMM_SMEM>>>(
        c, bi, bf, bg, bo, out);
}

// round 9
// speedup vs baseline: 3.1257x; 1.0496x over previous
#include <cuda_runtime.h>
#include <cuda_fp16.h>
#include <cstdint>

// ============================================================================
// CellLSTM on GB300 (sm_103a)
//   z = [x|h] @ [Wi|Wf|Wg|Wo] + b ; gates; c' = f*c + i*g ; h' = o*tanh(c')
//   R9: persistent CTAs (grid=152), fused ring across tiles so each tile's
//   epilogue overlaps the NEXT tile's cp.async loads; SMEM-free epilogue
//   (32B/lane contiguous stores = full sectors); tanh.approx for the tanhs.
// ============================================================================

#if defined(__CUDA_ARCH_FEAT_SM103_ALL) || defined(__CUDA_ARCH_FEAT_SM100_ALL)
#define USE_TCGEN05 1
#else
#define USE_TCGEN05 0
#endif

#define B_DIM 8192
#define T_DIM 1024
#define U_DIM 1024
#define K_DIM 2048
#define N_DIM 4096

#define BM 256              // two M=128 MMA halves
#define BN 256
#define BK 64
#define KTILES (K_DIM / BK)         // 32 k-iterations per tile
#define NTILES_TOTAL ((B_DIM / BM) * (N_DIM / BN))   // 32*16 = 512
#define NTILES_N (N_DIM / BN)       // 16
#define GRID_X 152                  // GB300 SM count
#define MAX_TILES_PER_CTA 4
#define GEMM_THREADS 256

// ---------------- scratch (device globals: allocation-rule-safe) -----------
__device__ __align__(16) __half g_A_h[(size_t)B_DIM * K_DIM];
// W transposed & gate-interleaved: row n = u*4 + gate, K-major
__device__ __align__(16) __half g_W_h[(size_t)N_DIM * K_DIM];

// ---------------- arch-neutral helpers -------------------------------------
__device__ __forceinline__ uint32_t smem_u32(const void* p) {
    uint32_t a;
    asm("{ .reg .u64 t; cvta.to.shared.u64 t, %1; cvt.u32.u64 %0, t; }"
        : "=r"(a) : "l"(p));
    return a;
}

#define SWZ128(off) ((off) ^ (((off) >> 3) & 0x70))

__device__ __forceinline__ float tanh_fast(float x) {
    float y;
    asm("tanh.approx.f32 %0, %1;" : "=f"(y) : "f"(x));
    return y;
}

__device__ __forceinline__ float fast_sigmoid(float z) {
    return 1.0f / (1.0f + __expf(-z));
}

#if USE_TCGEN05
// ---------------- tcgen05 / mbarrier / cp.async helpers --------------------
__device__ __forceinline__ uint32_t elect_one() {
    uint32_t pred;
    asm volatile(
        "{\n\t.reg .pred p;\n\telect.sync _|p, 0xFFFFFFFF;\n\t"
        "selp.b32 %0, 1, 0, p;\n\t}" : "=r"(pred));
    return pred;
}

#define MBARRIER_INIT(addr, cnt) \
    asm volatile("mbarrier.init.shared.b64 [%0], %1;" \
                 :: "r"((uint32_t)(addr)), "r"((uint32_t)(cnt)) : "memory")

#define MBARRIER_INVAL(addr) \
    asm volatile("mbarrier.inval.shared.b64 [%0];" \
                 :: "r"((uint32_t)(addr)) : "memory")

#define MBARRIER_WAIT_PARITY(mbar_smem_addr, phase_parity) do { \
    uint32_t _mbar = (uint32_t)(mbar_smem_addr); \
    uint32_t _parity = (uint32_t)(phase_parity); \
    uint32_t _done; \
    asm volatile( \
        "{\n\t.reg .pred p;\n\t" \
        "mbarrier.try_wait.parity.acquire.cta.shared::cta.b64 p, [%1], %2;\n\t" \
        "selp.b32 %0, 1, 0, p;\n\t}" \
        : "=r"(_done) : "r"(_mbar), "r"(_parity) : "memory"); \
    if (!_done) { \
        asm volatile( \
            "{\n\t.reg .pred P1;\n\t" \
            "WAIT_LOOP_%=:\n\t" \
            "mbarrier.try_wait.parity.acquire.cta.shared::cta.b64 P1, [%0], %1, 0x989680;\n\t" \
            "@P1 bra.uni WAIT_DONE_%=;\n\t" \
            "bra.uni WAIT_LOOP_%=;\n\t" \
            "WAIT_DONE_%=:\n\t}" \
            :: "r"(_mbar), "r"(_parity) : "memory"); \
    } \
} while (0)

#define TCGEN05_ALLOC(smem_result_addr, nCols) \
    asm volatile("tcgen05.alloc.cta_group::1.sync.aligned.shared::cta.b32 [%0], %1;" \
                 :: "r"((uint32_t)(smem_result_addr)), "r"((uint32_t)(nCols)) : "memory")

#define TCGEN05_DEALLOC(tmem_addr, nCols) \
    asm volatile("tcgen05.dealloc.cta_group::1.sync.aligned.b32 %0, %1;" \
                 :: "r"(tmem_addr), "r"((uint32_t)(nCols)))

#define TCGEN05_COMMIT(mbar_smem_addr) \
    asm volatile("tcgen05.commit.cta_group::1.mbarrier::arrive::one.shared::cluster.b64 [%0];" \
                 :: "r"((uint32_t)(mbar_smem_addr)) : "memory")

#define TCGEN05_FENCE_AFTER() \
    asm volatile("tcgen05.fence::after_thread_sync;" ::: "memory")
#define TCGEN05_FENCE_BEFORE() \
    asm volatile("tcgen05.fence::before_thread_sync;" ::: "memory")
#define TCGEN05_WAIT_LD() \
    asm volatile("tcgen05.wait::ld.sync.aligned;" ::: "memory")

#define FENCE_PROXY_ASYNC() \
    asm volatile("fence.proxy.async.shared::cta;" ::: "memory")

#define CP_ASYNC_COMMIT() asm volatile("cp.async.commit_group;" ::: "memory")
#define CP_ASYNC_WAIT(n)  asm volatile("cp.async.wait_group %0;" :: "n"(n) : "memory")

__device__ __forceinline__ void cp16(uint32_t dst, const void* src) {
    asm volatile("cp.async.cg.shared.global [%0], [%1], 16;"
                 :: "r"(dst), "l"(src) : "memory");
}

#define TCGEN05_LD_32X32B_X32(r, tmem_addr) \
    asm volatile( \
        "tcgen05.ld.sync.aligned.32x32b.x32.b32 " \
        "{%0, %1, %2, %3, %4, %5, %6, %7, " \
        " %8, %9, %10, %11, %12, %13, %14, %15, " \
        " %16, %17, %18, %19, %20, %21, %22, %23, " \
        " %24, %25, %26, %27, %28, %29, %30, %31}, [%32];" \
        : "=r"((r)[0]),  "=r"((r)[1]),  "=r"((r)[2]),  "=r"((r)[3]), \
          "=r"((r)[4]),  "=r"((r)[5]),  "=r"((r)[6]),  "=r"((r)[7]), \
          "=r"((r)[8]),  "=r"((r)[9]),  "=r"((r)[10]), "=r"((r)[11]), \
          "=r"((r)[12]), "=r"((r)[13]), "=r"((r)[14]), "=r"((r)[15]), \
          "=r"((r)[16]), "=r"((r)[17]), "=r"((r)[18]), "=r"((r)[19]), \
          "=r"((r)[20]), "=r"((r)[21]), "=r"((r)[22]), "=r"((r)[23]), \
          "=r"((r)[24]), "=r"((r)[25]), "=r"((r)[26]), "=r"((r)[27]), \
          "=r"((r)[28]), "=r"((r)[29]), "=r"((r)[30]), "=r"((r)[31]) \
        : "r"(tmem_addr))

// K-major SW128 smem descriptor (verified: test_mma_iter)
static constexpr uint64_t SMEM_DESC_BASE_SW128 =
    (uint64_t(2)  << 61) | (uint64_t(1) << 46) |
    (uint64_t(64) << 32) | (uint64_t(1) << 16);

__device__ __forceinline__ uint64_t make_desc(uint32_t addr) {
    return SMEM_DESC_BASE_SW128 | ((uint64_t)(addr >> 4) & 0x3FFF);
}

// idesc kind::f16, FP16 inputs, f32 accum, M=128 (per MMA stream), N=256
static constexpr uint32_t MMA_IDESC =
    (1u << 4) | (0u << 7) | (0u << 10) | ((BN / 8) << 17) | ((128 / 16) << 24);

__device__ __forceinline__ void mma_f16_ss(uint32_t d, uint64_t ad, uint64_t bd,
                                           uint32_t idesc, uint32_t acc) {
    asm volatile(
        "{\n\t.reg .pred p;\n\t"
        "setp.ne.u32 p, %4, 0;\n\t"
        "tcgen05.mma.cta_group::1.kind::f16 [%0], %1, %2, %3, {%5, %5, %5, %5}, p;\n\t"
        "}"
        :: "r"(d), "l"(ad), "l"(bd), "r"(idesc), "r"(acc), "r"(0u)
        : "memory");
}
#endif // USE_TCGEN05

// ---------------- prep kernel A: concat(x,h) -> fp16 -----------------------
__global__ void prep_a_kernel(const float* __restrict__ x, const float* __restrict__ h) {
    size_t idx8 = ((size_t)blockIdx.x * blockDim.x + threadIdx.x) * 8;
    int m = (int)(idx8 / K_DIM);
    int k = (int)(idx8 % K_DIM);
    const float* src = (k < T_DIM) ? (x + (size_t)m * T_DIM + k)
                                   : (h + (size_t)m * U_DIM + (k - T_DIM));
    float4 v0 = *reinterpret_cast<const float4*>(src);
    float4 v1 = *reinterpret_cast<const float4*>(src + 4);

    union Pack { __half b[8]; uint4 u; } p;
    p.b[0] = __float2half_rn(v0.x); p.b[1] = __float2half_rn(v0.y);
    p.b[2] = __float2half_rn(v0.z); p.b[3] = __float2half_rn(v0.w);
    p.b[4] = __float2half_rn(v1.x); p.b[5] = __float2half_rn(v1.y);
    p.b[6] = __float2half_rn(v1.z); p.b[7] = __float2half_rn(v1.w);
    *reinterpret_cast<uint4*>(g_A_h + idx8) = p.u;
}

// ---------------- prep kernel B: W transpose+convert, gate-interleaved -----
__global__ void prep_w_kernel(const float* __restrict__ Wi, const float* __restrict__ Wf,
                              const float* __restrict__ Wg, const float* __restrict__ Wo) {
    __shared__ float tile[32][33];
    int gate = blockIdx.z;
    const float* W = (gate == 0) ? Wi : (gate == 1) ? Wf : (gate == 2) ? Wg : Wo;
    int k0 = blockIdx.x * 32;
    int u0 = blockIdx.y * 32;
    int tx = threadIdx.x, ty = threadIdx.y;

#pragma unroll
    for (int i = 0; i < 4; i++) {
        int k = k0 + ty + i * 8;
        tile[ty + i * 8][tx] = W[(size_t)k * U_DIM + u0 + tx];  // coalesced over u
    }
    __syncthreads();
#pragma unroll
    for (int i = 0; i < 4; i++) {
        int u = u0 + ty + i * 8;
        float v = tile[tx][ty + i * 8];          // = W[k0+tx, u]
        size_t off = (size_t)(u * 4 + gate) * K_DIM + k0 + tx;  // coalesced over k
        g_W_h[off] = __float2half_rn(v);
    }
}

// ---------------- GEMM + LSTM epilogue -------------------------------------
// SMEM map:
//   [0]      tmem ptr
//   [8]      mbar[3] (one per ring stage)
//   [1024]   3 stages x (A 32K + B 32K) = 192KB ring
// epilogue uses NO smem (32B/lane contiguous LDG/STG = full sectors).
#define SM_TMEM 0
#define SM_MBAR 8
#define SM_STAGE 1024
#define A_TILE_BYTES 32768                  // 256 rows x 128B
#define B_TILE_BYTES 32768                  // 256 rows x 128B
#define STAGE_BYTES (A_TILE_BYTES + B_TILE_BYTES)           // 65536
#define NSTAGES 3
#define GEMM_SMEM (SM_STAGE + NSTAGES * STAGE_BYTES)        // 197632

#if USE_TCGEN05
__device__ __forceinline__ void load_stage(uint32_t sbase, int kt,
                                           int m0, int n0, int tid) {
    int koff = kt * BK;
    // A: 256 rows x 8 chunks of 16B
#pragma unroll
    for (int j = 0; j < 8; j++) {
        int i = tid + j * GEMM_THREADS;       // 0..2047
        int r = i >> 3;
        int c = i & 7;
        uint32_t soff = SWZ128((uint32_t)(r * 128 + c * 16));
        size_t ga = (size_t)(m0 + r) * K_DIM + koff + c * 8;
        cp16(sbase + soff, g_A_h + ga);
    }
    // B: 256 rows x 8 chunks of 16B
    uint32_t bbase = sbase + A_TILE_BYTES;
#pragma unroll
    for (int j = 0; j < 8; j++) {
        int i = tid + j * GEMM_THREADS;       // 0..2047
        int r = i >> 3;
        int c = i & 7;
        uint32_t soff = SWZ128((uint32_t)(r * 128 + c * 16));
        size_t gb = (size_t)(n0 + r) * K_DIM + koff + c * 8;
        cp16(bbase + soff, g_W_h + gb);
    }
}
#endif

__global__ void __launch_bounds__(GEMM_THREADS)
lstm_gemm_kernel(const float* __restrict__ c_in,
                 const float* __restrict__ bi, const float* __restrict__ bf_,
                 const float* __restrict__ bg, const float* __restrict__ bo,
                 float* __restrict__ out) {
    extern __shared__ char smem[];
    int tid = threadIdx.x;
    const size_t c_off = (size_t)B_DIM * U_DIM;

    // tiles owned by this CTA (persistent)
    int tiles[MAX_TILES_PER_CTA];
    int ntiles = 0;
    for (int t = blockIdx.x; t < NTILES_TOTAL && ntiles < MAX_TILES_PER_CTA;
         t += GRID_X)
        tiles[ntiles++] = t;
    if (ntiles == 0) return;

#if USE_TCGEN05
    // ======================= tcgen05 persistent path ========================
    uint32_t sb = smem_u32(smem);
    int wid = tid >> 5;
    int lid = tid & 31;

    if (wid == 0) TCGEN05_ALLOC(sb + SM_TMEM, 512);
    if (tid == 0) {
#pragma unroll
        for (int s = 0; s < NSTAGES; s++) MBARRIER_INIT(sb + SM_MBAR + 8 * s, 1);
    }
    __syncthreads();
    uint32_t tmem;
    asm volatile("ld.shared.b32 %0, [%1];" : "=r"(tmem) : "r"(sb + SM_TMEM));

    const int G = ntiles * KTILES;

    // prologue: stages for g=0,1 (tile 0, kt 0/1)
    {
        int m00 = (tiles[0] >> 4) * BM;
        int n00 = (tiles[0] & (NTILES_N - 1)) * BN;
        load_stage(sb + SM_STAGE + 0 * STAGE_BYTES, 0, m00, n00, tid);
        CP_ASYNC_COMMIT();
        load_stage(sb + SM_STAGE + 1 * STAGE_BYTES, 1, m00, n00, tid);
        CP_ASYNC_COMMIT();
    }

    int g = 0;
#pragma unroll 1
    for (int j = 0; j < ntiles; j++) {
        int t = tiles[j];
        int m0 = (t >> 4) * BM;
        int n0 = (t & (NTILES_N - 1)) * BN;
        int u_base = n0 >> 2;

#pragma unroll 1
        for (int kt = 0; kt < KTILES; kt++, g++) {
            // group for g complete (groups committed strictly in order;
            // exactly one group per iteration incl. empty tail groups)
            CP_ASYNC_WAIT(1);
            __syncthreads();

            // issue MMA(g) on ring slot g%3
            if (wid == 0) {
                FENCE_PROXY_ASYNC();
                uint32_t st = sb + SM_STAGE + (g % NSTAGES) * STAGE_BYTES;
                uint64_t dA0 = make_desc(st);                 // rows 0..127
                uint64_t dA1 = make_desc(st + 16384);         // rows 128..255
                uint64_t dB  = make_desc(st + A_TILE_BYTES);
                if (elect_one()) {
#pragma unroll
                    for (int s = 0; s < 4; s++) {  // 4 x K=16 steps
                        uint32_t off = s * 2;      // 32B = 2 x 16B units
                        uint32_t acc = (kt | s) != 0;
                        mma_f16_ss(tmem,       dA0 + off, dB + off, MMA_IDESC, acc);
                        mma_f16_ss(tmem + 256, dA1 + off, dB + off, MMA_IDESC, acc);
                    }
                    TCGEN05_COMMIT(sb + SM_MBAR + 8 * (g % NSTAGES));
                }
            }

            // refill slot (g+2)%3 (may belong to the NEXT tile)
            int g2 = g + 2;
            if (g2 < G) {
                if (g > 0) {
                    int w = g - 1;   // MMA that consumed slot (g+2)%3==(g-1)%3
                    MBARRIER_WAIT_PARITY(sb + SM_MBAR + 8 * (w % NSTAGES),
                                         (w / NSTAGES) & 1);
                }
                int j2 = g2 >> 5;             // KTILES == 32
                int kt2 = g2 & 31;
                int t2 = tiles[j2];
                int m02 = (t2 >> 4) * BM;
                int n02 = (t2 & (NTILES_N - 1)) * BN;
                load_stage(sb + SM_STAGE + (g2 % NSTAGES) * STAGE_BYTES,
                           kt2, m02, n02, tid);
            }
            CP_ASYNC_COMMIT();   // one group per iteration (may be empty)
        }

        // ---- tile epilogue (overlaps next tile's in-flight loads) ----
        {
            int gl = g - 1;      // last MMA of this tile
            MBARRIER_WAIT_PARITY(sb + SM_MBAR + 8 * (gl % NSTAGES),
                                 (gl / NSTAGES) & 1);
        }
        TCGEN05_FENCE_AFTER();

        int sub = wid & 3;
        int half = wid >> 2;
#pragma unroll
        for (int mh = 0; mh < 2; mh++) {
            int m = m0 + mh * 128 + sub * 32 + lid;
            const float* crow = c_in + (size_t)m * U_DIM;
            float* hrow = out + (size_t)m * U_DIM;
            float* corow = out + c_off + (size_t)m * U_DIM;
#pragma unroll
            for (int cg = 0; cg < 4; cg++) {
                uint32_t col = (uint32_t)(mh * 256 + cg * 64 + half * 32);
                uint32_t d[32];
                TCGEN05_LD_32X32B_X32(d, tmem + col);
                int u0c = u_base + cg * 16 + half * 8;
                float4 cv0 = *reinterpret_cast<const float4*>(crow + u0c);
                float4 cv1 = *reinterpret_cast<const float4*>(crow + u0c + 4);
                float cvs[8] = {cv0.x, cv0.y, cv0.z, cv0.w,
                                cv1.x, cv1.y, cv1.z, cv1.w};
                TCGEN05_WAIT_LD();
                float hv[8], cnv[8];
#pragma unroll
                for (int q = 0; q < 8; q++) {
                    int u = u0c + q;
                    float zi = __uint_as_float(d[4 * q + 0]) + bi[u];
                    float zf = __uint_as_float(d[4 * q + 1]) + bf_[u];
                    float zg = __uint_as_float(d[4 * q + 2]) + bg[u];
                    float zo = __uint_as_float(d[4 * q + 3]) + bo[u];
                    float ig = fast_sigmoid(zi);
                    float fg = fast_sigmoid(zf);
                    float gg = tanh_fast(zg);
                    float og = fast_sigmoid(zo);
                    float cn = fg * cvs[q] + ig * gg;
                    hv[q] = og * tanh_fast(cn);
                    cnv[q] = cn;
                }
                *reinterpret_cast<float4*>(hrow + u0c) =
                    make_float4(hv[0], hv[1], hv[2], hv[3]);
                *reinterpret_cast<float4*>(hrow + u0c + 4) =
                    make_float4(hv[4], hv[5], hv[6], hv[7]);
                *reinterpret_cast<float4*>(corow + u0c) =
                    make_float4(cnv[0], cnv[1], cnv[2], cnv[3]);
                *reinterpret_cast<float4*>(corow + u0c + 4) =
                    make_float4(cnv[4], cnv[5], cnv[6], cnv[7]);
            }
        }
        TCGEN05_FENCE_BEFORE();
        __syncthreads();   // all warps' LDTM done before next tile's acc=0 MMA
    }

    if (tid == 0) {
#pragma unroll
        for (int s = 0; s < NSTAGES; s++) MBARRIER_INVAL(sb + SM_MBAR + 8 * s);
    }
    __syncthreads();
    if (wid == 0) TCGEN05_DEALLOC(tmem, 512);

#else
    // ======================= SIMT fallback (plain sm_103 target) ===========
    const int PAD = 132;
    float* As = reinterpret_cast<float*>(smem);          // [32][PAD]
    float* Bs = As + 32 * PAD;                           // [32][PAD]

    int tx = tid & 15;
    int ty = tid >> 4;

#pragma unroll 1
    for (int j = 0; j < ntiles; j++) {
        int t = tiles[j];
        int m0 = (t >> 4) * BM;
        int n0 = (t & (NTILES_N - 1)) * BN;

#pragma unroll 1
        for (int mh = 0; mh < 2; mh++) {
            int m0h = m0 + mh * 128;
#pragma unroll 1
            for (int ns = 0; ns < 2; ns++) {             // two 128-wide n halves
                int n0h = n0 + ns * 128;
                int u0 = n0h >> 2;
                float acc[8][8];
#pragma unroll
                for (int i = 0; i < 8; i++)
#pragma unroll
                    for (int q = 0; q < 8; q++) acc[i][q] = 0.0f;

#pragma unroll 1
                for (int kt = 0; kt < K_DIM / 32; kt++) {
                    int koff = kt * 32;
#pragma unroll
                    for (int i = 0; i < 16; i++) {
                        int idx = tid + i * 256;
                        int kk = idx & 31;
                        int r = idx >> 5;
                        size_t ga = (size_t)(m0h + r) * K_DIM + koff + kk;
                        size_t gb = (size_t)(n0h + r) * K_DIM + koff + kk;
                        As[kk * PAD + r] = __half2float(g_A_h[ga]);
                        Bs[kk * PAD + r] = __half2float(g_W_h[gb]);
                    }
                    __syncthreads();
#pragma unroll 1
                    for (int kk = 0; kk < 32; kk++) {
                        float a[8], b[8];
#pragma unroll
                        for (int i = 0; i < 8; i++) a[i] = As[kk * PAD + ty * 8 + i];
#pragma unroll
                        for (int q = 0; q < 8; q++) b[q] = Bs[kk * PAD + tx * 8 + q];
#pragma unroll
                        for (int i = 0; i < 8; i++)
#pragma unroll
                            for (int q = 0; q < 8; q++) acc[i][q] += a[i] * b[q];
                    }
                    __syncthreads();
                }

#pragma unroll
                for (int i = 0; i < 8; i++) {
                    int m = m0h + ty * 8 + i;
#pragma unroll
                    for (int jj = 0; jj < 2; jj++) {
                        int u = u0 + tx * 2 + jj;
                        float zi = acc[i][jj * 4 + 0] + bi[u];
                        float zf = acc[i][jj * 4 + 1] + bf_[u];
                        float zg = acc[i][jj * 4 + 2] + bg[u];
                        float zo = acc[i][jj * 4 + 3] + bo[u];
                        float ig = fast_sigmoid(zi);
                        float fg = fast_sigmoid(zf);
                        float gg = tanh_fast(zg);
                        float og = fast_sigmoid(zo);
                        float cv = c_in[(size_t)m * U_DIM + u];
                        float cn = fg * cv + ig * gg;
                        float hn = og * tanh_fast(cn);
                        out[(size_t)m * U_DIM + u] = hn;
                        out[c_off + (size_t)m * U_DIM + u] = cn;
                    }
                }
                __syncthreads();
            }
        }
    }
#endif
}

// ---------------- launch ----------------------------------------------------
extern "C" void kernel_launch(void* const* d_in, const int* in_sizes, int n_in,
                              void* d_out, int out_size) {
    const float* x  = (const float*)d_in[0];
    const float* h  = (const float*)d_in[1];
    const float* c  = (const float*)d_in[2];
    const float* Wi = (const float*)d_in[3];
    const float* Wf = (const float*)d_in[4];
    const float* Wg = (const float*)d_in[5];
    const float* Wo = (const float*)d_in[6];
    const float* bi = (const float*)d_in[7];
    const float* bf = (const float*)d_in[8];
    const float* bg = (const float*)d_in[9];
    const float* bo = (const float*)d_in[10];
    float* out = (float*)d_out;

    // 1) concat -> fp16 A
    prep_a_kernel<<<(int)(((size_t)B_DIM * K_DIM / 8) / 256), 256>>>(x, h);
    // 2) transpose -> fp16 W (gate-interleaved columns)
    prep_w_kernel<<<dim3(K_DIM / 32, U_DIM / 32, 4), dim3(32, 8)>>>(Wi, Wf, Wg, Wo);
    // 3) persistent GEMM + LSTM epilogue
    cudaFuncSetAttribute(lstm_gemm_kernel,
                         cudaFuncAttributeMaxDynamicSharedMemorySize, GEMM_SMEM);
    lstm_gemm_kernel<<<GRID_X, GEMM_THREADS, GEMM_SMEM>>>(
        c, bi, bf, bg, bo, out);
}

// round 10
// speedup vs baseline: 3.8276x; 1.2246x over previous
#include <cuda_runtime.h>
#include <cuda_fp16.h>
#include <cstdint>

// ============================================================================
// CellLSTM on GB300 (sm_103a)
//   z = [x|h] @ [Wi|Wf|Wg|Wo] + b ; gates; c' = f*c + i*g ; h' = o*tanh(c')
//   R10: warp-specialized persistent kernel. Producers (warps 4-7) feed a
//   3-slot cp.async ring via full[]/mma[] mbarriers; consumer (warp 0) issues
//   tcgen05 MMAs; NO per-iteration __syncthreads (R9 measured ~635cyc/iter of
//   rendezvous overhead). Epilogue on warps 0-3 via named barrier.
// ============================================================================

#if defined(__CUDA_ARCH_FEAT_SM103_ALL) || defined(__CUDA_ARCH_FEAT_SM100_ALL)
#define USE_TCGEN05 1
#else
#define USE_TCGEN05 0
#endif

#define B_DIM 8192
#define T_DIM 1024
#define U_DIM 1024
#define K_DIM 2048
#define N_DIM 4096

#define BM 256              // two M=128 MMA halves
#define BN 256
#define BK 64
#define KTILES (K_DIM / BK)         // 32 k-iterations per tile
#define NTILES_TOTAL ((B_DIM / BM) * (N_DIM / BN))   // 512
#define NTILES_N (N_DIM / BN)       // 16
#define GRID_X 152
#define MAX_TILES_PER_CTA 4
#define GEMM_THREADS 256

// ---------------- scratch (device globals: allocation-rule-safe) -----------
__device__ __align__(16) __half g_A_h[(size_t)B_DIM * K_DIM];
// W transposed & gate-interleaved: row n = u*4 + gate, K-major
__device__ __align__(16) __half g_W_h[(size_t)N_DIM * K_DIM];

// ---------------- arch-neutral helpers -------------------------------------
__device__ __forceinline__ uint32_t smem_u32(const void* p) {
    uint32_t a;
    asm("{ .reg .u64 t; cvta.to.shared.u64 t, %1; cvt.u32.u64 %0, t; }"
        : "=r"(a) : "l"(p));
    return a;
}

#define SWZ128(off) ((off) ^ (((off) >> 3) & 0x70))

__device__ __forceinline__ float tanh_fast(float x) {
    float y;
    asm("tanh.approx.f32 %0, %1;" : "=f"(y) : "f"(x));
    return y;
}

// sigmoid(z) = 0.5*tanh(z/2) + 0.5  (1 MUFU instead of EX2+RCP)
__device__ __forceinline__ float fast_sigmoid(float z) {
    return fmaf(0.5f, tanh_fast(0.5f * z), 0.5f);
}

#if USE_TCGEN05
// ---------------- tcgen05 / mbarrier / cp.async helpers --------------------
__device__ __forceinline__ uint32_t elect_one() {
    uint32_t pred;
    asm volatile(
        "{\n\t.reg .pred p;\n\telect.sync _|p, 0xFFFFFFFF;\n\t"
        "selp.b32 %0, 1, 0, p;\n\t}" : "=r"(pred));
    return pred;
}

#define MBARRIER_INIT(addr, cnt) \
    asm volatile("mbarrier.init.shared.b64 [%0], %1;" \
                 :: "r"((uint32_t)(addr)), "r"((uint32_t)(cnt)) : "memory")

#define MBARRIER_INVAL(addr) \
    asm volatile("mbarrier.inval.shared.b64 [%0];" \
                 :: "r"((uint32_t)(addr)) : "memory")

#define MBARRIER_ARRIVE(addr) \
    asm volatile("mbarrier.arrive.shared.b64 _, [%0];" \
                 :: "r"((uint32_t)(addr)) : "memory")

#define MBARRIER_WAIT_PARITY(mbar_smem_addr, phase_parity) do { \
    uint32_t _mbar = (uint32_t)(mbar_smem_addr); \
    uint32_t _parity = (uint32_t)(phase_parity); \
    uint32_t _done; \
    asm volatile( \
        "{\n\t.reg .pred p;\n\t" \
        "mbarrier.try_wait.parity.acquire.cta.shared::cta.b64 p, [%1], %2;\n\t" \
        "selp.b32 %0, 1, 0, p;\n\t}" \
        : "=r"(_done) : "r"(_mbar), "r"(_parity) : "memory"); \
    if (!_done) { \
        asm volatile( \
            "{\n\t.reg .pred P1;\n\t" \
            "WAIT_LOOP_%=:\n\t" \
            "mbarrier.try_wait.parity.acquire.cta.shared::cta.b64 P1, [%0], %1, 0x989680;\n\t" \
            "@P1 bra.uni WAIT_DONE_%=;\n\t" \
            "bra.uni WAIT_LOOP_%=;\n\t" \
            "WAIT_DONE_%=:\n\t}" \
            :: "r"(_mbar), "r"(_parity) : "memory"); \
    } \
} while (0)

#define NAMED_BARRIER_SYNC(id, cnt) \
    asm volatile("bar.sync %0, %1;" :: "r"(id), "r"(cnt) : "memory")

#define TCGEN05_ALLOC(smem_result_addr, nCols) \
    asm volatile("tcgen05.alloc.cta_group::1.sync.aligned.shared::cta.b32 [%0], %1;" \
                 :: "r"((uint32_t)(smem_result_addr)), "r"((uint32_t)(nCols)) : "memory")

#define TCGEN05_DEALLOC(tmem_addr, nCols) \
    asm volatile("tcgen05.dealloc.cta_group::1.sync.aligned.b32 %0, %1;" \
                 :: "r"(tmem_addr), "r"((uint32_t)(nCols)))

#define TCGEN05_COMMIT(mbar_smem_addr) \
    asm volatile("tcgen05.commit.cta_group::1.mbarrier::arrive::one.shared::cluster.b64 [%0];" \
                 :: "r"((uint32_t)(mbar_smem_addr)) : "memory")

#define TCGEN05_FENCE_AFTER() \
    asm volatile("tcgen05.fence::after_thread_sync;" ::: "memory")
#define TCGEN05_FENCE_BEFORE() \
    asm volatile("tcgen05.fence::before_thread_sync;" ::: "memory")
#define TCGEN05_WAIT_LD() \
    asm volatile("tcgen05.wait::ld.sync.aligned;" ::: "memory")

#define FENCE_PROXY_ASYNC() \
    asm volatile("fence.proxy.async.shared::cta;" ::: "memory")

#define CP_ASYNC_COMMIT() asm volatile("cp.async.commit_group;" ::: "memory")
#define CP_ASYNC_WAIT(n)  asm volatile("cp.async.wait_group %0;" :: "n"(n) : "memory")

__device__ __forceinline__ void cp16(uint32_t dst, const void* src) {
    asm volatile("cp.async.cg.shared.global [%0], [%1], 16;"
                 :: "r"(dst), "l"(src) : "memory");
}

#define TCGEN05_LD_32X32B_X32(r, tmem_addr) \
    asm volatile( \
        "tcgen05.ld.sync.aligned.32x32b.x32.b32 " \
        "{%0, %1, %2, %3, %4, %5, %6, %7, " \
        " %8, %9, %10, %11, %12, %13, %14, %15, " \
        " %16, %17, %18, %19, %20, %21, %22, %23, " \
        " %24, %25, %26, %27, %28, %29, %30, %31}, [%32];" \
        : "=r"((r)[0]),  "=r"((r)[1]),  "=r"((r)[2]),  "=r"((r)[3]), \
          "=r"((r)[4]),  "=r"((r)[5]),  "=r"((r)[6]),  "=r"((r)[7]), \
          "=r"((r)[8]),  "=r"((r)[9]),  "=r"((r)[10]), "=r"((r)[11]), \
          "=r"((r)[12]), "=r"((r)[13]), "=r"((r)[14]), "=r"((r)[15]), \
          "=r"((r)[16]), "=r"((r)[17]), "=r"((r)[18]), "=r"((r)[19]), \
          "=r"((r)[20]), "=r"((r)[21]), "=r"((r)[22]), "=r"((r)[23]), \
          "=r"((r)[24]), "=r"((r)[25]), "=r"((r)[26]), "=r"((r)[27]), \
          "=r"((r)[28]), "=r"((r)[29]), "=r"((r)[30]), "=r"((r)[31]) \
        : "r"(tmem_addr))

// K-major SW128 smem descriptor (verified: test_mma_iter)
static constexpr uint64_t SMEM_DESC_BASE_SW128 =
    (uint64_t(2)  << 61) | (uint64_t(1) << 46) |
    (uint64_t(64) << 32) | (uint64_t(1) << 16);

__device__ __forceinline__ uint64_t make_desc(uint32_t addr) {
    return SMEM_DESC_BASE_SW128 | ((uint64_t)(addr >> 4) & 0x3FFF);
}

// idesc kind::f16, FP16 inputs, f32 accum, M=128 (per MMA stream), N=256
static constexpr uint32_t MMA_IDESC =
    (1u << 4) | (0u << 7) | (0u << 10) | ((BN / 8) << 17) | ((128 / 16) << 24);

__device__ __forceinline__ void mma_f16_ss(uint32_t d, uint64_t ad, uint64_t bd,
                                           uint32_t idesc, uint32_t acc) {
    asm volatile(
        "{\n\t.reg .pred p;\n\t"
        "setp.ne.u32 p, %4, 0;\n\t"
        "tcgen05.mma.cta_group::1.kind::f16 [%0], %1, %2, %3, {%5, %5, %5, %5}, p;\n\t"
        "}"
        :: "r"(d), "l"(ad), "l"(bd), "r"(idesc), "r"(acc), "r"(0u)
        : "memory");
}
#endif // USE_TCGEN05

// ---------------- prep kernel A: concat(x,h) -> fp16 -----------------------
__global__ void prep_a_kernel(const float* __restrict__ x, const float* __restrict__ h) {
    size_t idx8 = ((size_t)blockIdx.x * blockDim.x + threadIdx.x) * 8;
    int m = (int)(idx8 / K_DIM);
    int k = (int)(idx8 % K_DIM);
    const float* src = (k < T_DIM) ? (x + (size_t)m * T_DIM + k)
                                   : (h + (size_t)m * U_DIM + (k - T_DIM));
    float4 v0 = *reinterpret_cast<const float4*>(src);
    float4 v1 = *reinterpret_cast<const float4*>(src + 4);

    union Pack { __half b[8]; uint4 u; } p;
    p.b[0] = __float2half_rn(v0.x); p.b[1] = __float2half_rn(v0.y);
    p.b[2] = __float2half_rn(v0.z); p.b[3] = __float2half_rn(v0.w);
    p.b[4] = __float2half_rn(v1.x); p.b[5] = __float2half_rn(v1.y);
    p.b[6] = __float2half_rn(v1.z); p.b[7] = __float2half_rn(v1.w);
    *reinterpret_cast<uint4*>(g_A_h + idx8) = p.u;
}

// ---------------- prep kernel B: W transpose+convert, gate-interleaved -----
__global__ void prep_w_kernel(const float* __restrict__ Wi, const float* __restrict__ Wf,
                              const float* __restrict__ Wg, const float* __restrict__ Wo) {
    __shared__ float tile[32][33];
    int gate = blockIdx.z;
    const float* W = (gate == 0) ? Wi : (gate == 1) ? Wf : (gate == 2) ? Wg : Wo;
    int k0 = blockIdx.x * 32;
    int u0 = blockIdx.y * 32;
    int tx = threadIdx.x, ty = threadIdx.y;

#pragma unroll
    for (int i = 0; i < 4; i++) {
        int k = k0 + ty + i * 8;
        tile[ty + i * 8][tx] = W[(size_t)k * U_DIM + u0 + tx];  // coalesced over u
    }
    __syncthreads();
#pragma unroll
    for (int i = 0; i < 4; i++) {
        int u = u0 + ty + i * 8;
        float v = tile[tx][ty + i * 8];          // = W[k0+tx, u]
        size_t off = (size_t)(u * 4 + gate) * K_DIM + k0 + tx;  // coalesced over k
        g_W_h[off] = __float2half_rn(v);
    }
}

// ---------------- GEMM + LSTM epilogue -------------------------------------
// SMEM map:
//   [0]      tmem ptr
//   [8]      full[3] mbarriers (8B each)   -- producers signal data ready
//   [32]     mma[3]  mbarriers (8B each)   -- MMA commit frees a slot
//   [1024]   3 stages x (A 32K + B 32K) = 192KB ring
#define SM_TMEM 0
#define SM_FULL 8
#define SM_MMAB 32
#define SM_STAGE 1024
#define A_TILE_BYTES 32768                  // 256 rows x 128B
#define B_TILE_BYTES 32768                  // 256 rows x 128B
#define STAGE_BYTES (A_TILE_BYTES + B_TILE_BYTES)           // 65536
#define NSTAGES 3
#define GEMM_SMEM (SM_STAGE + NSTAGES * STAGE_BYTES)        // 197632
#define N_PRODUCER_THREADS 128

#if USE_TCGEN05
// Each of the 128 producer threads loads 32 x 16B chunks (A then B).
__device__ __forceinline__ void load_stage_quarter(uint32_t sbase, int kt,
                                                   int m0, int n0, int ptid) {
    int koff = kt * BK;
    // A: 256 rows x 8 chunks (2048 chunks) -> 16 per producer thread
#pragma unroll
    for (int j = 0; j < 16; j++) {
        int i = ptid + j * N_PRODUCER_THREADS;
        int r = i >> 3;
        int c = i & 7;
        uint32_t soff = SWZ128((uint32_t)(r * 128 + c * 16));
        size_t ga = (size_t)(m0 + r) * K_DIM + koff + c * 8;
        cp16(sbase + soff, g_A_h + ga);
    }
    // B: 256 rows x 8 chunks -> 16 per producer thread
    uint32_t bbase = sbase + A_TILE_BYTES;
#pragma unroll
    for (int j = 0; j < 16; j++) {
        int i = ptid + j * N_PRODUCER_THREADS;
        int r = i >> 3;
        int c = i & 7;
        uint32_t soff = SWZ128((uint32_t)(r * 128 + c * 16));
        size_t gb = (size_t)(n0 + r) * K_DIM + koff + c * 8;
        cp16(bbase + soff, g_W_h + gb);
    }
}
#endif

__global__ void __launch_bounds__(GEMM_THREADS)
lstm_gemm_kernel(const float* __restrict__ c_in,
                 const float* __restrict__ bi, const float* __restrict__ bf_,
                 const float* __restrict__ bg, const float* __restrict__ bo,
                 float* __restrict__ out) {
    extern __shared__ char smem[];
    int tid = threadIdx.x;
    const size_t c_off = (size_t)B_DIM * U_DIM;

    // tiles owned by this CTA (persistent)
    int tiles[MAX_TILES_PER_CTA];
    int ntiles = 0;
    for (int t = blockIdx.x; t < NTILES_TOTAL && ntiles < MAX_TILES_PER_CTA;
         t += GRID_X)
        tiles[ntiles++] = t;
    if (ntiles == 0) return;

#if USE_TCGEN05
    // ======================= warp-specialized persistent path ===============
    uint32_t sb = smem_u32(smem);
    int wid = tid >> 5;
    int lid = tid & 31;

    if (wid == 0) TCGEN05_ALLOC(sb + SM_TMEM, 512);
    if (tid == 0) {
#pragma unroll
        for (int s = 0; s < NSTAGES; s++) {
            MBARRIER_INIT(sb + SM_FULL + 8 * s, N_PRODUCER_THREADS);
            MBARRIER_INIT(sb + SM_MMAB + 8 * s, 1);
        }
    }
    __syncthreads();
    uint32_t tmem;
    asm volatile("ld.shared.b32 %0, [%1];" : "=r"(tmem) : "r"(sb + SM_TMEM));

    const int G = ntiles * KTILES;

    if (wid >= 4) {
        // =================== PRODUCER warps 4-7 =============================
        int ptid = tid - 128;    // 0..127

        // prologue: fill slots 0,1; signal full[0]
        {
            int m00 = (tiles[0] >> 4) * BM;
            int n00 = (tiles[0] & (NTILES_N - 1)) * BN;
            load_stage_quarter(sb + SM_STAGE + 0 * STAGE_BYTES, 0, m00, n00, ptid);
            CP_ASYNC_COMMIT();
            load_stage_quarter(sb + SM_STAGE + 1 * STAGE_BYTES, 1, m00, n00, ptid);
            CP_ASYNC_COMMIT();
            CP_ASYNC_WAIT(1);                       // group 0 landed
            MBARRIER_ARRIVE(sb + SM_FULL + 8 * 0);
        }

#pragma unroll 1
        for (int gp = 2; gp < G; gp++) {
            // slot gp%3 was consumed by MMA(gp-3): wait its commit
            if (gp >= 3) {
                int w = gp - 3;
                MBARRIER_WAIT_PARITY(sb + SM_MMAB + 8 * (w % NSTAGES),
                                     (w / NSTAGES) & 1);
            }
            int j2 = gp >> 5;                       // KTILES == 32
            int kt2 = gp & 31;
            int t2 = tiles[j2];
            int m02 = (t2 >> 4) * BM;
            int n02 = (t2 & (NTILES_N - 1)) * BN;
            load_stage_quarter(sb + SM_STAGE + (gp % NSTAGES) * STAGE_BYTES,
                               kt2, m02, n02, ptid);
            CP_ASYNC_COMMIT();
            CP_ASYNC_WAIT(1);                       // group gp-1 landed
            MBARRIER_ARRIVE(sb + SM_FULL + 8 * ((gp - 1) % NSTAGES));
        }
        CP_ASYNC_WAIT(0);                           // group G-1 landed
        MBARRIER_ARRIVE(sb + SM_FULL + 8 * ((G - 1) % NSTAGES));

    } else {
        // =================== CONSUMER warps 0-3 =============================
        int g = 0;
#pragma unroll 1
        for (int j = 0; j < ntiles; j++) {
            int t = tiles[j];
            int m0 = (t >> 4) * BM;
            int n0 = (t & (NTILES_N - 1)) * BN;
            int u_base = n0 >> 2;

            if (wid == 0) {
#pragma unroll 1
                for (int kt = 0; kt < KTILES; kt++, g++) {
                    MBARRIER_WAIT_PARITY(sb + SM_FULL + 8 * (g % NSTAGES),
                                         (g / NSTAGES) & 1);
                    uint32_t st = sb + SM_STAGE + (g % NSTAGES) * STAGE_BYTES;
                    uint64_t dA0 = make_desc(st);             // rows 0..127
                    uint64_t dA1 = make_desc(st + 16384);     // rows 128..255
                    uint64_t dB  = make_desc(st + A_TILE_BYTES);
                    if (elect_one()) {
                        FENCE_PROXY_ASYNC();
#pragma unroll
                        for (int s = 0; s < 4; s++) {
                            uint32_t off = s * 2;
                            uint32_t acc = (kt | s) != 0;
                            mma_f16_ss(tmem,       dA0 + off, dB + off, MMA_IDESC, acc);
                            mma_f16_ss(tmem + 256, dA1 + off, dB + off, MMA_IDESC, acc);
                        }
                        TCGEN05_COMMIT(sb + SM_MMAB + 8 * (g % NSTAGES));
                    }
                }
                // wait last MMA of this tile before epilogue
                int gl = g - 1;
                MBARRIER_WAIT_PARITY(sb + SM_MMAB + 8 * (gl % NSTAGES),
                                     (gl / NSTAGES) & 1);
            } else {
                g += KTILES;   // warps 1-3 skip the mainloop
            }

            // warps 0-3 rendezvous: warp 0 arrives only after gl commit
            NAMED_BARRIER_SYNC(1, 128);
            TCGEN05_FENCE_AFTER();

            // ------- epilogue: warp w owns D lanes w*32+lid (all 512 cols) --
#pragma unroll
            for (int mh = 0; mh < 2; mh++) {
                int m = m0 + mh * 128 + wid * 32 + lid;
                const float* crow = c_in + (size_t)m * U_DIM;
                float* hrow = out + (size_t)m * U_DIM;
                float* corow = out + c_off + (size_t)m * U_DIM;
#pragma unroll
                for (int ch = 0; ch < 8; ch++) {
                    uint32_t col = (uint32_t)(mh * 256 + ch * 32);
                    uint32_t d[32];
                    TCGEN05_LD_32X32B_X32(d, tmem + col);
                    int u0c = u_base + ch * 8;
                    float4 cv0 = *reinterpret_cast<const float4*>(crow + u0c);
                    float4 cv1 = *reinterpret_cast<const float4*>(crow + u0c + 4);
                    float cvs[8] = {cv0.x, cv0.y, cv0.z, cv0.w,
                                    cv1.x, cv1.y, cv1.z, cv1.w};
                    TCGEN05_WAIT_LD();
                    float hv[8], cnv[8];
#pragma unroll
                    for (int q = 0; q < 8; q++) {
                        int u = u0c + q;
                        float zi = __uint_as_float(d[4 * q + 0]) + bi[u];
                        float zf = __uint_as_float(d[4 * q + 1]) + bf_[u];
                        float zg = __uint_as_float(d[4 * q + 2]) + bg[u];
                        float zo = __uint_as_float(d[4 * q + 3]) + bo[u];
                        float ig = fast_sigmoid(zi);
                        float fg = fast_sigmoid(zf);
                        float gg = tanh_fast(zg);
                        float og = fast_sigmoid(zo);
                        float cn = fg * cvs[q] + ig * gg;
                        hv[q] = og * tanh_fast(cn);
                        cnv[q] = cn;
                    }
                    *reinterpret_cast<float4*>(hrow + u0c) =
                        make_float4(hv[0], hv[1], hv[2], hv[3]);
                    *reinterpret_cast<float4*>(hrow + u0c + 4) =
                        make_float4(hv[4], hv[5], hv[6], hv[7]);
                    *reinterpret_cast<float4*>(corow + u0c) =
                        make_float4(cnv[0], cnv[1], cnv[2], cnv[3]);
                    *reinterpret_cast<float4*>(corow + u0c + 4) =
                        make_float4(cnv[4], cnv[5], cnv[6], cnv[7]);
                }
            }
            TCGEN05_WAIT_LD();
            TCGEN05_FENCE_BEFORE();
            // all warps 0-3 done reading D before next tile's acc=0 MMA
            NAMED_BARRIER_SYNC(1, 128);
        }
    }

    __syncthreads();
    if (tid == 0) {
#pragma unroll
        for (int s = 0; s < NSTAGES; s++) {
            MBARRIER_INVAL(sb + SM_FULL + 8 * s);
            MBARRIER_INVAL(sb + SM_MMAB + 8 * s);
        }
    }
    __syncthreads();
    if (wid == 0) TCGEN05_DEALLOC(tmem, 512);

#else
    // ======================= SIMT fallback (plain sm_103 target) ===========
    const int PAD = 132;
    float* As = reinterpret_cast<float*>(smem);          // [32][PAD]
    float* Bs = As + 32 * PAD;                           // [32][PAD]

    int tx = tid & 15;
    int ty = tid >> 4;

#pragma unroll 1
    for (int j = 0; j < ntiles; j++) {
        int t = tiles[j];
        int m0 = (t >> 4) * BM;
        int n0 = (t & (NTILES_N - 1)) * BN;

#pragma unroll 1
        for (int mh = 0; mh < 2; mh++) {
            int m0h = m0 + mh * 128;
#pragma unroll 1
            for (int ns = 0; ns < 2; ns++) {             // two 128-wide n halves
                int n0h = n0 + ns * 128;
                int u0 = n0h >> 2;
                float acc[8][8];
#pragma unroll
                for (int i = 0; i < 8; i++)
#pragma unroll
                    for (int q = 0; q < 8; q++) acc[i][q] = 0.0f;

#pragma unroll 1
                for (int kt = 0; kt < K_DIM / 32; kt++) {
                    int koff = kt * 32;
#pragma unroll
                    for (int i = 0; i < 16; i++) {
                        int idx = tid + i * 256;
                        int kk = idx & 31;
                        int r = idx >> 5;
                        size_t ga = (size_t)(m0h + r) * K_DIM + koff + kk;
                        size_t gb = (size_t)(n0h + r) * K_DIM + koff + kk;
                        As[kk * PAD + r] = __half2float(g_A_h[ga]);
                        Bs[kk * PAD + r] = __half2float(g_W_h[gb]);
                    }
                    __syncthreads();
#pragma unroll 1
                    for (int kk = 0; kk < 32; kk++) {
                        float a[8], b[8];
#pragma unroll
                        for (int i = 0; i < 8; i++) a[i] = As[kk * PAD + ty * 8 + i];
#pragma unroll
                        for (int q = 0; q < 8; q++) b[q] = Bs[kk * PAD + tx * 8 + q];
#pragma unroll
                        for (int i = 0; i < 8; i++)
#pragma unroll
                            for (int q = 0; q < 8; q++) acc[i][q] += a[i] * b[q];
                    }
                    __syncthreads();
                }

#pragma unroll
                for (int i = 0; i < 8; i++) {
                    int m = m0h + ty * 8 + i;
#pragma unroll
                    for (int jj = 0; jj < 2; jj++) {
                        int u = u0 + tx * 2 + jj;
                        float zi = acc[i][jj * 4 + 0] + bi[u];
                        float zf = acc[i][jj * 4 + 1] + bf_[u];
                        float zg = acc[i][jj * 4 + 2] + bg[u];
                        float zo = acc[i][jj * 4 + 3] + bo[u];
                        float ig = fast_sigmoid(zi);
                        float fg = fast_sigmoid(zf);
                        float gg = tanh_fast(zg);
                        float og = fast_sigmoid(zo);
                        float cv = c_in[(size_t)m * U_DIM + u];
                        float cn = fg * cv + ig * gg;
                        float hn = og * tanh_fast(cn);
                        out[(size_t)m * U_DIM + u] = hn;
                        out[c_off + (size_t)m * U_DIM + u] = cn;
                    }
                }
                __syncthreads();
            }
        }
    }
#endif
}

// ---------------- launch ----------------------------------------------------
extern "C" void kernel_launch(void* const* d_in, const int* in_sizes, int n_in,
                              void* d_out, int out_size) {
    const float* x  = (const float*)d_in[0];
    const float* h  = (const float*)d_in[1];
    const float* c  = (const float*)d_in[2];
    const float* Wi = (const float*)d_in[3];
    const float* Wf = (const float*)d_in[4];
    const float* Wg = (const float*)d_in[5];
    const float* Wo = (const float*)d_in[6];
    const float* bi = (const float*)d_in[7];
    const float* bf = (const float*)d_in[8];
    const float* bg = (const float*)d_in[9];
    const float* bo = (const float*)d_in[10];
    float* out = (float*)d_out;

    // 1) concat -> fp16 A
    prep_a_kernel<<<(int)(((size_t)B_DIM * K_DIM / 8) / 256), 256>>>(x, h);
    // 2) transpose -> fp16 W (gate-interleaved columns)
    prep_w_kernel<<<dim3(K_DIM / 32, U_DIM / 32, 4), dim3(32, 8)>>>(Wi, Wf, Wg, Wo);
    // 3) persistent warp-specialized GEMM + LSTM epilogue
    cudaFuncSetAttribute(lstm_gemm_kernel,
                         cudaFuncAttributeMaxDynamicSharedMemorySize, GEMM_SMEM);
    lstm_gemm_kernel<<<GRID_X, GEMM_THREADS, GEMM_SMEM>>>(
        c, bi, bf, bg, bo, out);
}

// round 11
// speedup vs baseline: 3.9171x; 1.0234x over previous
#include <cuda_runtime.h>
#include <cuda_fp16.h>
#include <cstdint>

// ============================================================================
// CellLSTM on GB300 (sm_103a)
//   z = [x|h] @ [Wi|Wf|Wg|Wo] + b ; gates; c' = f*c + i*g ; h' = o*tanh(c')
//   R11: R10 warp-specialized persistent pipeline unchanged; scheduling fixes:
//   (1) prep_a + prep_w fused into ONE kernel (HBM-overlapped, -1 launch),
//   (2) GRID_X=128 -> exactly 4 tiles/CTA (R10's 152 left 56 CTAs pacing a
//   4th tile while 96 idled).
// ============================================================================

#if defined(__CUDA_ARCH_FEAT_SM103_ALL) || defined(__CUDA_ARCH_FEAT_SM100_ALL)
#define USE_TCGEN05 1
#else
#define USE_TCGEN05 0
#endif

#define B_DIM 8192
#define T_DIM 1024
#define U_DIM 1024
#define K_DIM 2048
#define N_DIM 4096

#define BM 256              // two M=128 MMA halves
#define BN 256
#define BK 64
#define KTILES (K_DIM / BK)         // 32 k-iterations per tile
#define NTILES_TOTAL ((B_DIM / BM) * (N_DIM / BN))   // 512
#define NTILES_N (N_DIM / BN)       // 16
#define GRID_X 128                  // 512 tiles / 128 = exactly 4 per CTA
#define MAX_TILES_PER_CTA 4
#define GEMM_THREADS 256

// ---------------- scratch (device globals: allocation-rule-safe) -----------
__device__ __align__(16) __half g_A_h[(size_t)B_DIM * K_DIM];
// W transposed & gate-interleaved: row n = u*4 + gate, K-major
__device__ __align__(16) __half g_W_h[(size_t)N_DIM * K_DIM];

// ---------------- arch-neutral helpers -------------------------------------
__device__ __forceinline__ uint32_t smem_u32(const void* p) {
    uint32_t a;
    asm("{ .reg .u64 t; cvta.to.shared.u64 t, %1; cvt.u32.u64 %0, t; }"
        : "=r"(a) : "l"(p));
    return a;
}

#define SWZ128(off) ((off) ^ (((off) >> 3) & 0x70))

__device__ __forceinline__ float tanh_fast(float x) {
    float y;
    asm("tanh.approx.f32 %0, %1;" : "=f"(y) : "f"(x));
    return y;
}

// sigmoid(z) = 0.5*tanh(z/2) + 0.5  (1 MUFU instead of EX2+RCP)
__device__ __forceinline__ float fast_sigmoid(float z) {
    return fmaf(0.5f, tanh_fast(0.5f * z), 0.5f);
}

#if USE_TCGEN05
// ---------------- tcgen05 / mbarrier / cp.async helpers --------------------
__device__ __forceinline__ uint32_t elect_one() {
    uint32_t pred;
    asm volatile(
        "{\n\t.reg .pred p;\n\telect.sync _|p, 0xFFFFFFFF;\n\t"
        "selp.b32 %0, 1, 0, p;\n\t}" : "=r"(pred));
    return pred;
}

#define MBARRIER_INIT(addr, cnt) \
    asm volatile("mbarrier.init.shared.b64 [%0], %1;" \
                 :: "r"((uint32_t)(addr)), "r"((uint32_t)(cnt)) : "memory")

#define MBARRIER_INVAL(addr) \
    asm volatile("mbarrier.inval.shared.b64 [%0];" \
                 :: "r"((uint32_t)(addr)) : "memory")

#define MBARRIER_ARRIVE(addr) \
    asm volatile("mbarrier.arrive.shared.b64 _, [%0];" \
                 :: "r"((uint32_t)(addr)) : "memory")

#define MBARRIER_WAIT_PARITY(mbar_smem_addr, phase_parity) do { \
    uint32_t _mbar = (uint32_t)(mbar_smem_addr); \
    uint32_t _parity = (uint32_t)(phase_parity); \
    uint32_t _done; \
    asm volatile( \
        "{\n\t.reg .pred p;\n\t" \
        "mbarrier.try_wait.parity.acquire.cta.shared::cta.b64 p, [%1], %2;\n\t" \
        "selp.b32 %0, 1, 0, p;\n\t}" \
        : "=r"(_done) : "r"(_mbar), "r"(_parity) : "memory"); \
    if (!_done) { \
        asm volatile( \
            "{\n\t.reg .pred P1;\n\t" \
            "WAIT_LOOP_%=:\n\t" \
            "mbarrier.try_wait.parity.acquire.cta.shared::cta.b64 P1, [%0], %1, 0x989680;\n\t" \
            "@P1 bra.uni WAIT_DONE_%=;\n\t" \
            "bra.uni WAIT_LOOP_%=;\n\t" \
            "WAIT_DONE_%=:\n\t}" \
            :: "r"(_mbar), "r"(_parity) : "memory"); \
    } \
} while (0)

#define NAMED_BARRIER_SYNC(id, cnt) \
    asm volatile("bar.sync %0, %1;" :: "r"(id), "r"(cnt) : "memory")

#define TCGEN05_ALLOC(smem_result_addr, nCols) \
    asm volatile("tcgen05.alloc.cta_group::1.sync.aligned.shared::cta.b32 [%0], %1;" \
                 :: "r"((uint32_t)(smem_result_addr)), "r"((uint32_t)(nCols)) : "memory")

#define TCGEN05_DEALLOC(tmem_addr, nCols) \
    asm volatile("tcgen05.dealloc.cta_group::1.sync.aligned.b32 %0, %1;" \
                 :: "r"(tmem_addr), "r"((uint32_t)(nCols)))

#define TCGEN05_COMMIT(mbar_smem_addr) \
    asm volatile("tcgen05.commit.cta_group::1.mbarrier::arrive::one.shared::cluster.b64 [%0];" \
                 :: "r"((uint32_t)(mbar_smem_addr)) : "memory")

#define TCGEN05_FENCE_AFTER() \
    asm volatile("tcgen05.fence::after_thread_sync;" ::: "memory")
#define TCGEN05_FENCE_BEFORE() \
    asm volatile("tcgen05.fence::before_thread_sync;" ::: "memory")
#define TCGEN05_WAIT_LD() \
    asm volatile("tcgen05.wait::ld.sync.aligned;" ::: "memory")

#define FENCE_PROXY_ASYNC() \
    asm volatile("fence.proxy.async.shared::cta;" ::: "memory")

#define CP_ASYNC_COMMIT() asm volatile("cp.async.commit_group;" ::: "memory")
#define CP_ASYNC_WAIT(n)  asm volatile("cp.async.wait_group %0;" :: "n"(n) : "memory")

__device__ __forceinline__ void cp16(uint32_t dst, const void* src) {
    asm volatile("cp.async.cg.shared.global [%0], [%1], 16;"
                 :: "r"(dst), "l"(src) : "memory");
}

#define TCGEN05_LD_32X32B_X32(r, tmem_addr) \
    asm volatile( \
        "tcgen05.ld.sync.aligned.32x32b.x32.b32 " \
        "{%0, %1, %2, %3, %4, %5, %6, %7, " \
        " %8, %9, %10, %11, %12, %13, %14, %15, " \
        " %16, %17, %18, %19, %20, %21, %22, %23, " \
        " %24, %25, %26, %27, %28, %29, %30, %31}, [%32];" \
        : "=r"((r)[0]),  "=r"((r)[1]),  "=r"((r)[2]),  "=r"((r)[3]), \
          "=r"((r)[4]),  "=r"((r)[5]),  "=r"((r)[6]),  "=r"((r)[7]), \
          "=r"((r)[8]),  "=r"((r)[9]),  "=r"((r)[10]), "=r"((r)[11]), \
          "=r"((r)[12]), "=r"((r)[13]), "=r"((r)[14]), "=r"((r)[15]), \
          "=r"((r)[16]), "=r"((r)[17]), "=r"((r)[18]), "=r"((r)[19]), \
          "=r"((r)[20]), "=r"((r)[21]), "=r"((r)[22]), "=r"((r)[23]), \
          "=r"((r)[24]), "=r"((r)[25]), "=r"((r)[26]), "=r"((r)[27]), \
          "=r"((r)[28]), "=r"((r)[29]), "=r"((r)[30]), "=r"((r)[31]) \
        : "r"(tmem_addr))

// K-major SW128 smem descriptor (verified: test_mma_iter)
static constexpr uint64_t SMEM_DESC_BASE_SW128 =
    (uint64_t(2)  << 61) | (uint64_t(1) << 46) |
    (uint64_t(64) << 32) | (uint64_t(1) << 16);

__device__ __forceinline__ uint64_t make_desc(uint32_t addr) {
    return SMEM_DESC_BASE_SW128 | ((uint64_t)(addr >> 4) & 0x3FFF);
}

// idesc kind::f16, FP16 inputs, f32 accum, M=128 (per MMA stream), N=256
static constexpr uint32_t MMA_IDESC =
    (1u << 4) | (0u << 7) | (0u << 10) | ((BN / 8) << 17) | ((128 / 16) << 24);

__device__ __forceinline__ void mma_f16_ss(uint32_t d, uint64_t ad, uint64_t bd,
                                           uint32_t idesc, uint32_t acc) {
    asm volatile(
        "{\n\t.reg .pred p;\n\t"
        "setp.ne.u32 p, %4, 0;\n\t"
        "tcgen05.mma.cta_group::1.kind::f16 [%0], %1, %2, %3, {%5, %5, %5, %5}, p;\n\t"
        "}"
        :: "r"(d), "l"(ad), "l"(bd), "r"(idesc), "r"(acc), "r"(0u)
        : "memory");
}
#endif // USE_TCGEN05

// ---------------- fused prep kernel -----------------------------------------
// blocks [0, PREP_A_BLOCKS): concat(x,h) -> fp16 A
// blocks [PREP_A_BLOCKS, ..): W transpose+convert, gate-interleaved
#define PREP_A_BLOCKS ((int)(((size_t)B_DIM * K_DIM / 8) / 256))   // 8192
#define PREP_W_BLOCKS ((K_DIM / 32) * (U_DIM / 32) * 4)            // 8192

__global__ void prep_fused_kernel(const float* __restrict__ x,
                                  const float* __restrict__ h,
                                  const float* __restrict__ Wi,
                                  const float* __restrict__ Wf,
                                  const float* __restrict__ Wg,
                                  const float* __restrict__ Wo) {
    __shared__ float tile[32][33];
    int bid = blockIdx.x;
    int tid = threadIdx.x;

    if (bid < PREP_A_BLOCKS) {
        // ---- A path: concat + fp16 convert, 8 elems/thread ----
        size_t idx8 = ((size_t)bid * 256 + tid) * 8;
        int m = (int)(idx8 / K_DIM);
        int k = (int)(idx8 % K_DIM);
        const float* src = (k < T_DIM) ? (x + (size_t)m * T_DIM + k)
                                       : (h + (size_t)m * U_DIM + (k - T_DIM));
        float4 v0 = *reinterpret_cast<const float4*>(src);
        float4 v1 = *reinterpret_cast<const float4*>(src + 4);

        union Pack { __half b[8]; uint4 u; } p;
        p.b[0] = __float2half_rn(v0.x); p.b[1] = __float2half_rn(v0.y);
        p.b[2] = __float2half_rn(v0.z); p.b[3] = __float2half_rn(v0.w);
        p.b[4] = __float2half_rn(v1.x); p.b[5] = __float2half_rn(v1.y);
        p.b[6] = __float2half_rn(v1.z); p.b[7] = __float2half_rn(v1.w);
        *reinterpret_cast<uint4*>(g_A_h + idx8) = p.u;
    } else {
        // ---- W path: 32x32 transpose tile per block ----
        int w = bid - PREP_A_BLOCKS;               // 0..8191
        int gate = w >> 11;                        // 2048 blocks per gate
        int rem = w & 2047;
        int k0 = (rem & 63) * 32;                  // 64 k-tiles
        int u0 = (rem >> 6) * 32;                  // 32 u-tiles
        const float* W = (gate == 0) ? Wi : (gate == 1) ? Wf
                        : (gate == 2) ? Wg : Wo;
        int tx = tid & 31;
        int ty = tid >> 5;                         // 0..7

#pragma unroll
        for (int i = 0; i < 4; i++) {
            int k = k0 + ty + i * 8;
            tile[ty + i * 8][tx] = W[(size_t)k * U_DIM + u0 + tx];
        }
        __syncthreads();
#pragma unroll
        for (int i = 0; i < 4; i++) {
            int u = u0 + ty + i * 8;
            float v = tile[tx][ty + i * 8];        // = W[k0+tx, u]
            size_t off = (size_t)(u * 4 + gate) * K_DIM + k0 + tx;
            g_W_h[off] = __float2half_rn(v);
        }
    }
}

// ---------------- GEMM + LSTM epilogue -------------------------------------
// SMEM map:
//   [0]      tmem ptr
//   [8]      full[3] mbarriers   -- producers signal data ready
//   [32]     mma[3]  mbarriers   -- MMA commit frees a slot
//   [1024]   3 stages x (A 32K + B 32K) = 192KB ring
#define SM_TMEM 0
#define SM_FULL 8
#define SM_MMAB 32
#define SM_STAGE 1024
#define A_TILE_BYTES 32768                  // 256 rows x 128B
#define B_TILE_BYTES 32768                  // 256 rows x 128B
#define STAGE_BYTES (A_TILE_BYTES + B_TILE_BYTES)           // 65536
#define NSTAGES 3
#define GEMM_SMEM (SM_STAGE + NSTAGES * STAGE_BYTES)        // 197632
#define N_PRODUCER_THREADS 128

#if USE_TCGEN05
// Each of the 128 producer threads loads 32 x 16B chunks (A then B).
__device__ __forceinline__ void load_stage_quarter(uint32_t sbase, int kt,
                                                   int m0, int n0, int ptid) {
    int koff = kt * BK;
#pragma unroll
    for (int j = 0; j < 16; j++) {
        int i = ptid + j * N_PRODUCER_THREADS;
        int r = i >> 3;
        int c = i & 7;
        uint32_t soff = SWZ128((uint32_t)(r * 128 + c * 16));
        size_t ga = (size_t)(m0 + r) * K_DIM + koff + c * 8;
        cp16(sbase + soff, g_A_h + ga);
    }
    uint32_t bbase = sbase + A_TILE_BYTES;
#pragma unroll
    for (int j = 0; j < 16; j++) {
        int i = ptid + j * N_PRODUCER_THREADS;
        int r = i >> 3;
        int c = i & 7;
        uint32_t soff = SWZ128((uint32_t)(r * 128 + c * 16));
        size_t gb = (size_t)(n0 + r) * K_DIM + koff + c * 8;
        cp16(bbase + soff, g_W_h + gb);
    }
}
#endif

__global__ void __launch_bounds__(GEMM_THREADS)
lstm_gemm_kernel(const float* __restrict__ c_in,
                 const float* __restrict__ bi, const float* __restrict__ bf_,
                 const float* __restrict__ bg, const float* __restrict__ bo,
                 float* __restrict__ out) {
    extern __shared__ char smem[];
    int tid = threadIdx.x;
    const size_t c_off = (size_t)B_DIM * U_DIM;

    // tiles owned by this CTA (persistent): exactly 4 at GRID_X=128
    int tiles[MAX_TILES_PER_CTA];
    int ntiles = 0;
    for (int t = blockIdx.x; t < NTILES_TOTAL && ntiles < MAX_TILES_PER_CTA;
         t += GRID_X)
        tiles[ntiles++] = t;
    if (ntiles == 0) return;

#if USE_TCGEN05
    // ======================= warp-specialized persistent path ===============
    uint32_t sb = smem_u32(smem);
    int wid = tid >> 5;
    int lid = tid & 31;

    if (wid == 0) TCGEN05_ALLOC(sb + SM_TMEM, 512);
    if (tid == 0) {
#pragma unroll
        for (int s = 0; s < NSTAGES; s++) {
            MBARRIER_INIT(sb + SM_FULL + 8 * s, N_PRODUCER_THREADS);
            MBARRIER_INIT(sb + SM_MMAB + 8 * s, 1);
        }
    }
    __syncthreads();
    uint32_t tmem;
    asm volatile("ld.shared.b32 %0, [%1];" : "=r"(tmem) : "r"(sb + SM_TMEM));

    const int G = ntiles * KTILES;

    if (wid >= 4) {
        // =================== PRODUCER warps 4-7 =============================
        int ptid = tid - 128;    // 0..127

        // prologue: fill slots 0,1; signal full[0]
        {
            int m00 = (tiles[0] >> 4) * BM;
            int n00 = (tiles[0] & (NTILES_N - 1)) * BN;
            load_stage_quarter(sb + SM_STAGE + 0 * STAGE_BYTES, 0, m00, n00, ptid);
            CP_ASYNC_COMMIT();
            load_stage_quarter(sb + SM_STAGE + 1 * STAGE_BYTES, 1, m00, n00, ptid);
            CP_ASYNC_COMMIT();
            CP_ASYNC_WAIT(1);                       // group 0 landed
            MBARRIER_ARRIVE(sb + SM_FULL + 8 * 0);
        }

#pragma unroll 1
        for (int gp = 2; gp < G; gp++) {
            // slot gp%3 was consumed by MMA(gp-3): wait its commit
            if (gp >= 3) {
                int w = gp - 3;
                MBARRIER_WAIT_PARITY(sb + SM_MMAB + 8 * (w % NSTAGES),
                                     (w / NSTAGES) & 1);
            }
            int j2 = gp >> 5;                       // KTILES == 32
            int kt2 = gp & 31;
            int t2 = tiles[j2];
            int m02 = (t2 >> 4) * BM;
            int n02 = (t2 & (NTILES_N - 1)) * BN;
            load_stage_quarter(sb + SM_STAGE + (gp % NSTAGES) * STAGE_BYTES,
                               kt2, m02, n02, ptid);
            CP_ASYNC_COMMIT();
            CP_ASYNC_WAIT(1);                       // group gp-1 landed
            MBARRIER_ARRIVE(sb + SM_FULL + 8 * ((gp - 1) % NSTAGES));
        }
        CP_ASYNC_WAIT(0);                           // group G-1 landed
        MBARRIER_ARRIVE(sb + SM_FULL + 8 * ((G - 1) % NSTAGES));

    } else {
        // =================== CONSUMER warps 0-3 =============================
        int g = 0;
#pragma unroll 1
        for (int j = 0; j < ntiles; j++) {
            int t = tiles[j];
            int m0 = (t >> 4) * BM;
            int n0 = (t & (NTILES_N - 1)) * BN;
            int u_base = n0 >> 2;

            if (wid == 0) {
#pragma unroll 1
                for (int kt = 0; kt < KTILES; kt++, g++) {
                    MBARRIER_WAIT_PARITY(sb + SM_FULL + 8 * (g % NSTAGES),
                                         (g / NSTAGES) & 1);
                    uint32_t st = sb + SM_STAGE + (g % NSTAGES) * STAGE_BYTES;
                    uint64_t dA0 = make_desc(st);             // rows 0..127
                    uint64_t dA1 = make_desc(st + 16384);     // rows 128..255
                    uint64_t dB  = make_desc(st + A_TILE_BYTES);
                    if (elect_one()) {
                        FENCE_PROXY_ASYNC();
#pragma unroll
                        for (int s = 0; s < 4; s++) {
                            uint32_t off = s * 2;
                            uint32_t acc = (kt | s) != 0;
                            mma_f16_ss(tmem,       dA0 + off, dB + off, MMA_IDESC, acc);
                            mma_f16_ss(tmem + 256, dA1 + off, dB + off, MMA_IDESC, acc);
                        }
                        TCGEN05_COMMIT(sb + SM_MMAB + 8 * (g % NSTAGES));
                    }
                }
                // wait last MMA of this tile before epilogue
                int gl = g - 1;
                MBARRIER_WAIT_PARITY(sb + SM_MMAB + 8 * (gl % NSTAGES),
                                     (gl / NSTAGES) & 1);
            } else {
                g += KTILES;   // warps 1-3 skip the mainloop
            }

            // warps 0-3 rendezvous: warp 0 arrives only after gl commit
            NAMED_BARRIER_SYNC(1, 128);
            TCGEN05_FENCE_AFTER();

            // ------- epilogue: warp w owns D lanes w*32+lid (all 512 cols) --
#pragma unroll
            for (int mh = 0; mh < 2; mh++) {
                int m = m0 + mh * 128 + wid * 32 + lid;
                const float* crow = c_in + (size_t)m * U_DIM;
                float* hrow = out + (size_t)m * U_DIM;
                float* corow = out + c_off + (size_t)m * U_DIM;
#pragma unroll
                for (int ch = 0; ch < 8; ch++) {
                    uint32_t col = (uint32_t)(mh * 256 + ch * 32);
                    uint32_t d[32];
                    TCGEN05_LD_32X32B_X32(d, tmem + col);
                    int u0c = u_base + ch * 8;
                    float4 cv0 = *reinterpret_cast<const float4*>(crow + u0c);
                    float4 cv1 = *reinterpret_cast<const float4*>(crow + u0c + 4);
                    float cvs[8] = {cv0.x, cv0.y, cv0.z, cv0.w,
                                    cv1.x, cv1.y, cv1.z, cv1.w};
                    TCGEN05_WAIT_LD();
                    float hv[8], cnv[8];
#pragma unroll
                    for (int q = 0; q < 8; q++) {
                        int u = u0c + q;
                        float zi = __uint_as_float(d[4 * q + 0]) + bi[u];
                        float zf = __uint_as_float(d[4 * q + 1]) + bf_[u];
                        float zg = __uint_as_float(d[4 * q + 2]) + bg[u];
                        float zo = __uint_as_float(d[4 * q + 3]) + bo[u];
                        float ig = fast_sigmoid(zi);
                        float fg = fast_sigmoid(zf);
                        float gg = tanh_fast(zg);
                        float og = fast_sigmoid(zo);
                        float cn = fg * cvs[q] + ig * gg;
                        hv[q] = og * tanh_fast(cn);
                        cnv[q] = cn;
                    }
                    *reinterpret_cast<float4*>(hrow + u0c) =
                        make_float4(hv[0], hv[1], hv[2], hv[3]);
                    *reinterpret_cast<float4*>(hrow + u0c + 4) =
                        make_float4(hv[4], hv[5], hv[6], hv[7]);
                    *reinterpret_cast<float4*>(corow + u0c) =
                        make_float4(cnv[0], cnv[1], cnv[2], cnv[3]);
                    *reinterpret_cast<float4*>(corow + u0c + 4) =
                        make_float4(cnv[4], cnv[5], cnv[6], cnv[7]);
                }
            }
            TCGEN05_WAIT_LD();
            TCGEN05_FENCE_BEFORE();
            // all warps 0-3 done reading D before next tile's acc=0 MMA
            NAMED_BARRIER_SYNC(1, 128);
        }
    }

    __syncthreads();
    if (tid == 0) {
#pragma unroll
        for (int s = 0; s < NSTAGES; s++) {
            MBARRIER_INVAL(sb + SM_FULL + 8 * s);
            MBARRIER_INVAL(sb + SM_MMAB + 8 * s);
        }
    }
    __syncthreads();
    if (wid == 0) TCGEN05_DEALLOC(tmem, 512);

#else
    // ======================= SIMT fallback (plain sm_103 target) ===========
    const int PAD = 132;
    float* As = reinterpret_cast<float*>(smem);          // [32][PAD]
    float* Bs = As + 32 * PAD;                           // [32][PAD]

    int tx = tid & 15;
    int ty = tid >> 4;

#pragma unroll 1
    for (int j = 0; j < ntiles; j++) {
        int t = tiles[j];
        int m0 = (t >> 4) * BM;
        int n0 = (t & (NTILES_N - 1)) * BN;

#pragma unroll 1
        for (int mh = 0; mh < 2; mh++) {
            int m0h = m0 + mh * 128;
#pragma unroll 1
            for (int ns = 0; ns < 2; ns++) {             // two 128-wide n halves
                int n0h = n0 + ns * 128;
                int u0 = n0h >> 2;
                float acc[8][8];
#pragma unroll
                for (int i = 0; i < 8; i++)
#pragma unroll
                    for (int q = 0; q < 8; q++) acc[i][q] = 0.0f;

#pragma unroll 1
                for (int kt = 0; kt < K_DIM / 32; kt++) {
                    int koff = kt * 32;
#pragma unroll
                    for (int i = 0; i < 16; i++) {
                        int idx = tid + i * 256;
                        int kk = idx & 31;
                        int r = idx >> 5;
                        size_t ga = (size_t)(m0h + r) * K_DIM + koff + kk;
                        size_t gb = (size_t)(n0h + r) * K_DIM + koff + kk;
                        As[kk * PAD + r] = __half2float(g_A_h[ga]);
                        Bs[kk * PAD + r] = __half2float(g_W_h[gb]);
                    }
                    __syncthreads();
#pragma unroll 1
                    for (int kk = 0; kk < 32; kk++) {
                        float a[8], b[8];
#pragma unroll
                        for (int i = 0; i < 8; i++) a[i] = As[kk * PAD + ty * 8 + i];
#pragma unroll
                        for (int q = 0; q < 8; q++) b[q] = Bs[kk * PAD + tx * 8 + q];
#pragma unroll
                        for (int i = 0; i < 8; i++)
#pragma unroll
                            for (int q = 0; q < 8; q++) acc[i][q] += a[i] * b[q];
                    }
                    __syncthreads();
                }

#pragma unroll
                for (int i = 0; i < 8; i++) {
                    int m = m0h + ty * 8 + i;
#pragma unroll
                    for (int jj = 0; jj < 2; jj++) {
                        int u = u0 + tx * 2 + jj;
                        float zi = acc[i][jj * 4 + 0] + bi[u];
                        float zf = acc[i][jj * 4 + 1] + bf_[u];
                        float zg = acc[i][jj * 4 + 2] + bg[u];
                        float zo = acc[i][jj * 4 + 3] + bo[u];
                        float ig = fast_sigmoid(zi);
                        float fg = fast_sigmoid(zf);
                        float gg = tanh_fast(zg);
                        float og = fast_sigmoid(zo);
                        float cv = c_in[(size_t)m * U_DIM + u];
                        float cn = fg * cv + ig * gg;
                        float hn = og * tanh_fast(cn);
                        out[(size_t)m * U_DIM + u] = hn;
                        out[c_off + (size_t)m * U_DIM + u] = cn;
                    }
                }
                __syncthreads();
            }
        }
    }
#endif
}

// ---------------- launch ----------------------------------------------------
extern "C" void kernel_launch(void* const* d_in, const int* in_sizes, int n_in,
                              void* d_out, int out_size) {
    const float* x  = (const float*)d_in[0];
    const float* h  = (const float*)d_in[1];
    const float* c  = (const float*)d_in[2];
    const float* Wi = (const float*)d_in[3];
    const float* Wf = (const float*)d_in[4];
    const float* Wg = (const float*)d_in[5];
    const float* Wo = (const float*)d_in[6];
    const float* bi = (const float*)d_in[7];
    const float* bf = (const float*)d_in[8];
    const float* bg = (const float*)d_in[9];
    const float* bo = (const float*)d_in[10];
    float* out = (float*)d_out;

    // 1) fused prep: concat->fp16 A  +  W transpose->fp16 (one launch)
    prep_fused_kernel<<<PREP_A_BLOCKS + PREP_W_BLOCKS, 256>>>(
        x, h, Wi, Wf, Wg, Wo);
    // 2) persistent warp-specialized GEMM + LSTM epilogue (4 tiles/CTA exact)
    cudaFuncSetAttribute(lstm_gemm_kernel,
                         cudaFuncAttributeMaxDynamicSharedMemorySize, GEMM_SMEM);
    lstm_gemm_kernel<<<GRID_X, GEMM_THREADS, GEMM_SMEM>>>(
        c, bi, bf, bg, bo, out);
}

// round 12
// speedup vs baseline: 3.9646x; 1.0121x over previous
#include <cuda_runtime.h>
#include <cuda_fp16.h>
#include <cstdint>

// ============================================================================
// CellLSTM on GB300 (sm_103a)
//   z = [x|h] @ [Wi|Wf|Wg|Wo] + b ; gates; c' = f*c + i*g ; h' = o*tanh(c')
//   R12: full[] barriers now signaled by cp.async.mbarrier.arrive.noinc --
//   the barrier fires when the DATA LANDS, not when the producer's blocking
//   wait_group gets around to it. R11 ncu: tensor=44%, L2=28% -> loop was
//   latency-bound (~1800cyc/iter vs 1024 tensor floor) on the old signaling.
// ============================================================================

#if defined(__CUDA_ARCH_FEAT_SM103_ALL) || defined(__CUDA_ARCH_FEAT_SM100_ALL)
#define USE_TCGEN05 1
#else
#define USE_TCGEN05 0
#endif

#define B_DIM 8192
#define T_DIM 1024
#define U_DIM 1024
#define K_DIM 2048
#define N_DIM 4096

#define BM 256              // two M=128 MMA halves
#define BN 256
#define BK 64
#define KTILES (K_DIM / BK)         // 32 k-iterations per tile
#define NTILES_TOTAL ((B_DIM / BM) * (N_DIM / BN))   // 512
#define NTILES_N (N_DIM / BN)       // 16
#define GRID_X 128                  // 512 tiles / 128 = exactly 4 per CTA
#define MAX_TILES_PER_CTA 4
#define GEMM_THREADS 256

// ---------------- scratch (device globals: allocation-rule-safe) -----------
__device__ __align__(16) __half g_A_h[(size_t)B_DIM * K_DIM];
// W transposed & gate-interleaved: row n = u*4 + gate, K-major
__device__ __align__(16) __half g_W_h[(size_t)N_DIM * K_DIM];

// ---------------- arch-neutral helpers -------------------------------------
__device__ __forceinline__ uint32_t smem_u32(const void* p) {
    uint32_t a;
    asm("{ .reg .u64 t; cvta.to.shared.u64 t, %1; cvt.u32.u64 %0, t; }"
        : "=r"(a) : "l"(p));
    return a;
}

#define SWZ128(off) ((off) ^ (((off) >> 3) & 0x70))

__device__ __forceinline__ float tanh_fast(float x) {
    float y;
    asm("tanh.approx.f32 %0, %1;" : "=f"(y) : "f"(x));
    return y;
}

// sigmoid(z) = 0.5*tanh(z/2) + 0.5  (1 MUFU instead of EX2+RCP)
__device__ __forceinline__ float fast_sigmoid(float z) {
    return fmaf(0.5f, tanh_fast(0.5f * z), 0.5f);
}

#if USE_TCGEN05
// ---------------- tcgen05 / mbarrier / cp.async helpers --------------------
__device__ __forceinline__ uint32_t elect_one() {
    uint32_t pred;
    asm volatile(
        "{\n\t.reg .pred p;\n\telect.sync _|p, 0xFFFFFFFF;\n\t"
        "selp.b32 %0, 1, 0, p;\n\t}" : "=r"(pred));
    return pred;
}

#define MBARRIER_INIT(addr, cnt) \
    asm volatile("mbarrier.init.shared.b64 [%0], %1;" \
                 :: "r"((uint32_t)(addr)), "r"((uint32_t)(cnt)) : "memory")

#define MBARRIER_INVAL(addr) \
    asm volatile("mbarrier.inval.shared.b64 [%0];" \
                 :: "r"((uint32_t)(addr)) : "memory")

// arrive on mbar when ALL prior cp.asyncs of this thread have completed.
// .noinc: expected-arrival count comes solely from mbarrier.init.
#define CP_ASYNC_MBAR_ARRIVE(addr) \
    asm volatile("cp.async.mbarrier.arrive.noinc.shared::cta.b64 [%0];" \
                 :: "r"((uint32_t)(addr)) : "memory")

#define MBARRIER_WAIT_PARITY(mbar_smem_addr, phase_parity) do { \
    uint32_t _mbar = (uint32_t)(mbar_smem_addr); \
    uint32_t _parity = (uint32_t)(phase_parity); \
    uint32_t _done; \
    asm volatile( \
        "{\n\t.reg .pred p;\n\t" \
        "mbarrier.try_wait.parity.acquire.cta.shared::cta.b64 p, [%1], %2;\n\t" \
        "selp.b32 %0, 1, 0, p;\n\t}" \
        : "=r"(_done) : "r"(_mbar), "r"(_parity) : "memory"); \
    if (!_done) { \
        asm volatile( \
            "{\n\t.reg .pred P1;\n\t" \
            "WAIT_LOOP_%=:\n\t" \
            "mbarrier.try_wait.parity.acquire.cta.shared::cta.b64 P1, [%0], %1, 0x989680;\n\t" \
            "@P1 bra.uni WAIT_DONE_%=;\n\t" \
            "bra.uni WAIT_LOOP_%=;\n\t" \
            "WAIT_DONE_%=:\n\t}" \
            :: "r"(_mbar), "r"(_parity) : "memory"); \
    } \
} while (0)

#define NAMED_BARRIER_SYNC(id, cnt) \
    asm volatile("bar.sync %0, %1;" :: "r"(id), "r"(cnt) : "memory")

#define TCGEN05_ALLOC(smem_result_addr, nCols) \
    asm volatile("tcgen05.alloc.cta_group::1.sync.aligned.shared::cta.b32 [%0], %1;" \
                 :: "r"((uint32_t)(smem_result_addr)), "r"((uint32_t)(nCols)) : "memory")

#define TCGEN05_DEALLOC(tmem_addr, nCols) \
    asm volatile("tcgen05.dealloc.cta_group::1.sync.aligned.b32 %0, %1;" \
                 :: "r"(tmem_addr), "r"((uint32_t)(nCols)))

#define TCGEN05_COMMIT(mbar_smem_addr) \
    asm volatile("tcgen05.commit.cta_group::1.mbarrier::arrive::one.shared::cluster.b64 [%0];" \
                 :: "r"((uint32_t)(mbar_smem_addr)) : "memory")

#define TCGEN05_FENCE_AFTER() \
    asm volatile("tcgen05.fence::after_thread_sync;" ::: "memory")
#define TCGEN05_FENCE_BEFORE() \
    asm volatile("tcgen05.fence::before_thread_sync;" ::: "memory")
#define TCGEN05_WAIT_LD() \
    asm volatile("tcgen05.wait::ld.sync.aligned;" ::: "memory")

#define FENCE_PROXY_ASYNC() \
    asm volatile("fence.proxy.async.shared::cta;" ::: "memory")

__device__ __forceinline__ void cp16(uint32_t dst, const void* src) {
    asm volatile("cp.async.cg.shared.global [%0], [%1], 16;"
                 :: "r"(dst), "l"(src) : "memory");
}

#define TCGEN05_LD_32X32B_X32(r, tmem_addr) \
    asm volatile( \
        "tcgen05.ld.sync.aligned.32x32b.x32.b32 " \
        "{%0, %1, %2, %3, %4, %5, %6, %7, " \
        " %8, %9, %10, %11, %12, %13, %14, %15, " \
        " %16, %17, %18, %19, %20, %21, %22, %23, " \
        " %24, %25, %26, %27, %28, %29, %30, %31}, [%32];" \
        : "=r"((r)[0]),  "=r"((r)[1]),  "=r"((r)[2]),  "=r"((r)[3]), \
          "=r"((r)[4]),  "=r"((r)[5]),  "=r"((r)[6]),  "=r"((r)[7]), \
          "=r"((r)[8]),  "=r"((r)[9]),  "=r"((r)[10]), "=r"((r)[11]), \
          "=r"((r)[12]), "=r"((r)[13]), "=r"((r)[14]), "=r"((r)[15]), \
          "=r"((r)[16]), "=r"((r)[17]), "=r"((r)[18]), "=r"((r)[19]), \
          "=r"((r)[20]), "=r"((r)[21]), "=r"((r)[22]), "=r"((r)[23]), \
          "=r"((r)[24]), "=r"((r)[25]), "=r"((r)[26]), "=r"((r)[27]), \
          "=r"((r)[28]), "=r"((r)[29]), "=r"((r)[30]), "=r"((r)[31]) \
        : "r"(tmem_addr))

// K-major SW128 smem descriptor (verified: test_mma_iter)
static constexpr uint64_t SMEM_DESC_BASE_SW128 =
    (uint64_t(2)  << 61) | (uint64_t(1) << 46) |
    (uint64_t(64) << 32) | (uint64_t(1) << 16);

__device__ __forceinline__ uint64_t make_desc(uint32_t addr) {
    return SMEM_DESC_BASE_SW128 | ((uint64_t)(addr >> 4) & 0x3FFF);
}

// idesc kind::f16, FP16 inputs, f32 accum, M=128 (per MMA stream), N=256
static constexpr uint32_t MMA_IDESC =
    (1u << 4) | (0u << 7) | (0u << 10) | ((BN / 8) << 17) | ((128 / 16) << 24);

__device__ __forceinline__ void mma_f16_ss(uint32_t d, uint64_t ad, uint64_t bd,
                                           uint32_t idesc, uint32_t acc) {
    asm volatile(
        "{\n\t.reg .pred p;\n\t"
        "setp.ne.u32 p, %4, 0;\n\t"
        "tcgen05.mma.cta_group::1.kind::f16 [%0], %1, %2, %3, {%5, %5, %5, %5}, p;\n\t"
        "}"
        :: "r"(d), "l"(ad), "l"(bd), "r"(idesc), "r"(acc), "r"(0u)
        : "memory");
}
#endif // USE_TCGEN05

// ---------------- fused prep kernel -----------------------------------------
#define PREP_A_BLOCKS ((int)(((size_t)B_DIM * K_DIM / 8) / 256))   // 8192
#define PREP_W_BLOCKS ((K_DIM / 32) * (U_DIM / 32) * 4)            // 8192

__global__ void prep_fused_kernel(const float* __restrict__ x,
                                  const float* __restrict__ h,
                                  const float* __restrict__ Wi,
                                  const float* __restrict__ Wf,
                                  const float* __restrict__ Wg,
                                  const float* __restrict__ Wo) {
    __shared__ float tile[32][33];
    int bid = blockIdx.x;
    int tid = threadIdx.x;

    if (bid < PREP_A_BLOCKS) {
        size_t idx8 = ((size_t)bid * 256 + tid) * 8;
        int m = (int)(idx8 / K_DIM);
        int k = (int)(idx8 % K_DIM);
        const float* src = (k < T_DIM) ? (x + (size_t)m * T_DIM + k)
                                       : (h + (size_t)m * U_DIM + (k - T_DIM));
        float4 v0 = *reinterpret_cast<const float4*>(src);
        float4 v1 = *reinterpret_cast<const float4*>(src + 4);

        union Pack { __half b[8]; uint4 u; } p;
        p.b[0] = __float2half_rn(v0.x); p.b[1] = __float2half_rn(v0.y);
        p.b[2] = __float2half_rn(v0.z); p.b[3] = __float2half_rn(v0.w);
        p.b[4] = __float2half_rn(v1.x); p.b[5] = __float2half_rn(v1.y);
        p.b[6] = __float2half_rn(v1.z); p.b[7] = __float2half_rn(v1.w);
        *reinterpret_cast<uint4*>(g_A_h + idx8) = p.u;
    } else {
        int w = bid - PREP_A_BLOCKS;               // 0..8191
        int gate = w >> 11;
        int rem = w & 2047;
        int k0 = (rem & 63) * 32;
        int u0 = (rem >> 6) * 32;
        const float* W = (gate == 0) ? Wi : (gate == 1) ? Wf
                        : (gate == 2) ? Wg : Wo;
        int tx = tid & 31;
        int ty = tid >> 5;

#pragma unroll
        for (int i = 0; i < 4; i++) {
            int k = k0 + ty + i * 8;
            tile[ty + i * 8][tx] = W[(size_t)k * U_DIM + u0 + tx];
        }
        __syncthreads();
#pragma unroll
        for (int i = 0; i < 4; i++) {
            int u = u0 + ty + i * 8;
            float v = tile[tx][ty + i * 8];        // = W[k0+tx, u]
            size_t off = (size_t)(u * 4 + gate) * K_DIM + k0 + tx;
            g_W_h[off] = __float2half_rn(v);
        }
    }
}

// ---------------- GEMM + LSTM epilogue -------------------------------------
// SMEM map:
//   [0]      tmem ptr
//   [8]      full[3] mbarriers   -- cp.async.mbarrier.arrive (data landed)
//   [32]     mma[3]  mbarriers   -- MMA commit frees a slot
//   [1024]   3 stages x (A 32K + B 32K) = 192KB ring
#define SM_TMEM 0
#define SM_FULL 8
#define SM_MMAB 32
#define SM_STAGE 1024
#define A_TILE_BYTES 32768                  // 256 rows x 128B
#define B_TILE_BYTES 32768                  // 256 rows x 128B
#define STAGE_BYTES (A_TILE_BYTES + B_TILE_BYTES)           // 65536
#define NSTAGES 3
#define GEMM_SMEM (SM_STAGE + NSTAGES * STAGE_BYTES)        // 197632
#define N_PRODUCER_THREADS 128

#if USE_TCGEN05
// Each of the 128 producer threads loads 32 x 16B chunks (A then B).
__device__ __forceinline__ void load_stage_quarter(uint32_t sbase, int kt,
                                                   int m0, int n0, int ptid) {
    int koff = kt * BK;
#pragma unroll
    for (int j = 0; j < 16; j++) {
        int i = ptid + j * N_PRODUCER_THREADS;
        int r = i >> 3;
        int c = i & 7;
        uint32_t soff = SWZ128((uint32_t)(r * 128 + c * 16));
        size_t ga = (size_t)(m0 + r) * K_DIM + koff + c * 8;
        cp16(sbase + soff, g_A_h + ga);
    }
    uint32_t bbase = sbase + A_TILE_BYTES;
#pragma unroll
    for (int j = 0; j < 16; j++) {
        int i = ptid + j * N_PRODUCER_THREADS;
        int r = i >> 3;
        int c = i & 7;
        uint32_t soff = SWZ128((uint32_t)(r * 128 + c * 16));
        size_t gb = (size_t)(n0 + r) * K_DIM + koff + c * 8;
        cp16(bbase + soff, g_W_h + gb);
    }
}
#endif

__global__ void __launch_bounds__(GEMM_THREADS)
lstm_gemm_kernel(const float* __restrict__ c_in,
                 const float* __restrict__ bi, const float* __restrict__ bf_,
                 const float* __restrict__ bg, const float* __restrict__ bo,
                 float* __restrict__ out) {
    extern __shared__ char smem[];
    int tid = threadIdx.x;
    const size_t c_off = (size_t)B_DIM * U_DIM;

    // tiles owned by this CTA (persistent): exactly 4 at GRID_X=128
    int tiles[MAX_TILES_PER_CTA];
    int ntiles = 0;
    for (int t = blockIdx.x; t < NTILES_TOTAL && ntiles < MAX_TILES_PER_CTA;
         t += GRID_X)
        tiles[ntiles++] = t;
    if (ntiles == 0) return;

#if USE_TCGEN05
    // ======================= warp-specialized persistent path ===============
    uint32_t sb = smem_u32(smem);
    int wid = tid >> 5;
    int lid = tid & 31;

    if (wid == 0) TCGEN05_ALLOC(sb + SM_TMEM, 512);
    if (tid == 0) {
#pragma unroll
        for (int s = 0; s < NSTAGES; s++) {
            MBARRIER_INIT(sb + SM_FULL + 8 * s, N_PRODUCER_THREADS);
            MBARRIER_INIT(sb + SM_MMAB + 8 * s, 1);
        }
    }
    __syncthreads();
    uint32_t tmem;
    asm volatile("ld.shared.b32 %0, [%1];" : "=r"(tmem) : "r"(sb + SM_TMEM));

    const int G = ntiles * KTILES;

    if (wid >= 4) {
        // =================== PRODUCER warps 4-7 =============================
        // full[s] is raised by the HW when the slot's data lands (cp.async
        // mbarrier arrive) -- producers never block on L2 latency.
        int ptid = tid - 128;    // 0..127

        // prologue: slots 0,1
        {
            int m00 = (tiles[0] >> 4) * BM;
            int n00 = (tiles[0] & (NTILES_N - 1)) * BN;
            load_stage_quarter(sb + SM_STAGE + 0 * STAGE_BYTES, 0, m00, n00, ptid);
            CP_ASYNC_MBAR_ARRIVE(sb + SM_FULL + 8 * 0);
            load_stage_quarter(sb + SM_STAGE + 1 * STAGE_BYTES, 1, m00, n00, ptid);
            CP_ASYNC_MBAR_ARRIVE(sb + SM_FULL + 8 * 1);
        }

#pragma unroll 1
        for (int gp = 2; gp < G; gp++) {
            // slot gp%3 was consumed by MMA(gp-3): wait its commit
            if (gp >= 3) {
                int w = gp - 3;
                MBARRIER_WAIT_PARITY(sb + SM_MMAB + 8 * (w % NSTAGES),
                                     (w / NSTAGES) & 1);
            }
            int j2 = gp >> 5;                       // KTILES == 32
            int kt2 = gp & 31;
            int t2 = tiles[j2];
            int m02 = (t2 >> 4) * BM;
            int n02 = (t2 & (NTILES_N - 1)) * BN;
            load_stage_quarter(sb + SM_STAGE + (gp % NSTAGES) * STAGE_BYTES,
                               kt2, m02, n02, ptid);
            CP_ASYNC_MBAR_ARRIVE(sb + SM_FULL + 8 * (gp % NSTAGES));
        }

    } else {
        // =================== CONSUMER warps 0-3 =============================
        int g = 0;
#pragma unroll 1
        for (int j = 0; j < ntiles; j++) {
            int t = tiles[j];
            int m0 = (t >> 4) * BM;
            int n0 = (t & (NTILES_N - 1)) * BN;
            int u_base = n0 >> 2;

            if (wid == 0) {
#pragma unroll 1
                for (int kt = 0; kt < KTILES; kt++, g++) {
                    MBARRIER_WAIT_PARITY(sb + SM_FULL + 8 * (g % NSTAGES),
                                         (g / NSTAGES) & 1);
                    uint32_t st = sb + SM_STAGE + (g % NSTAGES) * STAGE_BYTES;
                    uint64_t dA0 = make_desc(st);             // rows 0..127
                    uint64_t dA1 = make_desc(st + 16384);     // rows 128..255
                    uint64_t dB  = make_desc(st + A_TILE_BYTES);
                    if (elect_one()) {
                        FENCE_PROXY_ASYNC();
#pragma unroll
                        for (int s = 0; s < 4; s++) {
                            uint32_t off = s * 2;
                            uint32_t acc = (kt | s) != 0;
                            mma_f16_ss(tmem,       dA0 + off, dB + off, MMA_IDESC, acc);
                            mma_f16_ss(tmem + 256, dA1 + off, dB + off, MMA_IDESC, acc);
                        }
                        TCGEN05_COMMIT(sb + SM_MMAB + 8 * (g % NSTAGES));
                    }
                }
                // wait last MMA of this tile before epilogue
                int gl = g - 1;
                MBARRIER_WAIT_PARITY(sb + SM_MMAB + 8 * (gl % NSTAGES),
                                     (gl / NSTAGES) & 1);
            } else {
                g += KTILES;   // warps 1-3 skip the mainloop
            }

            // warps 0-3 rendezvous: warp 0 arrives only after gl commit
            NAMED_BARRIER_SYNC(1, 128);
            TCGEN05_FENCE_AFTER();

            // ------- epilogue: warp w owns D lanes w*32+lid (all 512 cols) --
#pragma unroll
            for (int mh = 0; mh < 2; mh++) {
                int m = m0 + mh * 128 + wid * 32 + lid;
                const float* crow = c_in + (size_t)m * U_DIM;
                float* hrow = out + (size_t)m * U_DIM;
                float* corow = out + c_off + (size_t)m * U_DIM;
#pragma unroll
                for (int ch = 0; ch < 8; ch++) {
                    uint32_t col = (uint32_t)(mh * 256 + ch * 32);
                    uint32_t d[32];
                    TCGEN05_LD_32X32B_X32(d, tmem + col);
                    int u0c = u_base + ch * 8;
                    float4 cv0 = *reinterpret_cast<const float4*>(crow + u0c);
                    float4 cv1 = *reinterpret_cast<const float4*>(crow + u0c + 4);
                    float cvs[8] = {cv0.x, cv0.y, cv0.z, cv0.w,
                                    cv1.x, cv1.y, cv1.z, cv1.w};
                    TCGEN05_WAIT_LD();
                    float hv[8], cnv[8];
#pragma unroll
                    for (int q = 0; q < 8; q++) {
                        int u = u0c + q;
                        float zi = __uint_as_float(d[4 * q + 0]) + bi[u];
                        float zf = __uint_as_float(d[4 * q + 1]) + bf_[u];
                        float zg = __uint_as_float(d[4 * q + 2]) + bg[u];
                        float zo = __uint_as_float(d[4 * q + 3]) + bo[u];
                        float ig = fast_sigmoid(zi);
                        float fg = fast_sigmoid(zf);
                        float gg = tanh_fast(zg);
                        float og = fast_sigmoid(zo);
                        float cn = fg * cvs[q] + ig * gg;
                        hv[q] = og * tanh_fast(cn);
                        cnv[q] = cn;
                    }
                    *reinterpret_cast<float4*>(hrow + u0c) =
                        make_float4(hv[0], hv[1], hv[2], hv[3]);
                    *reinterpret_cast<float4*>(hrow + u0c + 4) =
                        make_float4(hv[4], hv[5], hv[6], hv[7]);
                    *reinterpret_cast<float4*>(corow + u0c) =
                        make_float4(cnv[0], cnv[1], cnv[2], cnv[3]);
                    *reinterpret_cast<float4*>(corow + u0c + 4) =
                        make_float4(cnv[4], cnv[5], cnv[6], cnv[7]);
                }
            }
            TCGEN05_WAIT_LD();
            TCGEN05_FENCE_BEFORE();
            // all warps 0-3 done reading D before next tile's acc=0 MMA
            NAMED_BARRIER_SYNC(1, 128);
        }
    }

    __syncthreads();
    if (tid == 0) {
#pragma unroll
        for (int s = 0; s < NSTAGES; s++) {
            MBARRIER_INVAL(sb + SM_FULL + 8 * s);
            MBARRIER_INVAL(sb + SM_MMAB + 8 * s);
        }
    }
    __syncthreads();
    if (wid == 0) TCGEN05_DEALLOC(tmem, 512);

#else
    // ======================= SIMT fallback (plain sm_103 target) ===========
    const int PAD = 132;
    float* As = reinterpret_cast<float*>(smem);          // [32][PAD]
    float* Bs = As + 32 * PAD;                           // [32][PAD]

    int tx = tid & 15;
    int ty = tid >> 4;

#pragma unroll 1
    for (int j = 0; j < ntiles; j++) {
        int t = tiles[j];
        int m0 = (t >> 4) * BM;
        int n0 = (t & (NTILES_N - 1)) * BN;

#pragma unroll 1
        for (int mh = 0; mh < 2; mh++) {
            int m0h = m0 + mh * 128;
#pragma unroll 1
            for (int ns = 0; ns < 2; ns++) {
                int n0h = n0 + ns * 128;
                int u0 = n0h >> 2;
                float acc[8][8];
#pragma unroll
                for (int i = 0; i < 8; i++)
#pragma unroll
                    for (int q = 0; q < 8; q++) acc[i][q] = 0.0f;

#pragma unroll 1
                for (int kt = 0; kt < K_DIM / 32; kt++) {
                    int koff = kt * 32;
#pragma unroll
                    for (int i = 0; i < 16; i++) {
                        int idx = tid + i * 256;
                        int kk = idx & 31;
                        int r = idx >> 5;
                        size_t ga = (size_t)(m0h + r) * K_DIM + koff + kk;
                        size_t gb = (size_t)(n0h + r) * K_DIM + koff + kk;
                        As[kk * PAD + r] = __half2float(g_A_h[ga]);
                        Bs[kk * PAD + r] = __half2float(g_W_h[gb]);
                    }
                    __syncthreads();
#pragma unroll 1
                    for (int kk = 0; kk < 32; kk++) {
                        float a[8], b[8];
#pragma unroll
                        for (int i = 0; i < 8; i++) a[i] = As[kk * PAD + ty * 8 + i];
#pragma unroll
                        for (int q = 0; q < 8; q++) b[q] = Bs[kk * PAD + tx * 8 + q];
#pragma unroll
                        for (int i = 0; i < 8; i++)
#pragma unroll
                            for (int q = 0; q < 8; q++) acc[i][q] += a[i] * b[q];
                    }
                    __syncthreads();
                }

#pragma unroll
                for (int i = 0; i < 8; i++) {
                    int m = m0h + ty * 8 + i;
#pragma unroll
                    for (int jj = 0; jj < 2; jj++) {
                        int u = u0 + tx * 2 + jj;
                        float zi = acc[i][jj * 4 + 0] + bi[u];
                        float zf = acc[i][jj * 4 + 1] + bf_[u];
                        float zg = acc[i][jj * 4 + 2] + bg[u];
                        float zo = acc[i][jj * 4 + 3] + bo[u];
                        float ig = fast_sigmoid(zi);
                        float fg = fast_sigmoid(zf);
                        float gg = tanh_fast(zg);
                        float og = fast_sigmoid(zo);
                        float cv = c_in[(size_t)m * U_DIM + u];
                        float cn = fg * cv + ig * gg;
                        float hn = og * tanh_fast(cn);
                        out[(size_t)m * U_DIM + u] = hn;
                        out[c_off + (size_t)m * U_DIM + u] = cn;
                    }
                }
                __syncthreads();
            }
        }
    }
#endif
}

// ---------------- launch ----------------------------------------------------
extern "C" void kernel_launch(void* const* d_in, const int* in_sizes, int n_in,
                              void* d_out, int out_size) {
    const float* x  = (const float*)d_in[0];
    const float* h  = (const float*)d_in[1];
    const float* c  = (const float*)d_in[2];
    const float* Wi = (const float*)d_in[3];
    const float* Wf = (const float*)d_in[4];
    const float* Wg = (const float*)d_in[5];
    const float* Wo = (const float*)d_in[6];
    const float* bi = (const float*)d_in[7];
    const float* bf = (const float*)d_in[8];
    const float* bg = (const float*)d_in[9];
    const float* bo = (const float*)d_in[10];
    float* out = (float*)d_out;

    // 1) fused prep: concat->fp16 A  +  W transpose->fp16 (one launch)
    prep_fused_kernel<<<PREP_A_BLOCKS + PREP_W_BLOCKS, 256>>>(
        x, h, Wi, Wf, Wg, Wo);
    // 2) persistent warp-specialized GEMM + LSTM epilogue
    cudaFuncSetAttribute(lstm_gemm_kernel,
                         cudaFuncAttributeMaxDynamicSharedMemorySize, GEMM_SMEM);
    lstm_gemm_kernel<<<GRID_X, GEMM_THREADS, GEMM_SMEM>>>(
        c, bi, bf, bg, bo, out);
}